// round 5
// baseline (speedup 1.0000x reference)
#include <cuda_runtime.h>
#include <cuda_bf16.h>
#include <mma.h>
#include <cstdint>

using namespace nvcuda;

#define NB 4
#define NL 1024
#define ND 256
#define NH 8
#define NHD 2048
#define NBL 4096
#define ATT ((size_t)NB * NH * NL * NL)   // 33,554,432 attn elems

#define LDS_AB 72              // BK(64) + 8 pad -> 144B rows, LDSM conflict-free
#define PLE (128 * LDS_AB)     // elems per plane tile (9216)
#define PLB (PLE * 2)          // bytes per plane tile (18432)
#define STGB (4 * PLB)         // bytes per stage: Ahi|Alo|Bhi|Blo (73728)
#define NSTG 3                 // pipeline stages
#define LDC_S 132              // epilogue smem stride (floats)
#define SMEMB (NSTG * STGB)    // 221184 B (>= Cs 67584 B)

// ---------------------------------------------------------------------------
// cp.async helpers
// ---------------------------------------------------------------------------
__device__ __forceinline__ uint32_t smem_u32(const void* p) {
    uint32_t a;
    asm("{ .reg .u64 t; cvta.to.shared.u64 t, %1; cvt.u32.u64 %0, t; }" : "=r"(a) : "l"(p));
    return a;
}
#define CP_ASYNC16(dst, src) \
    asm volatile("cp.async.cg.shared.global [%0], [%1], 16;" :: "r"(dst), "l"(src) : "memory")
#define CP_COMMIT() asm volatile("cp.async.commit_group;" ::: "memory")
#define CP_WAIT0()  asm volatile("cp.async.wait_group 0;" ::: "memory")
#define CP_WAIT1()  asm volatile("cp.async.wait_group 1;" ::: "memory")

// ---------------------------------------------------------------------------
// scratch (device globals — allocations forbidden)
// ---------------------------------------------------------------------------
static __device__ __align__(16) __nv_bfloat16 g_qp[2 * NBL * ND];
static __device__ __align__(16) __nv_bfloat16 g_kp[2 * NBL * ND];
static __device__ __align__(16) __nv_bfloat16 g_vp[2 * NBL * ND];
static __device__ __align__(16) __nv_bfloat16 g_wqp[2 * NHD * ND];
static __device__ __align__(16) __nv_bfloat16 g_wkp[2 * NHD * ND];
static __device__ __align__(16) __nv_bfloat16 g_wvp[2 * NHD * ND];
static __device__ __align__(16) __nv_bfloat16 g_fcwp[2 * ND * NHD];
static __device__ __align__(16) __nv_bfloat16 g_qhp[2 * (size_t)NBL * NHD];
static __device__ __align__(16) __nv_bfloat16 g_khp[2 * (size_t)NBL * NHD];
static __device__ __align__(16) __nv_bfloat16 g_vht[2 * (size_t)NHD * NBL];
static __device__ __align__(16) __nv_bfloat16 g_hop[2 * (size_t)NBL * NHD];
static __device__ __align__(16) __nv_bfloat16 g_ap[2 * ATT];   // softmaxed attn planes
static __device__ float g_tmp[(size_t)4 * NBL * ND];

// ---------------------------------------------------------------------------
// fp32 -> (hi, lo) bf16 planes
// ---------------------------------------------------------------------------
__global__ void __launch_bounds__(256) cvt_k(const float* __restrict__ x,
                                             __nv_bfloat16* __restrict__ hi,
                                             __nv_bfloat16* __restrict__ lo, int n4) {
    int i = blockIdx.x * 256 + threadIdx.x;
    if (i >= n4) return;
    float4 v = *((const float4*)x + i);
    float f[4] = {v.x, v.y, v.z, v.w};
    __align__(8) __nv_bfloat16 h[4], l[4];
#pragma unroll
    for (int j = 0; j < 4; j++) {
        h[j] = __float2bfloat16(f[j]);
        l[j] = __float2bfloat16(f[j] - __bfloat162float(h[j]));
    }
    *(uint2*)(hi + (size_t)i * 4) = *(uint2*)h;
    *(uint2*)(lo + (size_t)i * 4) = *(uint2*)l;
}

// ---------------------------------------------------------------------------
// WMMA bf16x3 GEMM, cp.async 3-stage pipeline, BK=64, one sync per stage.
//   C[128x128 tile] = A @ B^T, fp32 accumulate; A/B are bf16 hi/lo planes.
//   EPI 0: write bf16 hi/lo pairs   1: scores (scale/clip/mask -> sentinel)
//   EPI 3: plain fp32 (fc split-K partials)
// 512 threads (16 warps, 4x4 grid), warp tile 32x32.
// ---------------------------------------------------------------------------
template <int EPI>
__global__ void __launch_bounds__(512, 1) tgemm(
    const __nv_bfloat16* __restrict__ Ag, long Asplit, int lda,
    const __nv_bfloat16* __restrict__ Bg, long Bsplit, int ldb,
    void* __restrict__ Cgv, int ldc, long Csplit,
    int K, int nBdim,
    long sAb, long sAh, long sBb, long sBh, long sCb, long sCh,
    const int* __restrict__ maskg, long sMb)
{
    extern __shared__ __align__(16) char sm[];
    const uint32_t smb = smem_u32(sm);
    float* Cs = (float*)sm;   // epilogue staging (reuses pipeline smem)

    const int tid = threadIdx.x;
    const int wid = tid >> 5;
    const int wm = wid & 3;   // warp row (4 x 32)
    const int wn = wid >> 2;  // warp col (4 x 32)

    const int z = blockIdx.z, zb = z % nBdim, zh = z / nBdim;
    const __nv_bfloat16* Ap = Ag + (size_t)zb * sAb + (size_t)zh * sAh;
    const __nv_bfloat16* Bp = Bg + (size_t)zb * sBb + (size_t)zh * sBh;

    const int rowBase = blockIdx.y * 128;
    const int colBase = blockIdx.x * 128;

    wmma::fragment<wmma::accumulator, 16, 16, 16, float> acc[2][2];
#pragma unroll
    for (int i = 0; i < 2; i++)
#pragma unroll
        for (int j = 0; j < 2; j++) wmma::fill_fragment(acc[i][j], 0.f);

    // issue one stage of async loads: 4 planes x 1024 16B-chunks, 512 threads
    auto ldst = [&](int t, int s) {
        const int ko = t * 64;
        const uint32_t sb = smb + s * STGB;
#pragma unroll
        for (int i = 0; i < 2; i++) {
            const int c = tid + i * 512;          // 0..1023
            const int row = c >> 3, col = (c & 7) * 8;
            const uint32_t soff = (uint32_t)(row * LDS_AB + col) * 2;
            const __nv_bfloat16* pa = Ap + (size_t)(rowBase + row) * lda + ko + col;
            CP_ASYNC16(sb + soff,           pa);
            CP_ASYNC16(sb + PLB + soff,     pa + Asplit);
            const __nv_bfloat16* pb = Bp + (size_t)(colBase + row) * ldb + ko + col;
            CP_ASYNC16(sb + 2 * PLB + soff, pb);
            CP_ASYNC16(sb + 3 * PLB + soff, pb + Bsplit);
        }
        CP_COMMIT();
    };

    auto compute = [&](int s) {
        const __nv_bfloat16* base = (const __nv_bfloat16*)(sm + s * STGB);
        const __nv_bfloat16* Ah0 = base + wm * 32 * LDS_AB;
        const __nv_bfloat16* Al0 = Ah0 + PLE;
        const __nv_bfloat16* Bh0 = base + 2 * PLE + wn * 32 * LDS_AB;
        const __nv_bfloat16* Bl0 = Bh0 + PLE;
#pragma unroll
        for (int ks = 0; ks < 4; ks++) {
            wmma::fragment<wmma::matrix_a, 16, 16, 16, __nv_bfloat16, wmma::row_major> fah[2], fal[2];
            wmma::fragment<wmma::matrix_b, 16, 16, 16, __nv_bfloat16, wmma::col_major> fbh[2], fbl[2];
#pragma unroll
            for (int i = 0; i < 2; i++) {
                wmma::load_matrix_sync(fah[i], Ah0 + i * 16 * LDS_AB + ks * 16, LDS_AB);
                wmma::load_matrix_sync(fal[i], Al0 + i * 16 * LDS_AB + ks * 16, LDS_AB);
            }
#pragma unroll
            for (int j = 0; j < 2; j++) {
                wmma::load_matrix_sync(fbh[j], Bh0 + j * 16 * LDS_AB + ks * 16, LDS_AB);
                wmma::load_matrix_sync(fbl[j], Bl0 + j * 16 * LDS_AB + ks * 16, LDS_AB);
            }
#pragma unroll
            for (int i = 0; i < 2; i++)
#pragma unroll
                for (int j = 0; j < 2; j++) {
                    wmma::mma_sync(acc[i][j], fah[i], fbh[j], acc[i][j]);
                    wmma::mma_sync(acc[i][j], fah[i], fbl[j], acc[i][j]);
                    wmma::mma_sync(acc[i][j], fal[i], fbh[j], acc[i][j]);
                }
        }
    };

    // ---- 3-stage pipelined mainloop (T >= 4 always here) ----
    const int T = K >> 6;
    ldst(0, 0);
    ldst(1, 1);
    for (int t = 0; t < T; t++) {
        if (t == T - 1) { CP_WAIT0(); } else { CP_WAIT1(); }
        __syncthreads();                       // stage t visible; slot (t+2)%3 free
        if (t + 2 < T) ldst(t + 2, (t + 2) % NSTG);
        compute(t % NSTG);
    }

    // ---- epilogue: stage accumulators through SMEM ----
    __syncthreads();
#pragma unroll
    for (int i = 0; i < 2; i++)
#pragma unroll
        for (int j = 0; j < 2; j++)
            wmma::store_matrix_sync(Cs + (size_t)(wm * 32 + i * 16) * LDC_S + wn * 32 + j * 16,
                                    acc[i][j], LDC_S, wmma::mem_row_major);
    __syncthreads();

    const int row = tid >> 2;
    const int ch  = (tid & 3) * 32;
    const float* crow = Cs + (size_t)row * LDC_S + ch;
    const int gr = rowBase + row;
    const int gc = colBase + ch;

    if (EPI == 0) {
        __nv_bfloat16* Ch = (__nv_bfloat16*)Cgv + (size_t)zb * sCb + (size_t)zh * sCh +
                            (size_t)gr * ldc + gc;
#pragma unroll
        for (int cb = 0; cb < 32; cb += 8) {
            __align__(16) __nv_bfloat16 hv[8], lv[8];
#pragma unroll
            for (int j = 0; j < 8; j++) {
                float v = crow[cb + j];
                hv[j] = __float2bfloat16(v);
                lv[j] = __float2bfloat16(v - __bfloat162float(hv[j]));
            }
            *(uint4*)(Ch + cb)          = *(uint4*)hv;
            *(uint4*)(Ch + Csplit + cb) = *(uint4*)lv;
        }
    } else if (EPI == 1) {
        float* C = (float*)Cgv + (size_t)zb * sCb + (size_t)zh * sCh + (size_t)gr * ldc + gc;
        const int* mrow = maskg + (size_t)zb * sMb + (size_t)gr * NL + gc;
#pragma unroll
        for (int j4 = 0; j4 < 8; j4++) {
            int4 m = *(const int4*)(mrow + j4 * 4);
            int mm[4] = {m.x, m.y, m.z, m.w};
            float ov[4];
#pragma unroll
            for (int j = 0; j < 4; j++) {
                float s = crow[j4 * 4 + j] * 0.0625f;   // 1/sqrt(256)
                s = fminf(15.f, fmaxf(-15.f, s));
                ov[j] = mm[j] ? s : 30000.f;
            }
            *(float4*)(C + j4 * 4) = *(float4*)ov;
        }
    } else {  // EPI == 3: plain fp32
        float* C = (float*)Cgv + (size_t)zb * sCb + (size_t)zh * sCh + (size_t)gr * ldc + gc;
#pragma unroll
        for (int j4 = 0; j4 < 8; j4++) {
            float ov[4] = {crow[j4 * 4], crow[j4 * 4 + 1], crow[j4 * 4 + 2], crow[j4 * 4 + 3]};
            *(float4*)(C + j4 * 4) = *(float4*)ov;
        }
    }
}

// ---------------------------------------------------------------------------
// masked softmax in place (sentinel > 1000 = masked); also emits bf16 hi/lo
// planes of the result for the attn@V GEMM.
// ---------------------------------------------------------------------------
__global__ void __launch_bounds__(256) softmax_k(float* __restrict__ attn,
                                                 __nv_bfloat16* __restrict__ ap)
{
    __shared__ float sh[8];
    const size_t rbase = (size_t)blockIdx.x * 1024;
    float* p = attn + rbase;
    const int t = threadIdx.x;

    float4 v4 = ((const float4*)p)[t];
    float x[4] = {v4.x, v4.y, v4.z, v4.w};
    bool msk[4];
    float mx = -1e30f;
#pragma unroll
    for (int i = 0; i < 4; i++) {
        msk[i] = (x[i] > 1000.f);
        if (msk[i]) x[i] = 0.f;
        mx = fmaxf(mx, x[i]);
    }
#pragma unroll
    for (int o = 16; o; o >>= 1) mx = fmaxf(mx, __shfl_xor_sync(0xffffffffu, mx, o));
    if ((t & 31) == 0) sh[t >> 5] = mx;
    __syncthreads();
    mx = sh[0];
#pragma unroll
    for (int i = 1; i < 8; i++) mx = fmaxf(mx, sh[i]);

    float e[4], s = 0.f;
#pragma unroll
    for (int i = 0; i < 4; i++) {
        e[i] = msk[i] ? 0.f : __expf(x[i] - mx);
        s += e[i];
    }
#pragma unroll
    for (int o = 16; o; o >>= 1) s += __shfl_xor_sync(0xffffffffu, s, o);
    __syncthreads();
    if ((t & 31) == 0) sh[t >> 5] = s;
    __syncthreads();
    s = 0.f;
#pragma unroll
    for (int i = 0; i < 8; i++) s += sh[i];

    const float inv = 1.f / (s + 1e-6f);
    float ov[4] = {e[0] * inv, e[1] * inv, e[2] * inv, e[3] * inv};
    ((float4*)p)[t] = *(float4*)ov;

    __align__(8) __nv_bfloat16 h[4], l[4];
#pragma unroll
    for (int i = 0; i < 4; i++) {
        h[i] = __float2bfloat16(ov[i]);
        l[i] = __float2bfloat16(ov[i] - __bfloat162float(h[i]));
    }
    const size_t idx = rbase + (size_t)t * 4;
    *(uint2*)(ap + idx)       = *(uint2*)h;
    *(uint2*)(ap + ATT + idx) = *(uint2*)l;
}

// ---------------------------------------------------------------------------
// split-K reduce + bias + residual + LayerNorm
// ---------------------------------------------------------------------------
__global__ void __launch_bounds__(256) fc_ln_k(
    const float* __restrict__ tmp, const float* __restrict__ fcb,
    const float* __restrict__ resid, const float* __restrict__ lg,
    const float* __restrict__ lb, float* __restrict__ out)
{
    __shared__ float shs[8], shq[8];
    const size_t o = (size_t)blockIdx.x * 256 + threadIdx.x;
    const int t = threadIdx.x;

    float v = tmp[o] + tmp[o + 1048576] + tmp[o + 2097152] + tmp[o + 3145728]
            + fcb[t] + resid[o];

    float s = v, qq = v * v;
#pragma unroll
    for (int d = 16; d; d >>= 1) {
        s  += __shfl_xor_sync(0xffffffffu, s, d);
        qq += __shfl_xor_sync(0xffffffffu, qq, d);
    }
    if ((t & 31) == 0) { shs[t >> 5] = s; shq[t >> 5] = qq; }
    __syncthreads();
    s = 0.f; qq = 0.f;
#pragma unroll
    for (int i = 0; i < 8; i++) { s += shs[i]; qq += shq[i]; }

    const float mean = s * (1.f / 256.f);
    const float var  = qq * (1.f / 256.f) - mean * mean;
    out[o] = (v - mean) * rsqrtf(var + 1e-5f) * lg[t] + lb[t];
}

// ---------------------------------------------------------------------------
extern "C" void kernel_launch(void* const* d_in, const int* in_sizes, int n_in,
                              void* d_out, int out_size)
{
    const float* q    = (const float*)d_in[0];
    const int*   mask = (const int*)  d_in[1];
    const float* k    = (const float*)d_in[2];
    const float* v    = (const float*)d_in[3];
    const float* w_qs = (const float*)d_in[4];
    const float* w_ks = (const float*)d_in[5];
    const float* w_vs = (const float*)d_in[6];
    const float* fc_w = (const float*)d_in[7];
    const float* fc_b = (const float*)d_in[8];
    const float* ln_g = (const float*)d_in[9];
    const float* ln_b = (const float*)d_in[10];

    float* out  = (float*)d_out;
    float* attn = out + (size_t)NBL * ND;

    __nv_bfloat16 *qp, *kp, *vp, *wqp, *wkp, *wvp, *fcwp, *qhp, *khp, *vht, *hop, *ap;
    float* tmp;
    cudaGetSymbolAddress((void**)&qp,   g_qp);
    cudaGetSymbolAddress((void**)&kp,   g_kp);
    cudaGetSymbolAddress((void**)&vp,   g_vp);
    cudaGetSymbolAddress((void**)&wqp,  g_wqp);
    cudaGetSymbolAddress((void**)&wkp,  g_wkp);
    cudaGetSymbolAddress((void**)&wvp,  g_wvp);
    cudaGetSymbolAddress((void**)&fcwp, g_fcwp);
    cudaGetSymbolAddress((void**)&qhp,  g_qhp);
    cudaGetSymbolAddress((void**)&khp,  g_khp);
    cudaGetSymbolAddress((void**)&vht,  g_vht);
    cudaGetSymbolAddress((void**)&hop,  g_hop);
    cudaGetSymbolAddress((void**)&ap,   g_ap);
    cudaGetSymbolAddress((void**)&tmp,  g_tmp);

    cudaFuncSetAttribute(tgemm<0>, cudaFuncAttributeMaxDynamicSharedMemorySize, SMEMB);
    cudaFuncSetAttribute(tgemm<1>, cudaFuncAttributeMaxDynamicSharedMemorySize, SMEMB);
    cudaFuncSetAttribute(tgemm<3>, cudaFuncAttributeMaxDynamicSharedMemorySize, SMEMB);

    // ---- convert fp32 -> bf16 hi/lo planes ----
    cvt_k<<<(NBL * ND / 4 + 255) / 256, 256>>>(q, qp, qp + NBL * ND, NBL * ND / 4);
    cvt_k<<<(NBL * ND / 4 + 255) / 256, 256>>>(k, kp, kp + NBL * ND, NBL * ND / 4);
    cvt_k<<<(NBL * ND / 4 + 255) / 256, 256>>>(v, vp, vp + NBL * ND, NBL * ND / 4);
    cvt_k<<<(NHD * ND / 4 + 255) / 256, 256>>>(w_qs, wqp, wqp + NHD * ND, NHD * ND / 4);
    cvt_k<<<(NHD * ND / 4 + 255) / 256, 256>>>(w_ks, wkp, wkp + NHD * ND, NHD * ND / 4);
    cvt_k<<<(NHD * ND / 4 + 255) / 256, 256>>>(w_vs, wvp, wvp + NHD * ND, NHD * ND / 4);
    cvt_k<<<(ND * NHD / 4 + 255) / 256, 256>>>(fc_w, fcwp, fcwp + ND * NHD, ND * NHD / 4);

    const long QKSZ = (long)NBL * ND;        // 1048576
    const long WSZ  = (long)NHD * ND;        // 524288
    const long BIG  = (long)NBL * NHD;       // 8388608

    // ---- Q, K projections: [4096,2048] = x @ w^T ----
    tgemm<0><<<dim3(16, 32, 1), 512, SMEMB>>>(
        qp, QKSZ, ND, wqp, WSZ, ND, qhp, NHD, BIG, ND, 1,
        0, 0, 0, 0, 0, 0, nullptr, 0);
    tgemm<0><<<dim3(16, 32, 1), 512, SMEMB>>>(
        kp, QKSZ, ND, wkp, WSZ, ND, khp, NHD, BIG, ND, 1,
        0, 0, 0, 0, 0, 0, nullptr, 0);

    // ---- V projection, transposed output: vht[hd, token] = w_vs @ v^T ----
    tgemm<0><<<dim3(32, 16, 1), 512, SMEMB>>>(
        wvp, WSZ, ND, vp, QKSZ, ND, vht, NBL, BIG, ND, 1,
        0, 0, 0, 0, 0, 0, nullptr, 0);

    // ---- scores: per (b,h)  attn[(h*B+b)] = qh @ kh^T /16, clip, mask ----
    tgemm<1><<<dim3(8, 8, 32), 512, SMEMB>>>(
        qhp, BIG, NHD, khp, BIG, NHD, attn, NL, 0, ND, NB,
        (long)NL * NHD, (long)ND,
        (long)NL * NHD, (long)ND,
        (long)NL * NL, (long)NB * NL * NL,
        mask, (long)NL * NL);

    // ---- masked softmax in place + bf16 plane emission ----
    softmax_k<<<NH * NB * NL, 256>>>(attn, ap);

    // ---- attn @ V: hop[b,l, h*256+d] ----
    tgemm<0><<<dim3(2, 8, 32), 512, SMEMB>>>(
        ap, (long)ATT, NL, vht, BIG, NBL, hop, NHD, BIG, NL, NB,
        (long)NL * NL, (long)NB * NL * NL,
        (long)NL, (long)ND * NBL,
        (long)NL * NHD, (long)ND,
        nullptr, 0);

    // ---- fc: split-K = 4 -> fp32 partials ----
    tgemm<3><<<dim3(2, 32, 4), 512, SMEMB>>>(
        hop, BIG, NHD, fcwp, (long)ND * NHD, NHD, tmp, ND, 0, 512, 1,
        0, 512, 0, 512, 0, (long)NBL * ND, nullptr, 0);

    // ---- reduce + bias + residual + LayerNorm ----
    fc_ln_k<<<NBL, 256>>>(tmp, fc_b, q, ln_g, ln_b, out);
}

// round 6
// speedup vs baseline: 1.0098x; 1.0098x over previous
#include <cuda_runtime.h>
#include <cuda_bf16.h>
#include <mma.h>
#include <cstdint>

using namespace nvcuda;

#define NB 4
#define NL 1024
#define ND 256
#define NH 8
#define NHD 2048
#define NBL 4096
#define ATT ((size_t)NB * NH * NL * NL)   // 33,554,432 attn elems

#define LDS_AB 72              // BK(64) + 8 pad -> 144B rows, LDSM conflict-free
#define PLE (128 * LDS_AB)     // elems per plane tile (9216)
#define PLB (PLE * 2)          // bytes per plane tile (18432)
#define STGB (4 * PLB)         // bytes per stage: Ahi|Alo|Bhi|Blo (73728)
#define NSTG 3                 // pipeline stages
#define LDC_S 132              // epilogue smem stride (floats)
#define SMEMB (NSTG * STGB)    // 221184 B (>= Cs 67584 B)

// ---------------------------------------------------------------------------
// cp.async helpers
// ---------------------------------------------------------------------------
__device__ __forceinline__ uint32_t smem_u32(const void* p) {
    uint32_t a;
    asm("{ .reg .u64 t; cvta.to.shared.u64 t, %1; cvt.u32.u64 %0, t; }" : "=r"(a) : "l"(p));
    return a;
}
#define CP_ASYNC16(dst, src) \
    asm volatile("cp.async.cg.shared.global [%0], [%1], 16;" :: "r"(dst), "l"(src) : "memory")
#define CP_COMMIT() asm volatile("cp.async.commit_group;" ::: "memory")
#define CP_WAIT0()  asm volatile("cp.async.wait_group 0;" ::: "memory")
#define CP_WAIT1()  asm volatile("cp.async.wait_group 1;" ::: "memory")

// ---------------------------------------------------------------------------
// scratch (device globals — allocations forbidden)
// ---------------------------------------------------------------------------
static __device__ __align__(16) __nv_bfloat16 g_qp[2 * NBL * ND];
static __device__ __align__(16) __nv_bfloat16 g_kp[2 * NBL * ND];
static __device__ __align__(16) __nv_bfloat16 g_vp[2 * NBL * ND];
static __device__ __align__(16) __nv_bfloat16 g_wqp[2 * NHD * ND];
static __device__ __align__(16) __nv_bfloat16 g_wkp[2 * NHD * ND];
static __device__ __align__(16) __nv_bfloat16 g_wvp[2 * NHD * ND];
static __device__ __align__(16) __nv_bfloat16 g_fcwp[2 * ND * NHD];
static __device__ __align__(16) __nv_bfloat16 g_qhp[2 * (size_t)NBL * NHD];
static __device__ __align__(16) __nv_bfloat16 g_khp[2 * (size_t)NBL * NHD];
static __device__ __align__(16) __nv_bfloat16 g_vht[2 * (size_t)NHD * NBL];
static __device__ __align__(16) __nv_bfloat16 g_hop[2 * (size_t)NBL * NHD];
static __device__ __align__(16) __nv_bfloat16 g_ap[2 * ATT];   // softmaxed attn planes
static __device__ float g_tmp[(size_t)4 * NBL * ND];

// ---------------------------------------------------------------------------
// fp32 -> (hi, lo) bf16 planes
// ---------------------------------------------------------------------------
__global__ void __launch_bounds__(256) cvt_k(const float* __restrict__ x,
                                             __nv_bfloat16* __restrict__ hi,
                                             __nv_bfloat16* __restrict__ lo, int n4) {
    int i = blockIdx.x * 256 + threadIdx.x;
    if (i >= n4) return;
    float4 v = *((const float4*)x + i);
    float f[4] = {v.x, v.y, v.z, v.w};
    __align__(8) __nv_bfloat16 h[4], l[4];
#pragma unroll
    for (int j = 0; j < 4; j++) {
        h[j] = __float2bfloat16(f[j]);
        l[j] = __float2bfloat16(f[j] - __bfloat162float(h[j]));
    }
    *(uint2*)(hi + (size_t)i * 4) = *(uint2*)h;
    *(uint2*)(lo + (size_t)i * 4) = *(uint2*)l;
}

// ---------------------------------------------------------------------------
// WMMA bf16x3 GEMM, cp.async 3-stage pipeline, BK=64, ONE sync per stage.
//   C[128x128 tile] = A @ B^T, fp32 accumulate; A/B are bf16 hi/lo planes.
//   EPI 0: write bf16 hi/lo pairs   1: scores (scale/clip/mask -> sentinel)
//   EPI 3: plain fp32 (fc split-K partials)
// 256 threads (8 warps, 2x4 grid), warp tile 64x32 (best measured config).
// ---------------------------------------------------------------------------
template <int EPI>
__global__ void __launch_bounds__(256, 1) tgemm(
    const __nv_bfloat16* __restrict__ Ag, long Asplit, int lda,
    const __nv_bfloat16* __restrict__ Bg, long Bsplit, int ldb,
    void* __restrict__ Cgv, int ldc, long Csplit,
    int K, int nBdim,
    long sAb, long sAh, long sBb, long sBh, long sCb, long sCh,
    const int* __restrict__ maskg, long sMb)
{
    extern __shared__ __align__(16) char sm[];
    const uint32_t smb = smem_u32(sm);
    float* Cs = (float*)sm;   // epilogue staging (reuses pipeline smem)

    const int tid = threadIdx.x;
    const int wid = tid >> 5;
    const int wm = wid & 1;   // warp row (2 x 64)
    const int wn = wid >> 1;  // warp col (4 x 32)

    const int z = blockIdx.z, zb = z % nBdim, zh = z / nBdim;
    const __nv_bfloat16* Ap = Ag + (size_t)zb * sAb + (size_t)zh * sAh;
    const __nv_bfloat16* Bp = Bg + (size_t)zb * sBb + (size_t)zh * sBh;

    const int rowBase = blockIdx.y * 128;
    const int colBase = blockIdx.x * 128;

    wmma::fragment<wmma::accumulator, 16, 16, 16, float> acc[4][2];
#pragma unroll
    for (int i = 0; i < 4; i++)
#pragma unroll
        for (int j = 0; j < 2; j++) wmma::fill_fragment(acc[i][j], 0.f);

    // issue one stage of async loads: 4 planes x 1024 16B-chunks, 256 threads
    auto ldst = [&](int t, int s) {
        const int ko = t * 64;
        const uint32_t sb = smb + s * STGB;
#pragma unroll
        for (int i = 0; i < 4; i++) {
            const int c = tid + i * 256;          // 0..1023
            const int row = c >> 3, col = (c & 7) * 8;
            const uint32_t soff = (uint32_t)(row * LDS_AB + col) * 2;
            const __nv_bfloat16* pa = Ap + (size_t)(rowBase + row) * lda + ko + col;
            CP_ASYNC16(sb + soff,           pa);
            CP_ASYNC16(sb + PLB + soff,     pa + Asplit);
            const __nv_bfloat16* pb = Bp + (size_t)(colBase + row) * ldb + ko + col;
            CP_ASYNC16(sb + 2 * PLB + soff, pb);
            CP_ASYNC16(sb + 3 * PLB + soff, pb + Bsplit);
        }
        CP_COMMIT();
    };

    auto compute = [&](int s) {
        const __nv_bfloat16* base = (const __nv_bfloat16*)(sm + s * STGB);
        const __nv_bfloat16* Ah0 = base + wm * 64 * LDS_AB;
        const __nv_bfloat16* Al0 = Ah0 + PLE;
        const __nv_bfloat16* Bh0 = base + 2 * PLE + wn * 32 * LDS_AB;
        const __nv_bfloat16* Bl0 = Bh0 + PLE;
#pragma unroll
        for (int ks = 0; ks < 4; ks++) {
            wmma::fragment<wmma::matrix_a, 16, 16, 16, __nv_bfloat16, wmma::row_major> fah[4], fal[4];
            wmma::fragment<wmma::matrix_b, 16, 16, 16, __nv_bfloat16, wmma::col_major> fbh[2], fbl[2];
#pragma unroll
            for (int i = 0; i < 4; i++) {
                wmma::load_matrix_sync(fah[i], Ah0 + i * 16 * LDS_AB + ks * 16, LDS_AB);
                wmma::load_matrix_sync(fal[i], Al0 + i * 16 * LDS_AB + ks * 16, LDS_AB);
            }
#pragma unroll
            for (int j = 0; j < 2; j++) {
                wmma::load_matrix_sync(fbh[j], Bh0 + j * 16 * LDS_AB + ks * 16, LDS_AB);
                wmma::load_matrix_sync(fbl[j], Bl0 + j * 16 * LDS_AB + ks * 16, LDS_AB);
            }
#pragma unroll
            for (int i = 0; i < 4; i++)
#pragma unroll
                for (int j = 0; j < 2; j++) {
                    wmma::mma_sync(acc[i][j], fah[i], fbh[j], acc[i][j]);
                    wmma::mma_sync(acc[i][j], fah[i], fbl[j], acc[i][j]);
                    wmma::mma_sync(acc[i][j], fal[i], fbh[j], acc[i][j]);
                }
        }
    };

    // ---- 3-stage pipelined mainloop, one sync per stage ----
    const int T = K >> 6;
    ldst(0, 0);
    ldst(1, 1);
    for (int t = 0; t < T; t++) {
        if (t == T - 1) { CP_WAIT0(); } else { CP_WAIT1(); }
        __syncthreads();                      // stage t visible; slot (t+2)%3 free
        if (t + 2 < T) ldst(t + 2, (t + 2) % NSTG);
        compute(t % NSTG);
    }

    // ---- epilogue: stage accumulators through SMEM ----
    __syncthreads();
#pragma unroll
    for (int i = 0; i < 4; i++)
#pragma unroll
        for (int j = 0; j < 2; j++)
            wmma::store_matrix_sync(Cs + (size_t)(wm * 64 + i * 16) * LDC_S + wn * 32 + j * 16,
                                    acc[i][j], LDC_S, wmma::mem_row_major);
    __syncthreads();

    const int row = tid >> 1;
    const int ch  = (tid & 1) * 64;
    const float* crow = Cs + (size_t)row * LDC_S + ch;
    const int gr = rowBase + row;
    const int gc = colBase + ch;

    if (EPI == 0) {
        __nv_bfloat16* Ch = (__nv_bfloat16*)Cgv + (size_t)zb * sCb + (size_t)zh * sCh +
                            (size_t)gr * ldc + gc;
#pragma unroll
        for (int cb = 0; cb < 64; cb += 8) {
            __align__(16) __nv_bfloat16 hv[8], lv[8];
#pragma unroll
            for (int j = 0; j < 8; j++) {
                float v = crow[cb + j];
                hv[j] = __float2bfloat16(v);
                lv[j] = __float2bfloat16(v - __bfloat162float(hv[j]));
            }
            *(uint4*)(Ch + cb)          = *(uint4*)hv;
            *(uint4*)(Ch + Csplit + cb) = *(uint4*)lv;
        }
    } else if (EPI == 1) {
        float* C = (float*)Cgv + (size_t)zb * sCb + (size_t)zh * sCh + (size_t)gr * ldc + gc;
        const int* mrow = maskg + (size_t)zb * sMb + (size_t)gr * NL + gc;
#pragma unroll
        for (int j4 = 0; j4 < 16; j4++) {
            int4 m = *(const int4*)(mrow + j4 * 4);
            int mm[4] = {m.x, m.y, m.z, m.w};
            float ov[4];
#pragma unroll
            for (int j = 0; j < 4; j++) {
                float s = crow[j4 * 4 + j] * 0.0625f;   // 1/sqrt(256)
                s = fminf(15.f, fmaxf(-15.f, s));
                ov[j] = mm[j] ? s : 30000.f;
            }
            *(float4*)(C + j4 * 4) = *(float4*)ov;
        }
    } else {  // EPI == 3: plain fp32
        float* C = (float*)Cgv + (size_t)zb * sCb + (size_t)zh * sCh + (size_t)gr * ldc + gc;
#pragma unroll
        for (int j4 = 0; j4 < 16; j4++) {
            float ov[4] = {crow[j4 * 4], crow[j4 * 4 + 1], crow[j4 * 4 + 2], crow[j4 * 4 + 3]};
            *(float4*)(C + j4 * 4) = *(float4*)ov;
        }
    }
}

// ---------------------------------------------------------------------------
// masked softmax in place (sentinel > 1000 = masked); also emits bf16 hi/lo
// planes of the result for the attn@V GEMM.
// ---------------------------------------------------------------------------
__global__ void __launch_bounds__(256) softmax_k(float* __restrict__ attn,
                                                 __nv_bfloat16* __restrict__ ap)
{
    __shared__ float sh[8];
    const size_t rbase = (size_t)blockIdx.x * 1024;
    float* p = attn + rbase;
    const int t = threadIdx.x;

    float4 v4 = ((const float4*)p)[t];
    float x[4] = {v4.x, v4.y, v4.z, v4.w};
    bool msk[4];
    float mx = -1e30f;
#pragma unroll
    for (int i = 0; i < 4; i++) {
        msk[i] = (x[i] > 1000.f);
        if (msk[i]) x[i] = 0.f;
        mx = fmaxf(mx, x[i]);
    }
#pragma unroll
    for (int o = 16; o; o >>= 1) mx = fmaxf(mx, __shfl_xor_sync(0xffffffffu, mx, o));
    if ((t & 31) == 0) sh[t >> 5] = mx;
    __syncthreads();
    mx = sh[0];
#pragma unroll
    for (int i = 1; i < 8; i++) mx = fmaxf(mx, sh[i]);

    float e[4], s = 0.f;
#pragma unroll
    for (int i = 0; i < 4; i++) {
        e[i] = msk[i] ? 0.f : __expf(x[i] - mx);
        s += e[i];
    }
#pragma unroll
    for (int o = 16; o; o >>= 1) s += __shfl_xor_sync(0xffffffffu, s, o);
    __syncthreads();
    if ((t & 31) == 0) sh[t >> 5] = s;
    __syncthreads();
    s = 0.f;
#pragma unroll
    for (int i = 0; i < 8; i++) s += sh[i];

    const float inv = 1.f / (s + 1e-6f);
    float ov[4] = {e[0] * inv, e[1] * inv, e[2] * inv, e[3] * inv};
    ((float4*)p)[t] = *(float4*)ov;

    __align__(8) __nv_bfloat16 h[4], l[4];
#pragma unroll
    for (int i = 0; i < 4; i++) {
        h[i] = __float2bfloat16(ov[i]);
        l[i] = __float2bfloat16(ov[i] - __bfloat162float(h[i]));
    }
    const size_t idx = rbase + (size_t)t * 4;
    *(uint2*)(ap + idx)       = *(uint2*)h;
    *(uint2*)(ap + ATT + idx) = *(uint2*)l;
}

// ---------------------------------------------------------------------------
// split-K reduce + bias + residual + LayerNorm
// ---------------------------------------------------------------------------
__global__ void __launch_bounds__(256) fc_ln_k(
    const float* __restrict__ tmp, const float* __restrict__ fcb,
    const float* __restrict__ resid, const float* __restrict__ lg,
    const float* __restrict__ lb, float* __restrict__ out)
{
    __shared__ float shs[8], shq[8];
    const size_t o = (size_t)blockIdx.x * 256 + threadIdx.x;
    const int t = threadIdx.x;

    float v = tmp[o] + tmp[o + 1048576] + tmp[o + 2097152] + tmp[o + 3145728]
            + fcb[t] + resid[o];

    float s = v, qq = v * v;
#pragma unroll
    for (int d = 16; d; d >>= 1) {
        s  += __shfl_xor_sync(0xffffffffu, s, d);
        qq += __shfl_xor_sync(0xffffffffu, qq, d);
    }
    if ((t & 31) == 0) { shs[t >> 5] = s; shq[t >> 5] = qq; }
    __syncthreads();
    s = 0.f; qq = 0.f;
#pragma unroll
    for (int i = 0; i < 8; i++) { s += shs[i]; qq += shq[i]; }

    const float mean = s * (1.f / 256.f);
    const float var  = qq * (1.f / 256.f) - mean * mean;
    out[o] = (v - mean) * rsqrtf(var + 1e-5f) * lg[t] + lb[t];
}

// ---------------------------------------------------------------------------
extern "C" void kernel_launch(void* const* d_in, const int* in_sizes, int n_in,
                              void* d_out, int out_size)
{
    const float* q    = (const float*)d_in[0];
    const int*   mask = (const int*)  d_in[1];
    const float* k    = (const float*)d_in[2];
    const float* v    = (const float*)d_in[3];
    const float* w_qs = (const float*)d_in[4];
    const float* w_ks = (const float*)d_in[5];
    const float* w_vs = (const float*)d_in[6];
    const float* fc_w = (const float*)d_in[7];
    const float* fc_b = (const float*)d_in[8];
    const float* ln_g = (const float*)d_in[9];
    const float* ln_b = (const float*)d_in[10];

    float* out  = (float*)d_out;
    float* attn = out + (size_t)NBL * ND;

    __nv_bfloat16 *qp, *kp, *vp, *wqp, *wkp, *wvp, *fcwp, *qhp, *khp, *vht, *hop, *ap;
    float* tmp;
    cudaGetSymbolAddress((void**)&qp,   g_qp);
    cudaGetSymbolAddress((void**)&kp,   g_kp);
    cudaGetSymbolAddress((void**)&vp,   g_vp);
    cudaGetSymbolAddress((void**)&wqp,  g_wqp);
    cudaGetSymbolAddress((void**)&wkp,  g_wkp);
    cudaGetSymbolAddress((void**)&wvp,  g_wvp);
    cudaGetSymbolAddress((void**)&fcwp, g_fcwp);
    cudaGetSymbolAddress((void**)&qhp,  g_qhp);
    cudaGetSymbolAddress((void**)&khp,  g_khp);
    cudaGetSymbolAddress((void**)&vht,  g_vht);
    cudaGetSymbolAddress((void**)&hop,  g_hop);
    cudaGetSymbolAddress((void**)&ap,   g_ap);
    cudaGetSymbolAddress((void**)&tmp,  g_tmp);

    cudaFuncSetAttribute(tgemm<0>, cudaFuncAttributeMaxDynamicSharedMemorySize, SMEMB);
    cudaFuncSetAttribute(tgemm<1>, cudaFuncAttributeMaxDynamicSharedMemorySize, SMEMB);
    cudaFuncSetAttribute(tgemm<3>, cudaFuncAttributeMaxDynamicSharedMemorySize, SMEMB);

    // ---- convert fp32 -> bf16 hi/lo planes ----
    cvt_k<<<(NBL * ND / 4 + 255) / 256, 256>>>(q, qp, qp + NBL * ND, NBL * ND / 4);
    cvt_k<<<(NBL * ND / 4 + 255) / 256, 256>>>(k, kp, kp + NBL * ND, NBL * ND / 4);
    cvt_k<<<(NBL * ND / 4 + 255) / 256, 256>>>(v, vp, vp + NBL * ND, NBL * ND / 4);
    cvt_k<<<(NHD * ND / 4 + 255) / 256, 256>>>(w_qs, wqp, wqp + NHD * ND, NHD * ND / 4);
    cvt_k<<<(NHD * ND / 4 + 255) / 256, 256>>>(w_ks, wkp, wkp + NHD * ND, NHD * ND / 4);
    cvt_k<<<(NHD * ND / 4 + 255) / 256, 256>>>(w_vs, wvp, wvp + NHD * ND, NHD * ND / 4);
    cvt_k<<<(ND * NHD / 4 + 255) / 256, 256>>>(fc_w, fcwp, fcwp + ND * NHD, ND * NHD / 4);

    const long QKSZ = (long)NBL * ND;        // 1048576
    const long WSZ  = (long)NHD * ND;        // 524288
    const long BIG  = (long)NBL * NHD;       // 8388608

    // ---- Q, K projections: [4096,2048] = x @ w^T ----
    tgemm<0><<<dim3(16, 32, 1), 256, SMEMB>>>(
        qp, QKSZ, ND, wqp, WSZ, ND, qhp, NHD, BIG, ND, 1,
        0, 0, 0, 0, 0, 0, nullptr, 0);
    tgemm<0><<<dim3(16, 32, 1), 256, SMEMB>>>(
        kp, QKSZ, ND, wkp, WSZ, ND, khp, NHD, BIG, ND, 1,
        0, 0, 0, 0, 0, 0, nullptr, 0);

    // ---- V projection, transposed output: vht[hd, token] = w_vs @ v^T ----
    tgemm<0><<<dim3(32, 16, 1), 256, SMEMB>>>(
        wvp, WSZ, ND, vp, QKSZ, ND, vht, NBL, BIG, ND, 1,
        0, 0, 0, 0, 0, 0, nullptr, 0);

    // ---- scores: per (b,h)  attn[(h*B+b)] = qh @ kh^T /16, clip, mask ----
    tgemm<1><<<dim3(8, 8, 32), 256, SMEMB>>>(
        qhp, BIG, NHD, khp, BIG, NHD, attn, NL, 0, ND, NB,
        (long)NL * NHD, (long)ND,
        (long)NL * NHD, (long)ND,
        (long)NL * NL, (long)NB * NL * NL,
        mask, (long)NL * NL);

    // ---- masked softmax in place + bf16 plane emission ----
    softmax_k<<<NH * NB * NL, 256>>>(attn, ap);

    // ---- attn @ V: hop[b,l, h*256+d] ----
    tgemm<0><<<dim3(2, 8, 32), 256, SMEMB>>>(
        ap, (long)ATT, NL, vht, BIG, NBL, hop, NHD, BIG, NL, NB,
        (long)NL * NL, (long)NB * NL * NL,
        (long)NL, (long)ND * NBL,
        (long)NL * NHD, (long)ND,
        nullptr, 0);

    // ---- fc: split-K = 4 -> fp32 partials ----
    tgemm<3><<<dim3(2, 32, 4), 256, SMEMB>>>(
        hop, BIG, NHD, fcwp, (long)ND * NHD, NHD, tmp, ND, 0, 512, 1,
        0, 512, 0, 512, 0, (long)NBL * ND, nullptr, 0);

    // ---- reduce + bias + residual + LayerNorm ----
    fc_ln_k<<<NBL, 256>>>(tmp, fc_b, q, ln_g, ln_b, out);
}

// round 7
// speedup vs baseline: 1.0628x; 1.0525x over previous
#include <cuda_runtime.h>
#include <cuda_bf16.h>
#include <mma.h>
#include <cstdint>

using namespace nvcuda;

#define NB 4
#define NL 1024
#define ND 256
#define NH 8
#define NHD 2048
#define NBL 4096
#define ATT ((size_t)NB * NH * NL * NL)   // 33,554,432 attn elems

#define LDS_AB 72              // BK(64) + 8 pad -> 144B rows, LDSM conflict-free
#define PLE (128 * LDS_AB)     // elems per plane tile (9216)
#define PLB (PLE * 2)          // bytes per plane tile (18432)
#define STGB (4 * PLB)         // bytes per stage: Ahi|Alo|Bhi|Blo (73728)
#define LDC_S 132              // epilogue smem stride (floats)
#define SMEMB (2 * STGB)       // 147456 B (>= Cs 67584 B)

// ---------------------------------------------------------------------------
// cp.async helpers
// ---------------------------------------------------------------------------
__device__ __forceinline__ uint32_t smem_u32(const void* p) {
    uint32_t a;
    asm("{ .reg .u64 t; cvta.to.shared.u64 t, %1; cvt.u32.u64 %0, t; }" : "=r"(a) : "l"(p));
    return a;
}
#define CP_ASYNC16(dst, src) \
    asm volatile("cp.async.cg.shared.global [%0], [%1], 16;" :: "r"(dst), "l"(src) : "memory")
#define CP_COMMIT() asm volatile("cp.async.commit_group;" ::: "memory")
#define CP_WAIT0()  asm volatile("cp.async.wait_group 0;" ::: "memory")
#define CP_WAIT1()  asm volatile("cp.async.wait_group 1;" ::: "memory")

// ---------------------------------------------------------------------------
// scratch (device globals — allocations forbidden)
// ---------------------------------------------------------------------------
static __device__ __align__(16) __nv_bfloat16 g_qp[2 * NBL * ND];
static __device__ __align__(16) __nv_bfloat16 g_kp[2 * NBL * ND];
static __device__ __align__(16) __nv_bfloat16 g_vp[2 * NBL * ND];
static __device__ __align__(16) __nv_bfloat16 g_wqp[2 * NHD * ND];
static __device__ __align__(16) __nv_bfloat16 g_wkp[2 * NHD * ND];
static __device__ __align__(16) __nv_bfloat16 g_wvp[2 * NHD * ND];
static __device__ __align__(16) __nv_bfloat16 g_fcwp[2 * ND * NHD];
static __device__ __align__(16) __nv_bfloat16 g_qhp[2 * (size_t)NBL * NHD];
static __device__ __align__(16) __nv_bfloat16 g_khp[2 * (size_t)NBL * NHD];
static __device__ __align__(16) __nv_bfloat16 g_vht[2 * (size_t)NHD * NBL];
static __device__ __align__(16) __nv_bfloat16 g_hop[2 * (size_t)NBL * NHD];
static __device__ __align__(16) __nv_bfloat16 g_ap[2 * ATT];   // softmaxed attn planes
static __device__ float g_tmp[(size_t)4 * NBL * ND];

// ---------------------------------------------------------------------------
// fused fp32 -> (hi, lo) bf16 planes for up to 4 tensors (blockIdx.y selects)
// ---------------------------------------------------------------------------
__global__ void __launch_bounds__(256) cvt4_k(
    const float* __restrict__ s0, const float* __restrict__ s1,
    const float* __restrict__ s2, const float* __restrict__ s3,
    __nv_bfloat16* __restrict__ d0, __nv_bfloat16* __restrict__ d1,
    __nv_bfloat16* __restrict__ d2, __nv_bfloat16* __restrict__ d3,
    int n4, long split)
{
    const int which = blockIdx.y;
    const float* x = which == 0 ? s0 : which == 1 ? s1 : which == 2 ? s2 : s3;
    __nv_bfloat16* hi = which == 0 ? d0 : which == 1 ? d1 : which == 2 ? d2 : d3;
    int i = blockIdx.x * 256 + threadIdx.x;
    if (i >= n4) return;
    float4 v = *((const float4*)x + i);
    float f[4] = {v.x, v.y, v.z, v.w};
    __align__(8) __nv_bfloat16 h[4], l[4];
#pragma unroll
    for (int j = 0; j < 4; j++) {
        h[j] = __float2bfloat16(f[j]);
        l[j] = __float2bfloat16(f[j] - __bfloat162float(h[j]));
    }
    *(uint2*)(hi + (size_t)i * 4)         = *(uint2*)h;
    *(uint2*)(hi + split + (size_t)i * 4) = *(uint2*)l;
}

// ---------------------------------------------------------------------------
// WMMA bf16x3 GEMM, cp.async 2-stage pipeline, BK=64 (R4 structure — best).
//   C[128x128 tile] = A @ B^T, fp32 accumulate; A/B are bf16 hi/lo planes.
//   EPI 0: write bf16 hi/lo pairs   1: scores (scale/clip/mask -> sentinel)
//   EPI 3: plain fp32 (fc split-K partials)
// 256 threads (8 warps, 2x4 grid), warp tile 64x32.
// ---------------------------------------------------------------------------
template <int EPI>
__global__ void __launch_bounds__(256, 1) tgemm(
    const __nv_bfloat16* __restrict__ Ag, long Asplit, int lda,
    const __nv_bfloat16* __restrict__ Bg, long Bsplit, int ldb,
    void* __restrict__ Cgv, int ldc, long Csplit,
    int K, int nBdim,
    long sAb, long sAh, long sBb, long sBh, long sCb, long sCh,
    const int* __restrict__ maskg, long sMb)
{
    extern __shared__ __align__(16) char sm[];
    const uint32_t smb = smem_u32(sm);
    float* Cs = (float*)sm;   // epilogue staging (reuses pipeline smem)

    const int tid = threadIdx.x;
    const int wid = tid >> 5;
    const int wm = wid & 1;   // warp row (2 x 64)
    const int wn = wid >> 1;  // warp col (4 x 32)

    const int z = blockIdx.z, zb = z % nBdim, zh = z / nBdim;
    const __nv_bfloat16* Ap = Ag + (size_t)zb * sAb + (size_t)zh * sAh;
    const __nv_bfloat16* Bp = Bg + (size_t)zb * sBb + (size_t)zh * sBh;

    const int rowBase = blockIdx.y * 128;
    const int colBase = blockIdx.x * 128;

    wmma::fragment<wmma::accumulator, 16, 16, 16, float> acc[4][2];
#pragma unroll
    for (int i = 0; i < 4; i++)
#pragma unroll
        for (int j = 0; j < 2; j++) wmma::fill_fragment(acc[i][j], 0.f);

    // issue one stage of async loads: 4 planes x 1024 16B-chunks, 256 threads
    auto ldst = [&](int t, int s) {
        const int ko = t * 64;
        const uint32_t sb = smb + s * STGB;
#pragma unroll
        for (int i = 0; i < 4; i++) {
            const int c = tid + i * 256;          // 0..1023
            const int row = c >> 3, col = (c & 7) * 8;
            const uint32_t soff = (uint32_t)(row * LDS_AB + col) * 2;
            const __nv_bfloat16* pa = Ap + (size_t)(rowBase + row) * lda + ko + col;
            CP_ASYNC16(sb + soff,           pa);
            CP_ASYNC16(sb + PLB + soff,     pa + Asplit);
            const __nv_bfloat16* pb = Bp + (size_t)(colBase + row) * ldb + ko + col;
            CP_ASYNC16(sb + 2 * PLB + soff, pb);
            CP_ASYNC16(sb + 3 * PLB + soff, pb + Bsplit);
        }
        CP_COMMIT();
    };

    auto compute = [&](int s) {
        const __nv_bfloat16* base = (const __nv_bfloat16*)(sm + s * STGB);
        const __nv_bfloat16* Ah0 = base + wm * 64 * LDS_AB;
        const __nv_bfloat16* Al0 = Ah0 + PLE;
        const __nv_bfloat16* Bh0 = base + 2 * PLE + wn * 32 * LDS_AB;
        const __nv_bfloat16* Bl0 = Bh0 + PLE;
#pragma unroll
        for (int ks = 0; ks < 4; ks++) {
            wmma::fragment<wmma::matrix_a, 16, 16, 16, __nv_bfloat16, wmma::row_major> fah[4], fal[4];
            wmma::fragment<wmma::matrix_b, 16, 16, 16, __nv_bfloat16, wmma::col_major> fbh[2], fbl[2];
#pragma unroll
            for (int i = 0; i < 4; i++) {
                wmma::load_matrix_sync(fah[i], Ah0 + i * 16 * LDS_AB + ks * 16, LDS_AB);
                wmma::load_matrix_sync(fal[i], Al0 + i * 16 * LDS_AB + ks * 16, LDS_AB);
            }
#pragma unroll
            for (int j = 0; j < 2; j++) {
                wmma::load_matrix_sync(fbh[j], Bh0 + j * 16 * LDS_AB + ks * 16, LDS_AB);
                wmma::load_matrix_sync(fbl[j], Bl0 + j * 16 * LDS_AB + ks * 16, LDS_AB);
            }
#pragma unroll
            for (int i = 0; i < 4; i++)
#pragma unroll
                for (int j = 0; j < 2; j++) {
                    wmma::mma_sync(acc[i][j], fah[i], fbh[j], acc[i][j]);
                    wmma::mma_sync(acc[i][j], fah[i], fbl[j], acc[i][j]);
                    wmma::mma_sync(acc[i][j], fal[i], fbh[j], acc[i][j]);
                }
        }
    };

    // ---- 2-stage pipelined mainloop (R4 structure) ----
    const int T = K >> 6;
    ldst(0, 0);
    ldst(1, 1);
    for (int t = 0; t < T; t++) {
        if (t == T - 1) { CP_WAIT0(); } else { CP_WAIT1(); }
        __syncthreads();
        compute(t & 1);
        __syncthreads();
        if (t + 2 < T) ldst(t + 2, t & 1);
    }

    // ---- epilogue: stage accumulators through SMEM ----
#pragma unroll
    for (int i = 0; i < 4; i++)
#pragma unroll
        for (int j = 0; j < 2; j++)
            wmma::store_matrix_sync(Cs + (size_t)(wm * 64 + i * 16) * LDC_S + wn * 32 + j * 16,
                                    acc[i][j], LDC_S, wmma::mem_row_major);
    __syncthreads();

    const int row = tid >> 1;
    const int ch  = (tid & 1) * 64;
    const float* crow = Cs + (size_t)row * LDC_S + ch;
    const int gr = rowBase + row;
    const int gc = colBase + ch;

    if (EPI == 0) {
        __nv_bfloat16* Ch = (__nv_bfloat16*)Cgv + (size_t)zb * sCb + (size_t)zh * sCh +
                            (size_t)gr * ldc + gc;
#pragma unroll
        for (int cb = 0; cb < 64; cb += 8) {
            __align__(16) __nv_bfloat16 hv[8], lv[8];
#pragma unroll
            for (int j = 0; j < 8; j++) {
                float v = crow[cb + j];
                hv[j] = __float2bfloat16(v);
                lv[j] = __float2bfloat16(v - __bfloat162float(hv[j]));
            }
            *(uint4*)(Ch + cb)          = *(uint4*)hv;
            *(uint4*)(Ch + Csplit + cb) = *(uint4*)lv;
        }
    } else if (EPI == 1) {
        float* C = (float*)Cgv + (size_t)zb * sCb + (size_t)zh * sCh + (size_t)gr * ldc + gc;
        const int* mrow = maskg + (size_t)zb * sMb + (size_t)gr * NL + gc;
#pragma unroll
        for (int j4 = 0; j4 < 16; j4++) {
            int4 m = *(const int4*)(mrow + j4 * 4);
            int mm[4] = {m.x, m.y, m.z, m.w};
            float ov[4];
#pragma unroll
            for (int j = 0; j < 4; j++) {
                float s = crow[j4 * 4 + j] * 0.0625f;   // 1/sqrt(256)
                s = fminf(15.f, fmaxf(-15.f, s));
                ov[j] = mm[j] ? s : 30000.f;
            }
            *(float4*)(C + j4 * 4) = *(float4*)ov;
        }
    } else {  // EPI == 3: plain fp32
        float* C = (float*)Cgv + (size_t)zb * sCb + (size_t)zh * sCh + (size_t)gr * ldc + gc;
#pragma unroll
        for (int j4 = 0; j4 < 16; j4++) {
            float ov[4] = {crow[j4 * 4], crow[j4 * 4 + 1], crow[j4 * 4 + 2], crow[j4 * 4 + 3]};
            *(float4*)(C + j4 * 4) = *(float4*)ov;
        }
    }
}

// ---------------------------------------------------------------------------
// masked softmax in place (sentinel > 1000 = masked); also emits bf16 hi/lo
// planes of the result for the attn@V GEMM.
// ---------------------------------------------------------------------------
__global__ void __launch_bounds__(256) softmax_k(float* __restrict__ attn,
                                                 __nv_bfloat16* __restrict__ ap)
{
    __shared__ float sh[8];
    const size_t rbase = (size_t)blockIdx.x * 1024;
    float* p = attn + rbase;
    const int t = threadIdx.x;

    float4 v4 = ((const float4*)p)[t];
    float x[4] = {v4.x, v4.y, v4.z, v4.w};
    bool msk[4];
    float mx = -1e30f;
#pragma unroll
    for (int i = 0; i < 4; i++) {
        msk[i] = (x[i] > 1000.f);
        if (msk[i]) x[i] = 0.f;
        mx = fmaxf(mx, x[i]);
    }
#pragma unroll
    for (int o = 16; o; o >>= 1) mx = fmaxf(mx, __shfl_xor_sync(0xffffffffu, mx, o));
    if ((t & 31) == 0) sh[t >> 5] = mx;
    __syncthreads();
    mx = sh[0];
#pragma unroll
    for (int i = 1; i < 8; i++) mx = fmaxf(mx, sh[i]);

    float e[4], s = 0.f;
#pragma unroll
    for (int i = 0; i < 4; i++) {
        e[i] = msk[i] ? 0.f : __expf(x[i] - mx);
        s += e[i];
    }
#pragma unroll
    for (int o = 16; o; o >>= 1) s += __shfl_xor_sync(0xffffffffu, s, o);
    __syncthreads();
    if ((t & 31) == 0) sh[t >> 5] = s;
    __syncthreads();
    s = 0.f;
#pragma unroll
    for (int i = 0; i < 8; i++) s += sh[i];

    const float inv = 1.f / (s + 1e-6f);
    float ov[4] = {e[0] * inv, e[1] * inv, e[2] * inv, e[3] * inv};
    ((float4*)p)[t] = *(float4*)ov;

    __align__(8) __nv_bfloat16 h[4], l[4];
#pragma unroll
    for (int i = 0; i < 4; i++) {
        h[i] = __float2bfloat16(ov[i]);
        l[i] = __float2bfloat16(ov[i] - __bfloat162float(h[i]));
    }
    const size_t idx = rbase + (size_t)t * 4;
    *(uint2*)(ap + idx)       = *(uint2*)h;
    *(uint2*)(ap + ATT + idx) = *(uint2*)l;
}

// ---------------------------------------------------------------------------
// split-K reduce + bias + residual + LayerNorm
// ---------------------------------------------------------------------------
__global__ void __launch_bounds__(256) fc_ln_k(
    const float* __restrict__ tmp, const float* __restrict__ fcb,
    const float* __restrict__ resid, const float* __restrict__ lg,
    const float* __restrict__ lb, float* __restrict__ out)
{
    __shared__ float shs[8], shq[8];
    const size_t o = (size_t)blockIdx.x * 256 + threadIdx.x;
    const int t = threadIdx.x;

    float v = tmp[o] + tmp[o + 1048576] + tmp[o + 2097152] + tmp[o + 3145728]
            + fcb[t] + resid[o];

    float s = v, qq = v * v;
#pragma unroll
    for (int d = 16; d; d >>= 1) {
        s  += __shfl_xor_sync(0xffffffffu, s, d);
        qq += __shfl_xor_sync(0xffffffffu, qq, d);
    }
    if ((t & 31) == 0) { shs[t >> 5] = s; shq[t >> 5] = qq; }
    __syncthreads();
    s = 0.f; qq = 0.f;
#pragma unroll
    for (int i = 0; i < 8; i++) { s += shs[i]; qq += shq[i]; }

    const float mean = s * (1.f / 256.f);
    const float var  = qq * (1.f / 256.f) - mean * mean;
    out[o] = (v - mean) * rsqrtf(var + 1e-5f) * lg[t] + lb[t];
}

// ---------------------------------------------------------------------------
extern "C" void kernel_launch(void* const* d_in, const int* in_sizes, int n_in,
                              void* d_out, int out_size)
{
    const float* q    = (const float*)d_in[0];
    const int*   mask = (const int*)  d_in[1];
    const float* k    = (const float*)d_in[2];
    const float* v    = (const float*)d_in[3];
    const float* w_qs = (const float*)d_in[4];
    const float* w_ks = (const float*)d_in[5];
    const float* w_vs = (const float*)d_in[6];
    const float* fc_w = (const float*)d_in[7];
    const float* fc_b = (const float*)d_in[8];
    const float* ln_g = (const float*)d_in[9];
    const float* ln_b = (const float*)d_in[10];

    float* out  = (float*)d_out;
    float* attn = out + (size_t)NBL * ND;

    __nv_bfloat16 *qp, *kp, *vp, *wqp, *wkp, *wvp, *fcwp, *qhp, *khp, *vht, *hop, *ap;
    float* tmp;
    cudaGetSymbolAddress((void**)&qp,   g_qp);
    cudaGetSymbolAddress((void**)&kp,   g_kp);
    cudaGetSymbolAddress((void**)&vp,   g_vp);
    cudaGetSymbolAddress((void**)&wqp,  g_wqp);
    cudaGetSymbolAddress((void**)&wkp,  g_wkp);
    cudaGetSymbolAddress((void**)&wvp,  g_wvp);
    cudaGetSymbolAddress((void**)&fcwp, g_fcwp);
    cudaGetSymbolAddress((void**)&qhp,  g_qhp);
    cudaGetSymbolAddress((void**)&khp,  g_khp);
    cudaGetSymbolAddress((void**)&vht,  g_vht);
    cudaGetSymbolAddress((void**)&hop,  g_hop);
    cudaGetSymbolAddress((void**)&ap,   g_ap);
    cudaGetSymbolAddress((void**)&tmp,  g_tmp);

    cudaFuncSetAttribute(tgemm<0>, cudaFuncAttributeMaxDynamicSharedMemorySize, SMEMB);
    cudaFuncSetAttribute(tgemm<1>, cudaFuncAttributeMaxDynamicSharedMemorySize, SMEMB);
    cudaFuncSetAttribute(tgemm<3>, cudaFuncAttributeMaxDynamicSharedMemorySize, SMEMB);

    // ---- fused conversions: launch 0 = q/k/v, launch 1 = 4 weight tensors ----
    cvt4_k<<<dim3(NBL * ND / 4 / 256, 3), 256>>>(
        q, k, v, v, qp, kp, vp, vp, NBL * ND / 4, (long)NBL * ND);
    cvt4_k<<<dim3(NHD * ND / 4 / 256, 4), 256>>>(
        w_qs, w_ks, w_vs, fc_w, wqp, wkp, wvp, fcwp, NHD * ND / 4, (long)NHD * ND);

    const long QKSZ = (long)NBL * ND;        // 1048576
    const long WSZ  = (long)NHD * ND;        // 524288
    const long BIG  = (long)NBL * NHD;       // 8388608

    // ---- Q, K projections: [4096,2048] = x @ w^T ----
    tgemm<0><<<dim3(16, 32, 1), 256, SMEMB>>>(
        qp, QKSZ, ND, wqp, WSZ, ND, qhp, NHD, BIG, ND, 1,
        0, 0, 0, 0, 0, 0, nullptr, 0);
    tgemm<0><<<dim3(16, 32, 1), 256, SMEMB>>>(
        kp, QKSZ, ND, wkp, WSZ, ND, khp, NHD, BIG, ND, 1,
        0, 0, 0, 0, 0, 0, nullptr, 0);

    // ---- V projection, transposed output: vht[hd, token] = w_vs @ v^T ----
    tgemm<0><<<dim3(32, 16, 1), 256, SMEMB>>>(
        wvp, WSZ, ND, vp, QKSZ, ND, vht, NBL, BIG, ND, 1,
        0, 0, 0, 0, 0, 0, nullptr, 0);

    // ---- scores (launch #5 — profiled): attn[(h*B+b)] = qh @ kh^T /16, clip, mask ----
    tgemm<1><<<dim3(8, 8, 32), 256, SMEMB>>>(
        qhp, BIG, NHD, khp, BIG, NHD, attn, NL, 0, ND, NB,
        (long)NL * NHD, (long)ND,
        (long)NL * NHD, (long)ND,
        (long)NL * NL, (long)NB * NL * NL,
        mask, (long)NL * NL);

    // ---- masked softmax in place + bf16 plane emission ----
    softmax_k<<<NH * NB * NL, 256>>>(attn, ap);

    // ---- attn @ V: hop[b,l, h*256+d] ----
    tgemm<0><<<dim3(2, 8, 32), 256, SMEMB>>>(
        ap, (long)ATT, NL, vht, BIG, NBL, hop, NHD, BIG, NL, NB,
        (long)NL * NL, (long)NB * NL * NL,
        (long)NL, (long)ND * NBL,
        (long)NL * NHD, (long)ND,
        nullptr, 0);

    // ---- fc: split-K = 4 -> fp32 partials ----
    tgemm<3><<<dim3(2, 32, 4), 256, SMEMB>>>(
        hop, BIG, NHD, fcwp, (long)ND * NHD, NHD, tmp, ND, 0, 512, 1,
        0, 512, 0, 512, 0, (long)NBL * ND, nullptr, 0);

    // ---- reduce + bias + residual + LayerNorm ----
    fc_ln_k<<<NBL, 256>>>(tmp, fc_b, q, ln_g, ln_b, out);
}

// round 8
// speedup vs baseline: 1.1194x; 1.0532x over previous
#include <cuda_runtime.h>
#include <cuda_bf16.h>
#include <mma.h>
#include <cstdint>

using namespace nvcuda;

#define NB 4
#define NL 1024
#define ND 256
#define NH 8
#define NHD 2048
#define NBL 4096
#define ATT ((size_t)NB * NH * NL * NL)   // 33,554,432 attn elems

#define BKK 32                 // k-tile
#define LDS_AB 40              // BK(32) + 8 pad -> 80B rows, LDSM conflict-free
#define PLE (128 * LDS_AB)     // elems per plane tile (5120)
#define PLB (PLE * 2)          // bytes per plane tile (10240)
#define STGB (4 * PLB)         // bytes per stage: Ahi|Alo|Bhi|Blo (40960)
#define LDC_S 132              // epilogue smem stride (floats)
#define SMEMB (2 * STGB)       // 81920 B (>= Cs 67584 B); 2 CTAs/SM fit

// ---------------------------------------------------------------------------
// cp.async helpers
// ---------------------------------------------------------------------------
__device__ __forceinline__ uint32_t smem_u32(const void* p) {
    uint32_t a;
    asm("{ .reg .u64 t; cvta.to.shared.u64 t, %1; cvt.u32.u64 %0, t; }" : "=r"(a) : "l"(p));
    return a;
}
#define CP_ASYNC16(dst, src) \
    asm volatile("cp.async.cg.shared.global [%0], [%1], 16;" :: "r"(dst), "l"(src) : "memory")
#define CP_COMMIT() asm volatile("cp.async.commit_group;" ::: "memory")
#define CP_WAIT0()  asm volatile("cp.async.wait_group 0;" ::: "memory")
#define CP_WAIT1()  asm volatile("cp.async.wait_group 1;" ::: "memory")

// ---------------------------------------------------------------------------
// scratch (device globals — allocations forbidden)
// ---------------------------------------------------------------------------
static __device__ __align__(16) __nv_bfloat16 g_qp[2 * NBL * ND];
static __device__ __align__(16) __nv_bfloat16 g_kp[2 * NBL * ND];
static __device__ __align__(16) __nv_bfloat16 g_vp[2 * NBL * ND];
static __device__ __align__(16) __nv_bfloat16 g_wqp[2 * NHD * ND];
static __device__ __align__(16) __nv_bfloat16 g_wkp[2 * NHD * ND];
static __device__ __align__(16) __nv_bfloat16 g_wvp[2 * NHD * ND];
static __device__ __align__(16) __nv_bfloat16 g_fcwp[2 * ND * NHD];
static __device__ __align__(16) __nv_bfloat16 g_qhp[2 * (size_t)NBL * NHD];
static __device__ __align__(16) __nv_bfloat16 g_khp[2 * (size_t)NBL * NHD];
static __device__ __align__(16) __nv_bfloat16 g_vht[2 * (size_t)NHD * NBL];
static __device__ __align__(16) __nv_bfloat16 g_hop[2 * (size_t)NBL * NHD];
static __device__ __align__(16) __nv_bfloat16 g_ap[2 * ATT];   // softmaxed attn planes
static __device__ float g_tmp[(size_t)4 * NBL * ND];

// ---------------------------------------------------------------------------
// fused fp32 -> (hi, lo) bf16 planes for up to 4 tensors (blockIdx.y selects)
// ---------------------------------------------------------------------------
__global__ void __launch_bounds__(256) cvt4_k(
    const float* __restrict__ s0, const float* __restrict__ s1,
    const float* __restrict__ s2, const float* __restrict__ s3,
    __nv_bfloat16* __restrict__ d0, __nv_bfloat16* __restrict__ d1,
    __nv_bfloat16* __restrict__ d2, __nv_bfloat16* __restrict__ d3,
    int n4, long split)
{
    const int which = blockIdx.y;
    const float* x = which == 0 ? s0 : which == 1 ? s1 : which == 2 ? s2 : s3;
    __nv_bfloat16* hi = which == 0 ? d0 : which == 1 ? d1 : which == 2 ? d2 : d3;
    int i = blockIdx.x * 256 + threadIdx.x;
    if (i >= n4) return;
    float4 v = *((const float4*)x + i);
    float f[4] = {v.x, v.y, v.z, v.w};
    __align__(8) __nv_bfloat16 h[4], l[4];
#pragma unroll
    for (int j = 0; j < 4; j++) {
        h[j] = __float2bfloat16(f[j]);
        l[j] = __float2bfloat16(f[j] - __bfloat162float(h[j]));
    }
    *(uint2*)(hi + (size_t)i * 4)         = *(uint2*)h;
    *(uint2*)(hi + split + (size_t)i * 4) = *(uint2*)l;
}

// ---------------------------------------------------------------------------
// WMMA bf16x3 GEMM, cp.async 2-stage pipeline, BK=32, 2 CTAs/SM.
//   C[128x128 tile] = A @ B^T, fp32 accumulate; A/B are bf16 hi/lo planes.
//   EPI 0: write bf16 hi/lo pairs   1: scores (scale/clip/mask -> sentinel)
//   EPI 3: plain fp32 (fc split-K partials)
// 256 threads (8 warps, 2x4 grid), warp tile 64x32.
// ---------------------------------------------------------------------------
template <int EPI>
__global__ void __launch_bounds__(256, 2) tgemm(
    const __nv_bfloat16* __restrict__ Ag, long Asplit, int lda,
    const __nv_bfloat16* __restrict__ Bg, long Bsplit, int ldb,
    void* __restrict__ Cgv, int ldc, long Csplit,
    int K, int nBdim,
    long sAb, long sAh, long sBb, long sBh, long sCb, long sCh,
    const int* __restrict__ maskg, long sMb)
{
    extern __shared__ __align__(16) char sm[];
    const uint32_t smb = smem_u32(sm);
    float* Cs = (float*)sm;   // epilogue staging (reuses pipeline smem)

    const int tid = threadIdx.x;
    const int wid = tid >> 5;
    const int wm = wid & 1;   // warp row (2 x 64)
    const int wn = wid >> 1;  // warp col (4 x 32)

    const int z = blockIdx.z, zb = z % nBdim, zh = z / nBdim;
    const __nv_bfloat16* Ap = Ag + (size_t)zb * sAb + (size_t)zh * sAh;
    const __nv_bfloat16* Bp = Bg + (size_t)zb * sBb + (size_t)zh * sBh;

    const int rowBase = blockIdx.y * 128;
    const int colBase = blockIdx.x * 128;

    wmma::fragment<wmma::accumulator, 16, 16, 16, float> acc[4][2];
#pragma unroll
    for (int i = 0; i < 4; i++)
#pragma unroll
        for (int j = 0; j < 2; j++) wmma::fill_fragment(acc[i][j], 0.f);

    // issue one stage of async loads: 4 planes x 512 16B-chunks, 256 threads
    auto ldst = [&](int t, int s) {
        const int ko = t * BKK;
        const uint32_t sb = smb + s * STGB;
#pragma unroll
        for (int i = 0; i < 2; i++) {
            const int c = tid + i * 256;          // 0..511
            const int row = c >> 2, col = (c & 3) * 8;
            const uint32_t soff = (uint32_t)(row * LDS_AB + col) * 2;
            const __nv_bfloat16* pa = Ap + (size_t)(rowBase + row) * lda + ko + col;
            CP_ASYNC16(sb + soff,           pa);
            CP_ASYNC16(sb + PLB + soff,     pa + Asplit);
            const __nv_bfloat16* pb = Bp + (size_t)(colBase + row) * ldb + ko + col;
            CP_ASYNC16(sb + 2 * PLB + soff, pb);
            CP_ASYNC16(sb + 3 * PLB + soff, pb + Bsplit);
        }
        CP_COMMIT();
    };

    auto compute = [&](int s) {
        const __nv_bfloat16* base = (const __nv_bfloat16*)(sm + s * STGB);
        const __nv_bfloat16* Ah0 = base + wm * 64 * LDS_AB;
        const __nv_bfloat16* Al0 = Ah0 + PLE;
        const __nv_bfloat16* Bh0 = base + 2 * PLE + wn * 32 * LDS_AB;
        const __nv_bfloat16* Bl0 = Bh0 + PLE;
#pragma unroll
        for (int ks = 0; ks < 2; ks++) {
            wmma::fragment<wmma::matrix_a, 16, 16, 16, __nv_bfloat16, wmma::row_major> fah[4], fal[4];
            wmma::fragment<wmma::matrix_b, 16, 16, 16, __nv_bfloat16, wmma::col_major> fbh[2], fbl[2];
#pragma unroll
            for (int i = 0; i < 4; i++) {
                wmma::load_matrix_sync(fah[i], Ah0 + i * 16 * LDS_AB + ks * 16, LDS_AB);
                wmma::load_matrix_sync(fal[i], Al0 + i * 16 * LDS_AB + ks * 16, LDS_AB);
            }
#pragma unroll
            for (int j = 0; j < 2; j++) {
                wmma::load_matrix_sync(fbh[j], Bh0 + j * 16 * LDS_AB + ks * 16, LDS_AB);
                wmma::load_matrix_sync(fbl[j], Bl0 + j * 16 * LDS_AB + ks * 16, LDS_AB);
            }
#pragma unroll
            for (int i = 0; i < 4; i++)
#pragma unroll
                for (int j = 0; j < 2; j++) {
                    wmma::mma_sync(acc[i][j], fah[i], fbh[j], acc[i][j]);
                    wmma::mma_sync(acc[i][j], fah[i], fbl[j], acc[i][j]);
                    wmma::mma_sync(acc[i][j], fal[i], fbh[j], acc[i][j]);
                }
        }
    };

    // ---- 2-stage pipelined mainloop (R4 structure) ----
    const int T = K / BKK;
    ldst(0, 0);
    ldst(1, 1);
    for (int t = 0; t < T; t++) {
        if (t == T - 1) { CP_WAIT0(); } else { CP_WAIT1(); }
        __syncthreads();
        compute(t & 1);
        __syncthreads();
        if (t + 2 < T) ldst(t + 2, t & 1);
    }

    // ---- epilogue: stage accumulators through SMEM ----
#pragma unroll
    for (int i = 0; i < 4; i++)
#pragma unroll
        for (int j = 0; j < 2; j++)
            wmma::store_matrix_sync(Cs + (size_t)(wm * 64 + i * 16) * LDC_S + wn * 32 + j * 16,
                                    acc[i][j], LDC_S, wmma::mem_row_major);
    __syncthreads();

    const int row = tid >> 1;
    const int ch  = (tid & 1) * 64;
    const float* crow = Cs + (size_t)row * LDC_S + ch;
    const int gr = rowBase + row;
    const int gc = colBase + ch;

    if (EPI == 0) {
        __nv_bfloat16* Ch = (__nv_bfloat16*)Cgv + (size_t)zb * sCb + (size_t)zh * sCh +
                            (size_t)gr * ldc + gc;
#pragma unroll
        for (int cb = 0; cb < 64; cb += 8) {
            __align__(16) __nv_bfloat16 hv[8], lv[8];
#pragma unroll
            for (int j = 0; j < 8; j++) {
                float v = crow[cb + j];
                hv[j] = __float2bfloat16(v);
                lv[j] = __float2bfloat16(v - __bfloat162float(hv[j]));
            }
            *(uint4*)(Ch + cb)          = *(uint4*)hv;
            *(uint4*)(Ch + Csplit + cb) = *(uint4*)lv;
        }
    } else if (EPI == 1) {
        float* C = (float*)Cgv + (size_t)zb * sCb + (size_t)zh * sCh + (size_t)gr * ldc + gc;
        const int* mrow = maskg + (size_t)zb * sMb + (size_t)gr * NL + gc;
#pragma unroll
        for (int j4 = 0; j4 < 16; j4++) {
            int4 m = *(const int4*)(mrow + j4 * 4);
            int mm[4] = {m.x, m.y, m.z, m.w};
            float ov[4];
#pragma unroll
            for (int j = 0; j < 4; j++) {
                float s = crow[j4 * 4 + j] * 0.0625f;   // 1/sqrt(256)
                s = fminf(15.f, fmaxf(-15.f, s));
                ov[j] = mm[j] ? s : 30000.f;
            }
            *(float4*)(C + j4 * 4) = *(float4*)ov;
        }
    } else {  // EPI == 3: plain fp32
        float* C = (float*)Cgv + (size_t)zb * sCb + (size_t)zh * sCh + (size_t)gr * ldc + gc;
#pragma unroll
        for (int j4 = 0; j4 < 16; j4++) {
            float ov[4] = {crow[j4 * 4], crow[j4 * 4 + 1], crow[j4 * 4 + 2], crow[j4 * 4 + 3]};
            *(float4*)(C + j4 * 4) = *(float4*)ov;
        }
    }
}

// ---------------------------------------------------------------------------
// masked softmax in place (sentinel > 1000 = masked); also emits bf16 hi/lo
// planes of the result for the attn@V GEMM.
// ---------------------------------------------------------------------------
__global__ void __launch_bounds__(256) softmax_k(float* __restrict__ attn,
                                                 __nv_bfloat16* __restrict__ ap)
{
    __shared__ float sh[8];
    const size_t rbase = (size_t)blockIdx.x * 1024;
    float* p = attn + rbase;
    const int t = threadIdx.x;

    float4 v4 = ((const float4*)p)[t];
    float x[4] = {v4.x, v4.y, v4.z, v4.w};
    bool msk[4];
    float mx = -1e30f;
#pragma unroll
    for (int i = 0; i < 4; i++) {
        msk[i] = (x[i] > 1000.f);
        if (msk[i]) x[i] = 0.f;
        mx = fmaxf(mx, x[i]);
    }
#pragma unroll
    for (int o = 16; o; o >>= 1) mx = fmaxf(mx, __shfl_xor_sync(0xffffffffu, mx, o));
    if ((t & 31) == 0) sh[t >> 5] = mx;
    __syncthreads();
    mx = sh[0];
#pragma unroll
    for (int i = 1; i < 8; i++) mx = fmaxf(mx, sh[i]);

    float e[4], s = 0.f;
#pragma unroll
    for (int i = 0; i < 4; i++) {
        e[i] = msk[i] ? 0.f : __expf(x[i] - mx);
        s += e[i];
    }
#pragma unroll
    for (int o = 16; o; o >>= 1) s += __shfl_xor_sync(0xffffffffu, s, o);
    __syncthreads();
    if ((t & 31) == 0) sh[t >> 5] = s;
    __syncthreads();
    s = 0.f;
#pragma unroll
    for (int i = 0; i < 8; i++) s += sh[i];

    const float inv = 1.f / (s + 1e-6f);
    float ov[4] = {e[0] * inv, e[1] * inv, e[2] * inv, e[3] * inv};
    ((float4*)p)[t] = *(float4*)ov;

    __align__(8) __nv_bfloat16 h[4], l[4];
#pragma unroll
    for (int i = 0; i < 4; i++) {
        h[i] = __float2bfloat16(ov[i]);
        l[i] = __float2bfloat16(ov[i] - __bfloat162float(h[i]));
    }
    const size_t idx = rbase + (size_t)t * 4;
    *(uint2*)(ap + idx)       = *(uint2*)h;
    *(uint2*)(ap + ATT + idx) = *(uint2*)l;
}

// ---------------------------------------------------------------------------
// split-K reduce + bias + residual + LayerNorm
// ---------------------------------------------------------------------------
__global__ void __launch_bounds__(256) fc_ln_k(
    const float* __restrict__ tmp, const float* __restrict__ fcb,
    const float* __restrict__ resid, const float* __restrict__ lg,
    const float* __restrict__ lb, float* __restrict__ out)
{
    __shared__ float shs[8], shq[8];
    const size_t o = (size_t)blockIdx.x * 256 + threadIdx.x;
    const int t = threadIdx.x;

    float v = tmp[o] + tmp[o + 1048576] + tmp[o + 2097152] + tmp[o + 3145728]
            + fcb[t] + resid[o];

    float s = v, qq = v * v;
#pragma unroll
    for (int d = 16; d; d >>= 1) {
        s  += __shfl_xor_sync(0xffffffffu, s, d);
        qq += __shfl_xor_sync(0xffffffffu, qq, d);
    }
    if ((t & 31) == 0) { shs[t >> 5] = s; shq[t >> 5] = qq; }
    __syncthreads();
    s = 0.f; qq = 0.f;
#pragma unroll
    for (int i = 0; i < 8; i++) { s += shs[i]; qq += shq[i]; }

    const float mean = s * (1.f / 256.f);
    const float var  = qq * (1.f / 256.f) - mean * mean;
    out[o] = (v - mean) * rsqrtf(var + 1e-5f) * lg[t] + lb[t];
}

// ---------------------------------------------------------------------------
extern "C" void kernel_launch(void* const* d_in, const int* in_sizes, int n_in,
                              void* d_out, int out_size)
{
    const float* q    = (const float*)d_in[0];
    const int*   mask = (const int*)  d_in[1];
    const float* k    = (const float*)d_in[2];
    const float* v    = (const float*)d_in[3];
    const float* w_qs = (const float*)d_in[4];
    const float* w_ks = (const float*)d_in[5];
    const float* w_vs = (const float*)d_in[6];
    const float* fc_w = (const float*)d_in[7];
    const float* fc_b = (const float*)d_in[8];
    const float* ln_g = (const float*)d_in[9];
    const float* ln_b = (const float*)d_in[10];

    float* out  = (float*)d_out;
    float* attn = out + (size_t)NBL * ND;

    __nv_bfloat16 *qp, *kp, *vp, *wqp, *wkp, *wvp, *fcwp, *qhp, *khp, *vht, *hop, *ap;
    float* tmp;
    cudaGetSymbolAddress((void**)&qp,   g_qp);
    cudaGetSymbolAddress((void**)&kp,   g_kp);
    cudaGetSymbolAddress((void**)&vp,   g_vp);
    cudaGetSymbolAddress((void**)&wqp,  g_wqp);
    cudaGetSymbolAddress((void**)&wkp,  g_wkp);
    cudaGetSymbolAddress((void**)&wvp,  g_wvp);
    cudaGetSymbolAddress((void**)&fcwp, g_fcwp);
    cudaGetSymbolAddress((void**)&qhp,  g_qhp);
    cudaGetSymbolAddress((void**)&khp,  g_khp);
    cudaGetSymbolAddress((void**)&vht,  g_vht);
    cudaGetSymbolAddress((void**)&hop,  g_hop);
    cudaGetSymbolAddress((void**)&ap,   g_ap);
    cudaGetSymbolAddress((void**)&tmp,  g_tmp);

    cudaFuncSetAttribute(tgemm<0>, cudaFuncAttributeMaxDynamicSharedMemorySize, SMEMB);
    cudaFuncSetAttribute(tgemm<1>, cudaFuncAttributeMaxDynamicSharedMemorySize, SMEMB);
    cudaFuncSetAttribute(tgemm<3>, cudaFuncAttributeMaxDynamicSharedMemorySize, SMEMB);

    // ---- fused conversions: launch 0 = q/k/v, launch 1 = 4 weight tensors ----
    cvt4_k<<<dim3(NBL * ND / 4 / 256, 3), 256>>>(
        q, k, v, v, qp, kp, vp, vp, NBL * ND / 4, (long)NBL * ND);
    cvt4_k<<<dim3(NHD * ND / 4 / 256, 4), 256>>>(
        w_qs, w_ks, w_vs, fc_w, wqp, wkp, wvp, fcwp, NHD * ND / 4, (long)NHD * ND);

    const long QKSZ = (long)NBL * ND;        // 1048576
    const long WSZ  = (long)NHD * ND;        // 524288
    const long BIG  = (long)NBL * NHD;       // 8388608

    // ---- Q, K projections: [4096,2048] = x @ w^T ----
    tgemm<0><<<dim3(16, 32, 1), 256, SMEMB>>>(
        qp, QKSZ, ND, wqp, WSZ, ND, qhp, NHD, BIG, ND, 1,
        0, 0, 0, 0, 0, 0, nullptr, 0);
    tgemm<0><<<dim3(16, 32, 1), 256, SMEMB>>>(
        kp, QKSZ, ND, wkp, WSZ, ND, khp, NHD, BIG, ND, 1,
        0, 0, 0, 0, 0, 0, nullptr, 0);

    // ---- V projection, transposed output: vht[hd, token] = w_vs @ v^T ----
    tgemm<0><<<dim3(32, 16, 1), 256, SMEMB>>>(
        wvp, WSZ, ND, vp, QKSZ, ND, vht, NBL, BIG, ND, 1,
        0, 0, 0, 0, 0, 0, nullptr, 0);

    // ---- scores (launch #5 — profiled): attn[(h*B+b)] = qh @ kh^T /16, clip, mask ----
    tgemm<1><<<dim3(8, 8, 32), 256, SMEMB>>>(
        qhp, BIG, NHD, khp, BIG, NHD, attn, NL, 0, ND, NB,
        (long)NL * NHD, (long)ND,
        (long)NL * NHD, (long)ND,
        (long)NL * NL, (long)NB * NL * NL,
        mask, (long)NL * NL);

    // ---- masked softmax in place + bf16 plane emission ----
    softmax_k<<<NH * NB * NL, 256>>>(attn, ap);

    // ---- attn @ V: hop[b,l, h*256+d] ----
    tgemm<0><<<dim3(2, 8, 32), 256, SMEMB>>>(
        ap, (long)ATT, NL, vht, BIG, NBL, hop, NHD, BIG, NL, NB,
        (long)NL * NL, (long)NB * NL * NL,
        (long)NL, (long)ND * NBL,
        (long)NL * NHD, (long)ND,
        nullptr, 0);

    // ---- fc: split-K = 4 -> fp32 partials ----
    tgemm<3><<<dim3(2, 32, 4), 256, SMEMB>>>(
        hop, BIG, NHD, fcwp, (long)ND * NHD, NHD, tmp, ND, 0, 512, 1,
        0, 512, 0, 512, 0, (long)NBL * ND, nullptr, 0);

    // ---- reduce + bias + residual + LayerNorm ----
    fc_ln_k<<<NBL, 256>>>(tmp, fc_b, q, ln_g, ln_b, out);
}

// round 9
// speedup vs baseline: 1.1801x; 1.0543x over previous
#include <cuda_runtime.h>
#include <cuda_fp16.h>
#include <mma.h>
#include <cstdint>

using namespace nvcuda;

#define NB 4
#define NL 1024
#define ND 256
#define NH 8
#define NHD 2048
#define NBL 4096
#define ATT ((size_t)NB * NH * NL * NL)   // 33,554,432 attn elems

#define BKK 64                 // k-tile
#define LDS_AB 72              // BK(64) + 8 pad -> 144B rows, LDSM conflict-free
#define PLE (128 * LDS_AB)     // elems per plane tile (9216)
#define PLB (PLE * 2)          // bytes per plane tile (18432)
#define STGB (4 * PLB)         // bytes per stage: Ahi|Alo|Bhi|Blo (73728)
#define LDC_S 132              // epilogue smem stride (elems)
#define CS_B  (128 * LDC_S * 4)            // fp32 staging bytes (67584)
#define SMEMB (2 * STGB)       // 147456 B (>= Cs 67584 + Hs 33792)

// ---------------------------------------------------------------------------
// cp.async helpers
// ---------------------------------------------------------------------------
__device__ __forceinline__ uint32_t smem_u32(const void* p) {
    uint32_t a;
    asm("{ .reg .u64 t; cvta.to.shared.u64 t, %1; cvt.u32.u64 %0, t; }" : "=r"(a) : "l"(p));
    return a;
}
#define CP_ASYNC16(dst, src) \
    asm volatile("cp.async.cg.shared.global [%0], [%1], 16;" :: "r"(dst), "l"(src) : "memory")
#define CP_COMMIT() asm volatile("cp.async.commit_group;" ::: "memory")
#define CP_WAIT0()  asm volatile("cp.async.wait_group 0;" ::: "memory")
#define CP_WAIT1()  asm volatile("cp.async.wait_group 1;" ::: "memory")

// ---------------------------------------------------------------------------
// scratch (device globals — allocations forbidden)
// ---------------------------------------------------------------------------
static __device__ __align__(16) __half g_qp[2 * NBL * ND];
static __device__ __align__(16) __half g_kp[2 * NBL * ND];
static __device__ __align__(16) __half g_vp[2 * NBL * ND];
static __device__ __align__(16) __half g_wqp[2 * NHD * ND];
static __device__ __align__(16) __half g_wkp[2 * NHD * ND];
static __device__ __align__(16) __half g_wvp[2 * NHD * ND];
static __device__ __align__(16) __half g_fcwp[2 * ND * NHD];
static __device__ __align__(16) __half g_qhp[2 * (size_t)NBL * NHD];
static __device__ __align__(16) __half g_khp[2 * (size_t)NBL * NHD];
static __device__ __align__(16) __half g_vht[2 * (size_t)NHD * NBL];
static __device__ __align__(16) __half g_hop[2 * (size_t)NBL * NHD];
static __device__ __align__(16) __half g_ap[2 * ATT];   // softmaxed attn planes
static __device__ float g_tmp[(size_t)4 * NBL * ND];

// ---------------------------------------------------------------------------
// fused fp32 -> (hi, lo) fp16 planes for up to 4 tensors (blockIdx.y selects)
// ---------------------------------------------------------------------------
__global__ void __launch_bounds__(256) cvt4_k(
    const float* __restrict__ s0, const float* __restrict__ s1,
    const float* __restrict__ s2, const float* __restrict__ s3,
    __half* __restrict__ d0, __half* __restrict__ d1,
    __half* __restrict__ d2, __half* __restrict__ d3,
    int n4, long split)
{
    const int which = blockIdx.y;
    const float* x = which == 0 ? s0 : which == 1 ? s1 : which == 2 ? s2 : s3;
    __half* hi = which == 0 ? d0 : which == 1 ? d1 : which == 2 ? d2 : d3;
    int i = blockIdx.x * 256 + threadIdx.x;
    if (i >= n4) return;
    float4 v = *((const float4*)x + i);
    float f[4] = {v.x, v.y, v.z, v.w};
    __align__(8) __half h[4], l[4];
#pragma unroll
    for (int j = 0; j < 4; j++) {
        h[j] = __float2half_rn(f[j]);
        l[j] = __float2half_rn(f[j] - __half2float(h[j]));
    }
    *(uint2*)(hi + (size_t)i * 4)         = *(uint2*)h;
    *(uint2*)(hi + split + (size_t)i * 4) = *(uint2*)l;
}

// ---------------------------------------------------------------------------
// WMMA fp16x3 GEMM with mixed-rate accumulation:
//   main term Ah*Bh -> fp32 accumulators (slow fp32-acc HMMA path)
//   corrections Ah*Bl, Al*Bh -> fp16 accumulators (fast fp16-acc HMMA path)
//   combined in epilogue through SMEM (layout-safe store_matrix_sync both).
//   EPI 0: write fp16 hi/lo pairs   1: scores (scale/clip/mask -> sentinel)
//   EPI 3: plain fp32 (fc split-K partials)
// 256 threads (8 warps, 2x4 grid), warp tile 64x32, BK=64, 2-stage cp.async.
// ---------------------------------------------------------------------------
template <int EPI>
__global__ void __launch_bounds__(256, 1) tgemm(
    const __half* __restrict__ Ag, long Asplit, int lda,
    const __half* __restrict__ Bg, long Bsplit, int ldb,
    void* __restrict__ Cgv, int ldc, long Csplit,
    int K, int nBdim,
    long sAb, long sAh, long sBb, long sBh, long sCb, long sCh,
    const int* __restrict__ maskg, long sMb)
{
    extern __shared__ __align__(16) char sm[];
    const uint32_t smb = smem_u32(sm);
    float*  Cs = (float*)sm;               // fp32 acc staging
    __half* Hs = (__half*)(sm + CS_B);     // fp16 correction staging

    const int tid = threadIdx.x;
    const int wid = tid >> 5;
    const int wm = wid & 1;   // warp row (2 x 64)
    const int wn = wid >> 1;  // warp col (4 x 32)

    const int z = blockIdx.z, zb = z % nBdim, zh = z / nBdim;
    const __half* Ap = Ag + (size_t)zb * sAb + (size_t)zh * sAh;
    const __half* Bp = Bg + (size_t)zb * sBb + (size_t)zh * sBh;

    const int rowBase = blockIdx.y * 128;
    const int colBase = blockIdx.x * 128;

    wmma::fragment<wmma::accumulator, 16, 16, 16, float>  acc[4][2];
    wmma::fragment<wmma::accumulator, 16, 16, 16, __half> hacc[4][2];
#pragma unroll
    for (int i = 0; i < 4; i++)
#pragma unroll
        for (int j = 0; j < 2; j++) {
            wmma::fill_fragment(acc[i][j], 0.f);
            wmma::fill_fragment(hacc[i][j], __float2half(0.f));
        }

    // issue one stage of async loads: 4 planes x 1024 16B-chunks, 256 threads
    auto ldst = [&](int t, int s) {
        const int ko = t * BKK;
        const uint32_t sb = smb + s * STGB;
#pragma unroll
        for (int i = 0; i < 4; i++) {
            const int c = tid + i * 256;          // 0..1023
            const int row = c >> 3, col = (c & 7) * 8;
            const uint32_t soff = (uint32_t)(row * LDS_AB + col) * 2;
            const __half* pa = Ap + (size_t)(rowBase + row) * lda + ko + col;
            CP_ASYNC16(sb + soff,           pa);
            CP_ASYNC16(sb + PLB + soff,     pa + Asplit);
            const __half* pb = Bp + (size_t)(colBase + row) * ldb + ko + col;
            CP_ASYNC16(sb + 2 * PLB + soff, pb);
            CP_ASYNC16(sb + 3 * PLB + soff, pb + Bsplit);
        }
        CP_COMMIT();
    };

    auto compute = [&](int s) {
        const __half* base = (const __half*)(sm + s * STGB);
        const __half* Ah0 = base + wm * 64 * LDS_AB;
        const __half* Al0 = Ah0 + PLE;
        const __half* Bh0 = base + 2 * PLE + wn * 32 * LDS_AB;
        const __half* Bl0 = Bh0 + PLE;
#pragma unroll
        for (int ks = 0; ks < 4; ks++) {
            wmma::fragment<wmma::matrix_a, 16, 16, 16, __half, wmma::row_major> fah[4], fal[4];
            wmma::fragment<wmma::matrix_b, 16, 16, 16, __half, wmma::col_major> fbh[2], fbl[2];
#pragma unroll
            for (int i = 0; i < 4; i++) {
                wmma::load_matrix_sync(fah[i], Ah0 + i * 16 * LDS_AB + ks * 16, LDS_AB);
                wmma::load_matrix_sync(fal[i], Al0 + i * 16 * LDS_AB + ks * 16, LDS_AB);
            }
#pragma unroll
            for (int j = 0; j < 2; j++) {
                wmma::load_matrix_sync(fbh[j], Bh0 + j * 16 * LDS_AB + ks * 16, LDS_AB);
                wmma::load_matrix_sync(fbl[j], Bl0 + j * 16 * LDS_AB + ks * 16, LDS_AB);
            }
#pragma unroll
            for (int i = 0; i < 4; i++)
#pragma unroll
                for (int j = 0; j < 2; j++) {
                    wmma::mma_sync(acc[i][j],  fah[i], fbh[j], acc[i][j]);   // fp32 acc
                    wmma::mma_sync(hacc[i][j], fah[i], fbl[j], hacc[i][j]);  // fp16 acc
                    wmma::mma_sync(hacc[i][j], fal[i], fbh[j], hacc[i][j]);  // fp16 acc
                }
        }
    };

    // ---- 2-stage pipelined mainloop (R4 structure — measured best) ----
    const int T = K / BKK;
    ldst(0, 0);
    ldst(1, 1);
    for (int t = 0; t < T; t++) {
        if (t == T - 1) { CP_WAIT0(); } else { CP_WAIT1(); }
        __syncthreads();
        compute(t & 1);
        __syncthreads();
        if (t + 2 < T) ldst(t + 2, t & 1);
    }

    // ---- epilogue: stage both accumulator sets through SMEM, combine ----
#pragma unroll
    for (int i = 0; i < 4; i++)
#pragma unroll
        for (int j = 0; j < 2; j++) {
            wmma::store_matrix_sync(Cs + (size_t)(wm * 64 + i * 16) * LDC_S + wn * 32 + j * 16,
                                    acc[i][j], LDC_S, wmma::mem_row_major);
            wmma::store_matrix_sync(Hs + (size_t)(wm * 64 + i * 16) * LDC_S + wn * 32 + j * 16,
                                    hacc[i][j], LDC_S, wmma::mem_row_major);
        }
    __syncthreads();

    const int row = tid >> 1;
    const int ch  = (tid & 1) * 64;
    const float*  crow = Cs + (size_t)row * LDC_S + ch;
    const __half* hrow = Hs + (size_t)row * LDC_S + ch;
    const int gr = rowBase + row;
    const int gc = colBase + ch;

    if (EPI == 0) {
        __half* Ch = (__half*)Cgv + (size_t)zb * sCb + (size_t)zh * sCh +
                     (size_t)gr * ldc + gc;
#pragma unroll
        for (int cb = 0; cb < 64; cb += 8) {
            __align__(16) __half hv[8], lv[8];
#pragma unroll
            for (int j = 0; j < 8; j++) {
                float v = crow[cb + j] + __half2float(hrow[cb + j]);
                hv[j] = __float2half_rn(v);
                lv[j] = __float2half_rn(v - __half2float(hv[j]));
            }
            *(uint4*)(Ch + cb)          = *(uint4*)hv;
            *(uint4*)(Ch + Csplit + cb) = *(uint4*)lv;
        }
    } else if (EPI == 1) {
        float* C = (float*)Cgv + (size_t)zb * sCb + (size_t)zh * sCh + (size_t)gr * ldc + gc;
        const int* mrow = maskg + (size_t)zb * sMb + (size_t)gr * NL + gc;
#pragma unroll
        for (int j4 = 0; j4 < 16; j4++) {
            int4 m = *(const int4*)(mrow + j4 * 4);
            int mm[4] = {m.x, m.y, m.z, m.w};
            float ov[4];
#pragma unroll
            for (int j = 0; j < 4; j++) {
                float s = (crow[j4 * 4 + j] + __half2float(hrow[j4 * 4 + j])) * 0.0625f;
                s = fminf(15.f, fmaxf(-15.f, s));
                ov[j] = mm[j] ? s : 30000.f;
            }
            *(float4*)(C + j4 * 4) = *(float4*)ov;
        }
    } else {  // EPI == 3: plain fp32
        float* C = (float*)Cgv + (size_t)zb * sCb + (size_t)zh * sCh + (size_t)gr * ldc + gc;
#pragma unroll
        for (int j4 = 0; j4 < 16; j4++) {
            float ov[4];
#pragma unroll
            for (int j = 0; j < 4; j++)
                ov[j] = crow[j4 * 4 + j] + __half2float(hrow[j4 * 4 + j]);
            *(float4*)(C + j4 * 4) = *(float4*)ov;
        }
    }
}

// ---------------------------------------------------------------------------
// masked softmax in place (sentinel > 1000 = masked); also emits fp16 hi/lo
// planes of the result for the attn@V GEMM.
// ---------------------------------------------------------------------------
__global__ void __launch_bounds__(256) softmax_k(float* __restrict__ attn,
                                                 __half* __restrict__ ap)
{
    __shared__ float sh[8];
    const size_t rbase = (size_t)blockIdx.x * 1024;
    float* p = attn + rbase;
    const int t = threadIdx.x;

    float4 v4 = ((const float4*)p)[t];
    float x[4] = {v4.x, v4.y, v4.z, v4.w};
    bool msk[4];
    float mx = -1e30f;
#pragma unroll
    for (int i = 0; i < 4; i++) {
        msk[i] = (x[i] > 1000.f);
        if (msk[i]) x[i] = 0.f;
        mx = fmaxf(mx, x[i]);
    }
#pragma unroll
    for (int o = 16; o; o >>= 1) mx = fmaxf(mx, __shfl_xor_sync(0xffffffffu, mx, o));
    if ((t & 31) == 0) sh[t >> 5] = mx;
    __syncthreads();
    mx = sh[0];
#pragma unroll
    for (int i = 1; i < 8; i++) mx = fmaxf(mx, sh[i]);

    float e[4], s = 0.f;
#pragma unroll
    for (int i = 0; i < 4; i++) {
        e[i] = msk[i] ? 0.f : __expf(x[i] - mx);
        s += e[i];
    }
#pragma unroll
    for (int o = 16; o; o >>= 1) s += __shfl_xor_sync(0xffffffffu, s, o);
    __syncthreads();
    if ((t & 31) == 0) sh[t >> 5] = s;
    __syncthreads();
    s = 0.f;
#pragma unroll
    for (int i = 0; i < 8; i++) s += sh[i];

    const float inv = 1.f / (s + 1e-6f);
    float ov[4] = {e[0] * inv, e[1] * inv, e[2] * inv, e[3] * inv};
    ((float4*)p)[t] = *(float4*)ov;

    __align__(8) __half h[4], l[4];
#pragma unroll
    for (int i = 0; i < 4; i++) {
        h[i] = __float2half_rn(ov[i]);
        l[i] = __float2half_rn(ov[i] - __half2float(h[i]));
    }
    const size_t idx = rbase + (size_t)t * 4;
    *(uint2*)(ap + idx)       = *(uint2*)h;
    *(uint2*)(ap + ATT + idx) = *(uint2*)l;
}

// ---------------------------------------------------------------------------
// split-K reduce + bias + residual + LayerNorm
// ---------------------------------------------------------------------------
__global__ void __launch_bounds__(256) fc_ln_k(
    const float* __restrict__ tmp, const float* __restrict__ fcb,
    const float* __restrict__ resid, const float* __restrict__ lg,
    const float* __restrict__ lb, float* __restrict__ out)
{
    __shared__ float shs[8], shq[8];
    const size_t o = (size_t)blockIdx.x * 256 + threadIdx.x;
    const int t = threadIdx.x;

    float v = tmp[o] + tmp[o + 1048576] + tmp[o + 2097152] + tmp[o + 3145728]
            + fcb[t] + resid[o];

    float s = v, qq = v * v;
#pragma unroll
    for (int d = 16; d; d >>= 1) {
        s  += __shfl_xor_sync(0xffffffffu, s, d);
        qq += __shfl_xor_sync(0xffffffffu, qq, d);
    }
    if ((t & 31) == 0) { shs[t >> 5] = s; shq[t >> 5] = qq; }
    __syncthreads();
    s = 0.f; qq = 0.f;
#pragma unroll
    for (int i = 0; i < 8; i++) { s += shs[i]; qq += shq[i]; }

    const float mean = s * (1.f / 256.f);
    const float var  = qq * (1.f / 256.f) - mean * mean;
    out[o] = (v - mean) * rsqrtf(var + 1e-5f) * lg[t] + lb[t];
}

// ---------------------------------------------------------------------------
extern "C" void kernel_launch(void* const* d_in, const int* in_sizes, int n_in,
                              void* d_out, int out_size)
{
    const float* q    = (const float*)d_in[0];
    const int*   mask = (const int*)  d_in[1];
    const float* k    = (const float*)d_in[2];
    const float* v    = (const float*)d_in[3];
    const float* w_qs = (const float*)d_in[4];
    const float* w_ks = (const float*)d_in[5];
    const float* w_vs = (const float*)d_in[6];
    const float* fc_w = (const float*)d_in[7];
    const float* fc_b = (const float*)d_in[8];
    const float* ln_g = (const float*)d_in[9];
    const float* ln_b = (const float*)d_in[10];

    float* out  = (float*)d_out;
    float* attn = out + (size_t)NBL * ND;

    __half *qp, *kp, *vp, *wqp, *wkp, *wvp, *fcwp, *qhp, *khp, *vht, *hop, *ap;
    float* tmp;
    cudaGetSymbolAddress((void**)&qp,   g_qp);
    cudaGetSymbolAddress((void**)&kp,   g_kp);
    cudaGetSymbolAddress((void**)&vp,   g_vp);
    cudaGetSymbolAddress((void**)&wqp,  g_wqp);
    cudaGetSymbolAddress((void**)&wkp,  g_wkp);
    cudaGetSymbolAddress((void**)&wvp,  g_wvp);
    cudaGetSymbolAddress((void**)&fcwp, g_fcwp);
    cudaGetSymbolAddress((void**)&qhp,  g_qhp);
    cudaGetSymbolAddress((void**)&khp,  g_khp);
    cudaGetSymbolAddress((void**)&vht,  g_vht);
    cudaGetSymbolAddress((void**)&hop,  g_hop);
    cudaGetSymbolAddress((void**)&ap,   g_ap);
    cudaGetSymbolAddress((void**)&tmp,  g_tmp);

    cudaFuncSetAttribute(tgemm<0>, cudaFuncAttributeMaxDynamicSharedMemorySize, SMEMB);
    cudaFuncSetAttribute(tgemm<1>, cudaFuncAttributeMaxDynamicSharedMemorySize, SMEMB);
    cudaFuncSetAttribute(tgemm<3>, cudaFuncAttributeMaxDynamicSharedMemorySize, SMEMB);

    // ---- fused conversions: launch 0 = q/k/v, launch 1 = 4 weight tensors ----
    cvt4_k<<<dim3(NBL * ND / 4 / 256, 3), 256>>>(
        q, k, v, v, qp, kp, vp, vp, NBL * ND / 4, (long)NBL * ND);
    cvt4_k<<<dim3(NHD * ND / 4 / 256, 4), 256>>>(
        w_qs, w_ks, w_vs, fc_w, wqp, wkp, wvp, fcwp, NHD * ND / 4, (long)NHD * ND);

    const long QKSZ = (long)NBL * ND;        // 1048576
    const long WSZ  = (long)NHD * ND;        // 524288
    const long BIG  = (long)NBL * NHD;       // 8388608

    // ---- Q, K projections: [4096,2048] = x @ w^T ----
    tgemm<0><<<dim3(16, 32, 1), 256, SMEMB>>>(
        qp, QKSZ, ND, wqp, WSZ, ND, qhp, NHD, BIG, ND, 1,
        0, 0, 0, 0, 0, 0, nullptr, 0);
    tgemm<0><<<dim3(16, 32, 1), 256, SMEMB>>>(
        kp, QKSZ, ND, wkp, WSZ, ND, khp, NHD, BIG, ND, 1,
        0, 0, 0, 0, 0, 0, nullptr, 0);

    // ---- V projection, transposed output: vht[hd, token] = w_vs @ v^T ----
    tgemm<0><<<dim3(32, 16, 1), 256, SMEMB>>>(
        wvp, WSZ, ND, vp, QKSZ, ND, vht, NBL, BIG, ND, 1,
        0, 0, 0, 0, 0, 0, nullptr, 0);

    // ---- scores (launch #5 — profiled): attn[(h*B+b)] = qh @ kh^T /16, clip, mask ----
    tgemm<1><<<dim3(8, 8, 32), 256, SMEMB>>>(
        qhp, BIG, NHD, khp, BIG, NHD, attn, NL, 0, ND, NB,
        (long)NL * NHD, (long)ND,
        (long)NL * NHD, (long)ND,
        (long)NL * NL, (long)NB * NL * NL,
        mask, (long)NL * NL);

    // ---- masked softmax in place + fp16 plane emission ----
    softmax_k<<<NH * NB * NL, 256>>>(attn, ap);

    // ---- attn @ V: hop[b,l, h*256+d] ----
    tgemm<0><<<dim3(2, 8, 32), 256, SMEMB>>>(
        ap, (long)ATT, NL, vht, BIG, NBL, hop, NHD, BIG, NL, NB,
        (long)NL * NL, (long)NB * NL * NL,
        (long)NL, (long)ND * NBL,
        (long)NL * NHD, (long)ND,
        nullptr, 0);

    // ---- fc: split-K = 4 -> fp32 partials ----
    tgemm<3><<<dim3(2, 32, 4), 256, SMEMB>>>(
        hop, BIG, NHD, fcwp, (long)ND * NHD, NHD, tmp, ND, 0, 512, 1,
        0, 512, 0, 512, 0, (long)NBL * ND, nullptr, 0);

    // ---- reduce + bias + residual + LayerNorm ----
    fc_ln_k<<<NBL, 256>>>(tmp, fc_b, q, ln_g, ln_b, out);
}

// round 10
// speedup vs baseline: 1.6229x; 1.3752x over previous
#include <cuda_runtime.h>
#include <cuda_fp16.h>
#include <mma.h>
#include <cstdint>

using namespace nvcuda;

#define NB 4
#define NL 1024
#define ND 256
#define NH 8
#define NHD 2048
#define NBL 4096
#define ATT ((size_t)NB * NH * NL * NL)   // 33,554,432 attn elems

#define BKK 64                 // k-tile
#define LDS_AB 72              // BK(64) + 8 pad -> 144B rows, LDSM conflict-free
#define PLE (128 * LDS_AB)     // elems per plane tile (9216)
#define PLB (PLE * 2)          // bytes per plane tile (18432)
#define STGB (4 * PLB)         // bytes per stage: Ahi|Alo|Bhi|Blo (73728)
#define LDC_S 132              // epilogue smem stride (elems)
#define CS_B  (128 * LDC_S * 4)            // fp32 staging bytes (67584)
#define SMEMB (2 * STGB)       // 147456 B (>= Cs 67584 + Hs 33792)

// ---------------------------------------------------------------------------
// cp.async helpers
// ---------------------------------------------------------------------------
__device__ __forceinline__ uint32_t smem_u32(const void* p) {
    uint32_t a;
    asm("{ .reg .u64 t; cvta.to.shared.u64 t, %1; cvt.u32.u64 %0, t; }" : "=r"(a) : "l"(p));
    return a;
}
#define CP_ASYNC16(dst, src) \
    asm volatile("cp.async.cg.shared.global [%0], [%1], 16;" :: "r"(dst), "l"(src) : "memory")
#define CP_COMMIT() asm volatile("cp.async.commit_group;" ::: "memory")
#define CP_WAIT0()  asm volatile("cp.async.wait_group 0;" ::: "memory")
#define CP_WAIT1()  asm volatile("cp.async.wait_group 1;" ::: "memory")

// ---------------------------------------------------------------------------
// scratch (device globals — allocations forbidden)
// ---------------------------------------------------------------------------
static __device__ __align__(16) __half g_qp[2 * NBL * ND];
static __device__ __align__(16) __half g_kp[2 * NBL * ND];
static __device__ __align__(16) __half g_vp[2 * NBL * ND];
static __device__ __align__(16) __half g_wqp[2 * NHD * ND];
static __device__ __align__(16) __half g_wkp[2 * NHD * ND];
static __device__ __align__(16) __half g_wvp[2 * NHD * ND];
static __device__ __align__(16) __half g_fcwp[2 * ND * NHD];
static __device__ __align__(16) __half g_qhp[2 * (size_t)NBL * NHD];   // hi/lo
static __device__ __align__(16) __half g_khp[2 * (size_t)NBL * NHD];   // hi/lo
static __device__ __align__(16) __half g_vht[(size_t)NHD * NBL];       // single plane
static __device__ __align__(16) __half g_hop[(size_t)NBL * NHD];       // single plane
static __device__ __align__(16) __half g_ap[ATT];                      // single plane
static __device__ float g_tmp[(size_t)4 * NBL * ND];

// ---------------------------------------------------------------------------
// fused fp32 -> (hi, lo) fp16 planes for up to 4 tensors (blockIdx.y selects)
// ---------------------------------------------------------------------------
__global__ void __launch_bounds__(256) cvt4_k(
    const float* __restrict__ s0, const float* __restrict__ s1,
    const float* __restrict__ s2, const float* __restrict__ s3,
    __half* __restrict__ d0, __half* __restrict__ d1,
    __half* __restrict__ d2, __half* __restrict__ d3,
    int n4, long split)
{
    const int which = blockIdx.y;
    const float* x = which == 0 ? s0 : which == 1 ? s1 : which == 2 ? s2 : s3;
    __half* hi = which == 0 ? d0 : which == 1 ? d1 : which == 2 ? d2 : d3;
    int i = blockIdx.x * 256 + threadIdx.x;
    if (i >= n4) return;
    float4 v = *((const float4*)x + i);
    float f[4] = {v.x, v.y, v.z, v.w};
    __align__(8) __half h[4], l[4];
#pragma unroll
    for (int j = 0; j < 4; j++) {
        h[j] = __float2half_rn(f[j]);
        l[j] = __float2half_rn(f[j] - __half2float(h[j]));
    }
    *(uint2*)(hi + (size_t)i * 4)         = *(uint2*)h;
    *(uint2*)(hi + split + (size_t)i * 4) = *(uint2*)l;
}

// ---------------------------------------------------------------------------
// WMMA fp16 GEMM, configurable compensation planes.
//   AP/BP = number of fp16 planes for A/B (1 or 2).
//   Main term Ah*Bh -> fp32 acc; correction terms -> fp16 acc (combined in epi).
//   EPI 0: fp16 hi/lo out  1: scores(scale/clip/mask->sentinel)
//   EPI 2: fp16 single out 3: plain fp32 out
// 256 threads (8 warps, 2x4), warp tile 64x32, BK=64, 2-stage cp.async.
// ---------------------------------------------------------------------------
template <int EPI, int AP, int BP>
__global__ void __launch_bounds__(256, 1) tgemm(
    const __half* __restrict__ Ag, long Asplit, int lda,
    const __half* __restrict__ Bg, long Bsplit, int ldb,
    void* __restrict__ Cgv, int ldc, long Csplit,
    int K, int nBdim,
    long sAb, long sAh, long sBb, long sBh, long sCb, long sCh,
    const int* __restrict__ maskg, long sMb)
{
    constexpr bool CORR = (AP + BP > 2);
    extern __shared__ __align__(16) char sm[];
    const uint32_t smb = smem_u32(sm);
    float*  Cs = (float*)sm;               // fp32 acc staging
    __half* Hs = (__half*)(sm + CS_B);     // fp16 correction staging

    const int tid = threadIdx.x;
    const int wid = tid >> 5;
    const int wm = wid & 1;   // warp row (2 x 64)
    const int wn = wid >> 1;  // warp col (4 x 32)

    const int z = blockIdx.z, zb = z % nBdim, zh = z / nBdim;
    const __half* Ap_ = Ag + (size_t)zb * sAb + (size_t)zh * sAh;
    const __half* Bp_ = Bg + (size_t)zb * sBb + (size_t)zh * sBh;

    const int rowBase = blockIdx.y * 128;
    const int colBase = blockIdx.x * 128;

    wmma::fragment<wmma::accumulator, 16, 16, 16, float>  acc[4][2];
    wmma::fragment<wmma::accumulator, 16, 16, 16, __half> hacc[4][2];
#pragma unroll
    for (int i = 0; i < 4; i++)
#pragma unroll
        for (int j = 0; j < 2; j++) {
            wmma::fill_fragment(acc[i][j], 0.f);
            if (CORR) wmma::fill_fragment(hacc[i][j], __float2half(0.f));
        }

    // issue one stage of async loads (only the planes in use)
    auto ldst = [&](int t, int s) {
        const int ko = t * BKK;
        const uint32_t sb = smb + s * STGB;
#pragma unroll
        for (int i = 0; i < 4; i++) {
            const int c = tid + i * 256;          // 0..1023
            const int row = c >> 3, col = (c & 7) * 8;
            const uint32_t soff = (uint32_t)(row * LDS_AB + col) * 2;
            const __half* pa = Ap_ + (size_t)(rowBase + row) * lda + ko + col;
            CP_ASYNC16(sb + soff, pa);
            if (AP == 2) CP_ASYNC16(sb + PLB + soff, pa + Asplit);
            const __half* pb = Bp_ + (size_t)(colBase + row) * ldb + ko + col;
            CP_ASYNC16(sb + 2 * PLB + soff, pb);
            if (BP == 2) CP_ASYNC16(sb + 3 * PLB + soff, pb + Bsplit);
        }
        CP_COMMIT();
    };

    auto compute = [&](int s) {
        const __half* base = (const __half*)(sm + s * STGB);
        const __half* Ah0 = base + wm * 64 * LDS_AB;
        const __half* Al0 = Ah0 + PLE;
        const __half* Bh0 = base + 2 * PLE + wn * 32 * LDS_AB;
        const __half* Bl0 = Bh0 + PLE;
#pragma unroll
        for (int ks = 0; ks < 4; ks++) {
            wmma::fragment<wmma::matrix_a, 16, 16, 16, __half, wmma::row_major> fah[4], fal[4];
            wmma::fragment<wmma::matrix_b, 16, 16, 16, __half, wmma::col_major> fbh[2], fbl[2];
#pragma unroll
            for (int i = 0; i < 4; i++) {
                wmma::load_matrix_sync(fah[i], Ah0 + i * 16 * LDS_AB + ks * 16, LDS_AB);
                if (AP == 2)
                    wmma::load_matrix_sync(fal[i], Al0 + i * 16 * LDS_AB + ks * 16, LDS_AB);
            }
#pragma unroll
            for (int j = 0; j < 2; j++) {
                wmma::load_matrix_sync(fbh[j], Bh0 + j * 16 * LDS_AB + ks * 16, LDS_AB);
                if (BP == 2)
                    wmma::load_matrix_sync(fbl[j], Bl0 + j * 16 * LDS_AB + ks * 16, LDS_AB);
            }
#pragma unroll
            for (int i = 0; i < 4; i++)
#pragma unroll
                for (int j = 0; j < 2; j++) {
                    wmma::mma_sync(acc[i][j], fah[i], fbh[j], acc[i][j]);       // fp32 acc
                    if (BP == 2)
                        wmma::mma_sync(hacc[i][j], fah[i], fbl[j], hacc[i][j]); // fp16 acc
                    if (AP == 2)
                        wmma::mma_sync(hacc[i][j], fal[i], fbh[j], hacc[i][j]); // fp16 acc
                }
        }
    };

    // ---- 2-stage pipelined mainloop (R4 structure — measured best) ----
    const int T = K / BKK;
    ldst(0, 0);
    ldst(1, 1);
    for (int t = 0; t < T; t++) {
        if (t == T - 1) { CP_WAIT0(); } else { CP_WAIT1(); }
        __syncthreads();
        compute(t & 1);
        __syncthreads();
        if (t + 2 < T) ldst(t + 2, t & 1);
    }

    // ---- epilogue: stage accumulators through SMEM, combine ----
#pragma unroll
    for (int i = 0; i < 4; i++)
#pragma unroll
        for (int j = 0; j < 2; j++) {
            wmma::store_matrix_sync(Cs + (size_t)(wm * 64 + i * 16) * LDC_S + wn * 32 + j * 16,
                                    acc[i][j], LDC_S, wmma::mem_row_major);
            if (CORR)
                wmma::store_matrix_sync(Hs + (size_t)(wm * 64 + i * 16) * LDC_S + wn * 32 + j * 16,
                                        hacc[i][j], LDC_S, wmma::mem_row_major);
        }
    __syncthreads();

    const int row = tid >> 1;
    const int ch  = (tid & 1) * 64;
    const float*  crow = Cs + (size_t)row * LDC_S + ch;
    const __half* hrow = Hs + (size_t)row * LDC_S + ch;
    const int gr = rowBase + row;
    const int gc = colBase + ch;

    auto getv = [&](int idx) -> float {
        float v = crow[idx];
        if (CORR) v += __half2float(hrow[idx]);
        return v;
    };

    if (EPI == 0) {
        __half* Ch = (__half*)Cgv + (size_t)zb * sCb + (size_t)zh * sCh +
                     (size_t)gr * ldc + gc;
#pragma unroll
        for (int cb = 0; cb < 64; cb += 8) {
            __align__(16) __half hv[8], lv[8];
#pragma unroll
            for (int j = 0; j < 8; j++) {
                float v = getv(cb + j);
                hv[j] = __float2half_rn(v);
                lv[j] = __float2half_rn(v - __half2float(hv[j]));
            }
            *(uint4*)(Ch + cb)          = *(uint4*)hv;
            *(uint4*)(Ch + Csplit + cb) = *(uint4*)lv;
        }
    } else if (EPI == 2) {
        __half* Ch = (__half*)Cgv + (size_t)zb * sCb + (size_t)zh * sCh +
                     (size_t)gr * ldc + gc;
#pragma unroll
        for (int cb = 0; cb < 64; cb += 8) {
            __align__(16) __half hv[8];
#pragma unroll
            for (int j = 0; j < 8; j++) hv[j] = __float2half_rn(getv(cb + j));
            *(uint4*)(Ch + cb) = *(uint4*)hv;
        }
    } else if (EPI == 1) {
        float* C = (float*)Cgv + (size_t)zb * sCb + (size_t)zh * sCh + (size_t)gr * ldc + gc;
        const int* mrow = maskg + (size_t)zb * sMb + (size_t)gr * NL + gc;
#pragma unroll
        for (int j4 = 0; j4 < 16; j4++) {
            int4 m = *(const int4*)(mrow + j4 * 4);
            int mm[4] = {m.x, m.y, m.z, m.w};
            float ov[4];
#pragma unroll
            for (int j = 0; j < 4; j++) {
                float s = getv(j4 * 4 + j) * 0.0625f;   // 1/sqrt(256)
                s = fminf(15.f, fmaxf(-15.f, s));
                ov[j] = mm[j] ? s : 30000.f;
            }
            *(float4*)(C + j4 * 4) = *(float4*)ov;
        }
    } else {  // EPI == 3: plain fp32
        float* C = (float*)Cgv + (size_t)zb * sCb + (size_t)zh * sCh + (size_t)gr * ldc + gc;
#pragma unroll
        for (int j4 = 0; j4 < 16; j4++) {
            float ov[4] = {getv(j4 * 4), getv(j4 * 4 + 1), getv(j4 * 4 + 2), getv(j4 * 4 + 3)};
            *(float4*)(C + j4 * 4) = *(float4*)ov;
        }
    }
}

// ---------------------------------------------------------------------------
// masked softmax in place (sentinel > 1000 = masked); emits single fp16 plane.
// ---------------------------------------------------------------------------
__global__ void __launch_bounds__(256) softmax_k(float* __restrict__ attn,
                                                 __half* __restrict__ ap)
{
    __shared__ float sh[8];
    const size_t rbase = (size_t)blockIdx.x * 1024;
    float* p = attn + rbase;
    const int t = threadIdx.x;

    float4 v4 = ((const float4*)p)[t];
    float x[4] = {v4.x, v4.y, v4.z, v4.w};
    bool msk[4];
    float mx = -1e30f;
#pragma unroll
    for (int i = 0; i < 4; i++) {
        msk[i] = (x[i] > 1000.f);
        if (msk[i]) x[i] = 0.f;
        mx = fmaxf(mx, x[i]);
    }
#pragma unroll
    for (int o = 16; o; o >>= 1) mx = fmaxf(mx, __shfl_xor_sync(0xffffffffu, mx, o));
    if ((t & 31) == 0) sh[t >> 5] = mx;
    __syncthreads();
    mx = sh[0];
#pragma unroll
    for (int i = 1; i < 8; i++) mx = fmaxf(mx, sh[i]);

    float e[4], s = 0.f;
#pragma unroll
    for (int i = 0; i < 4; i++) {
        e[i] = msk[i] ? 0.f : __expf(x[i] - mx);
        s += e[i];
    }
#pragma unroll
    for (int o = 16; o; o >>= 1) s += __shfl_xor_sync(0xffffffffu, s, o);
    __syncthreads();
    if ((t & 31) == 0) sh[t >> 5] = s;
    __syncthreads();
    s = 0.f;
#pragma unroll
    for (int i = 0; i < 8; i++) s += sh[i];

    const float inv = 1.f / (s + 1e-6f);
    float ov[4] = {e[0] * inv, e[1] * inv, e[2] * inv, e[3] * inv};
    ((float4*)p)[t] = *(float4*)ov;

    __align__(8) __half h[4];
#pragma unroll
    for (int i = 0; i < 4; i++) h[i] = __float2half_rn(ov[i]);
    *(uint2*)(ap + rbase + (size_t)t * 4) = *(uint2*)h;
}

// ---------------------------------------------------------------------------
// split-K reduce + bias + residual + LayerNorm
// ---------------------------------------------------------------------------
__global__ void __launch_bounds__(256) fc_ln_k(
    const float* __restrict__ tmp, const float* __restrict__ fcb,
    const float* __restrict__ resid, const float* __restrict__ lg,
    const float* __restrict__ lb, float* __restrict__ out)
{
    __shared__ float shs[8], shq[8];
    const size_t o = (size_t)blockIdx.x * 256 + threadIdx.x;
    const int t = threadIdx.x;

    float v = tmp[o] + tmp[o + 1048576] + tmp[o + 2097152] + tmp[o + 3145728]
            + fcb[t] + resid[o];

    float s = v, qq = v * v;
#pragma unroll
    for (int d = 16; d; d >>= 1) {
        s  += __shfl_xor_sync(0xffffffffu, s, d);
        qq += __shfl_xor_sync(0xffffffffu, qq, d);
    }
    if ((t & 31) == 0) { shs[t >> 5] = s; shq[t >> 5] = qq; }
    __syncthreads();
    s = 0.f; qq = 0.f;
#pragma unroll
    for (int i = 0; i < 8; i++) { s += shs[i]; qq += shq[i]; }

    const float mean = s * (1.f / 256.f);
    const float var  = qq * (1.f / 256.f) - mean * mean;
    out[o] = (v - mean) * rsqrtf(var + 1e-5f) * lg[t] + lb[t];
}

// ---------------------------------------------------------------------------
extern "C" void kernel_launch(void* const* d_in, const int* in_sizes, int n_in,
                              void* d_out, int out_size)
{
    const float* q    = (const float*)d_in[0];
    const int*   mask = (const int*)  d_in[1];
    const float* k    = (const float*)d_in[2];
    const float* v    = (const float*)d_in[3];
    const float* w_qs = (const float*)d_in[4];
    const float* w_ks = (const float*)d_in[5];
    const float* w_vs = (const float*)d_in[6];
    const float* fc_w = (const float*)d_in[7];
    const float* fc_b = (const float*)d_in[8];
    const float* ln_g = (const float*)d_in[9];
    const float* ln_b = (const float*)d_in[10];

    float* out  = (float*)d_out;
    float* attn = out + (size_t)NBL * ND;

    __half *qp, *kp, *vp, *wqp, *wkp, *wvp, *fcwp, *qhp, *khp, *vht, *hop, *ap;
    float* tmp;
    cudaGetSymbolAddress((void**)&qp,   g_qp);
    cudaGetSymbolAddress((void**)&kp,   g_kp);
    cudaGetSymbolAddress((void**)&vp,   g_vp);
    cudaGetSymbolAddress((void**)&wqp,  g_wqp);
    cudaGetSymbolAddress((void**)&wkp,  g_wkp);
    cudaGetSymbolAddress((void**)&wvp,  g_wvp);
    cudaGetSymbolAddress((void**)&fcwp, g_fcwp);
    cudaGetSymbolAddress((void**)&qhp,  g_qhp);
    cudaGetSymbolAddress((void**)&khp,  g_khp);
    cudaGetSymbolAddress((void**)&vht,  g_vht);
    cudaGetSymbolAddress((void**)&hop,  g_hop);
    cudaGetSymbolAddress((void**)&ap,   g_ap);
    cudaGetSymbolAddress((void**)&tmp,  g_tmp);

    cudaFuncSetAttribute(tgemm<0, 2, 2>, cudaFuncAttributeMaxDynamicSharedMemorySize, SMEMB);
    cudaFuncSetAttribute(tgemm<1, 2, 1>, cudaFuncAttributeMaxDynamicSharedMemorySize, SMEMB);
    cudaFuncSetAttribute(tgemm<2, 1, 1>, cudaFuncAttributeMaxDynamicSharedMemorySize, SMEMB);
    cudaFuncSetAttribute(tgemm<3, 1, 1>, cudaFuncAttributeMaxDynamicSharedMemorySize, SMEMB);

    // ---- fused conversions: launch 0 = q/k/v, launch 1 = 4 weight tensors ----
    cvt4_k<<<dim3(NBL * ND / 4 / 256, 3), 256>>>(
        q, k, v, v, qp, kp, vp, vp, NBL * ND / 4, (long)NBL * ND);
    cvt4_k<<<dim3(NHD * ND / 4 / 256, 4), 256>>>(
        w_qs, w_ks, w_vs, fc_w, wqp, wkp, wvp, fcwp, NHD * ND / 4, (long)NHD * ND);

    const long QKSZ = (long)NBL * ND;        // 1048576
    const long WSZ  = (long)NHD * ND;        // 524288
    const long BIG  = (long)NBL * NHD;       // 8388608

    // ---- Q, K projections (full x3): [4096,2048] = x @ w^T -> hi/lo pairs ----
    tgemm<0, 2, 2><<<dim3(16, 32, 1), 256, SMEMB>>>(
        qp, QKSZ, ND, wqp, WSZ, ND, qhp, NHD, BIG, ND, 1,
        0, 0, 0, 0, 0, 0, nullptr, 0);
    tgemm<0, 2, 2><<<dim3(16, 32, 1), 256, SMEMB>>>(
        kp, QKSZ, ND, wkp, WSZ, ND, khp, NHD, BIG, ND, 1,
        0, 0, 0, 0, 0, 0, nullptr, 0);

    // ---- V projection (1x1, single-plane out): vht[hd, token] = w_vs @ v^T ----
    tgemm<2, 1, 1><<<dim3(32, 16, 1), 256, SMEMB>>>(
        wvp, 0, ND, vp, 0, ND, vht, NBL, 0, ND, 1,
        0, 0, 0, 0, 0, 0, nullptr, 0);

    // ---- scores (2-term: qh hi/lo x kh hi): attn = qh @ kh^T /16, clip, mask ----
    tgemm<1, 2, 1><<<dim3(8, 8, 32), 256, SMEMB>>>(
        qhp, BIG, NHD, khp, 0, NHD, attn, NL, 0, ND, NB,
        (long)NL * NHD, (long)ND,
        (long)NL * NHD, (long)ND,
        (long)NL * NL, (long)NB * NL * NL,
        mask, (long)NL * NL);

    // ---- masked softmax in place + single fp16 plane ----
    softmax_k<<<NH * NB * NL, 256>>>(attn, ap);

    // ---- attn @ V (1x1): hop[b,l, h*256+d] ----
    tgemm<2, 1, 1><<<dim3(2, 8, 32), 256, SMEMB>>>(
        ap, 0, NL, vht, 0, NBL, hop, NHD, 0, NL, NB,
        (long)NL * NL, (long)NB * NL * NL,
        (long)NL, (long)ND * NBL,
        (long)NL * NHD, (long)ND,
        nullptr, 0);

    // ---- fc (1x1): split-K = 4 -> fp32 partials ----
    tgemm<3, 1, 1><<<dim3(2, 32, 4), 256, SMEMB>>>(
        hop, 0, NHD, fcwp, 0, NHD, tmp, ND, 0, 512, 1,
        0, 512, 0, 512, 0, (long)NBL * ND, nullptr, 0);

    // ---- reduce + bias + residual + LayerNorm ----
    fc_ln_k<<<NBL, 256>>>(tmp, fc_b, q, ln_g, ln_b, out);
}

// round 11
// speedup vs baseline: 1.8228x; 1.1232x over previous
#include <cuda_runtime.h>
#include <cuda_fp16.h>
#include <mma.h>
#include <cstdint>

using namespace nvcuda;

#define NB 4
#define NL 1024
#define ND 256
#define NH 8
#define NHD 2048
#define NBL 4096
#define ATT ((size_t)NB * NH * NL * NL)   // 33,554,432 attn elems

#define BKK 64                 // k-tile
#define LDS_AB 72              // BK(64) + 8 pad -> 144B rows, LDSM conflict-free
#define PLE (128 * LDS_AB)     // elems per plane tile (9216)
#define PLB (PLE * 2)          // bytes per plane tile (18432)
#define STGB (4 * PLB)         // bytes per stage: Ahi|Alo|Bhi|Blo (73728)
#define LDC_S 132              // epilogue smem stride (elems)
#define CS_B  (128 * LDC_S * 4)            // fp32 staging bytes (67584)
#define SMEMB (2 * STGB)       // 147456 B (>= Cs 67584 + Hs 33792)

// ---------------------------------------------------------------------------
// cp.async helpers
// ---------------------------------------------------------------------------
__device__ __forceinline__ uint32_t smem_u32(const void* p) {
    uint32_t a;
    asm("{ .reg .u64 t; cvta.to.shared.u64 t, %1; cvt.u32.u64 %0, t; }" : "=r"(a) : "l"(p));
    return a;
}
#define CP_ASYNC16(dst, src) \
    asm volatile("cp.async.cg.shared.global [%0], [%1], 16;" :: "r"(dst), "l"(src) : "memory")
#define CP_COMMIT() asm volatile("cp.async.commit_group;" ::: "memory")
#define CP_WAIT0()  asm volatile("cp.async.wait_group 0;" ::: "memory")
#define CP_WAIT1()  asm volatile("cp.async.wait_group 1;" ::: "memory")

// ---------------------------------------------------------------------------
// scratch (device globals — allocations forbidden)
// ---------------------------------------------------------------------------
static __device__ __align__(16) __half g_qp[2 * NBL * ND];
static __device__ __align__(16) __half g_kp[2 * NBL * ND];
static __device__ __align__(16) __half g_vp[2 * NBL * ND];
static __device__ __align__(16) __half g_wqp[2 * NHD * ND];
static __device__ __align__(16) __half g_wkp[2 * NHD * ND];
static __device__ __align__(16) __half g_wvp[2 * NHD * ND];
static __device__ __align__(16) __half g_fcwp[2 * ND * NHD];
static __device__ __align__(16) __half g_qhp[(size_t)NBL * NHD];   // hi only
static __device__ __align__(16) __half g_khp[(size_t)NBL * NHD];   // hi only
static __device__ __align__(16) __half g_vht[(size_t)NHD * NBL];   // single plane
static __device__ __align__(16) __half g_hop[(size_t)NBL * NHD];   // single plane
static __device__ __align__(16) __half g_ap[ATT];                  // single plane
static __device__ float g_tmp[(size_t)4 * NBL * ND];

// ---------------------------------------------------------------------------
// fused fp32 -> (hi, lo) fp16 planes for up to 4 tensors (blockIdx.y selects)
// ---------------------------------------------------------------------------
__global__ void __launch_bounds__(256) cvt4_k(
    const float* __restrict__ s0, const float* __restrict__ s1,
    const float* __restrict__ s2, const float* __restrict__ s3,
    __half* __restrict__ d0, __half* __restrict__ d1,
    __half* __restrict__ d2, __half* __restrict__ d3,
    int n4, long split)
{
    const int which = blockIdx.y;
    const float* x = which == 0 ? s0 : which == 1 ? s1 : which == 2 ? s2 : s3;
    __half* hi = which == 0 ? d0 : which == 1 ? d1 : which == 2 ? d2 : d3;
    int i = blockIdx.x * 256 + threadIdx.x;
    if (i >= n4) return;
    float4 v = *((const float4*)x + i);
    float f[4] = {v.x, v.y, v.z, v.w};
    __align__(8) __half h[4], l[4];
#pragma unroll
    for (int j = 0; j < 4; j++) {
        h[j] = __float2half_rn(f[j]);
        l[j] = __float2half_rn(f[j] - __half2float(h[j]));
    }
    *(uint2*)(hi + (size_t)i * 4)         = *(uint2*)h;
    *(uint2*)(hi + split + (size_t)i * 4) = *(uint2*)l;
}

// ---------------------------------------------------------------------------
// WMMA fp16 GEMM, configurable compensation planes.
//   AP/BP = number of fp16 planes for A/B (1 or 2).
//   Main term Ah*Bh -> fp32 acc; correction terms -> fp16 acc (combined in epi).
//   EPI 0: fp16 hi/lo out  1: scores(scale/clip/mask->sentinel)
//   EPI 2: fp16 single out 3: plain fp32 out
// 256 threads (8 warps, 2x4), warp tile 64x32, BK=64, 2-stage cp.async.
// ---------------------------------------------------------------------------
template <int EPI, int AP, int BP>
__global__ void __launch_bounds__(256, 1) tgemm(
    const __half* __restrict__ Ag, long Asplit, int lda,
    const __half* __restrict__ Bg, long Bsplit, int ldb,
    void* __restrict__ Cgv, int ldc, long Csplit,
    int K, int nBdim,
    long sAb, long sAh, long sBb, long sBh, long sCb, long sCh,
    const int* __restrict__ maskg, long sMb)
{
    constexpr bool CORR = (AP + BP > 2);
    extern __shared__ __align__(16) char sm[];
    const uint32_t smb = smem_u32(sm);
    float*  Cs = (float*)sm;               // fp32 acc staging
    __half* Hs = (__half*)(sm + CS_B);     // fp16 correction staging

    const int tid = threadIdx.x;
    const int wid = tid >> 5;
    const int wm = wid & 1;   // warp row (2 x 64)
    const int wn = wid >> 1;  // warp col (4 x 32)

    const int z = blockIdx.z, zb = z % nBdim, zh = z / nBdim;
    const __half* Ap_ = Ag + (size_t)zb * sAb + (size_t)zh * sAh;
    const __half* Bp_ = Bg + (size_t)zb * sBb + (size_t)zh * sBh;

    const int rowBase = blockIdx.y * 128;
    const int colBase = blockIdx.x * 128;

    wmma::fragment<wmma::accumulator, 16, 16, 16, float>  acc[4][2];
    wmma::fragment<wmma::accumulator, 16, 16, 16, __half> hacc[4][2];
#pragma unroll
    for (int i = 0; i < 4; i++)
#pragma unroll
        for (int j = 0; j < 2; j++) {
            wmma::fill_fragment(acc[i][j], 0.f);
            if (CORR) wmma::fill_fragment(hacc[i][j], __float2half(0.f));
        }

    // issue one stage of async loads (only the planes in use)
    auto ldst = [&](int t, int s) {
        const int ko = t * BKK;
        const uint32_t sb = smb + s * STGB;
#pragma unroll
        for (int i = 0; i < 4; i++) {
            const int c = tid + i * 256;          // 0..1023
            const int row = c >> 3, col = (c & 7) * 8;
            const uint32_t soff = (uint32_t)(row * LDS_AB + col) * 2;
            const __half* pa = Ap_ + (size_t)(rowBase + row) * lda + ko + col;
            CP_ASYNC16(sb + soff, pa);
            if (AP == 2) CP_ASYNC16(sb + PLB + soff, pa + Asplit);
            const __half* pb = Bp_ + (size_t)(colBase + row) * ldb + ko + col;
            CP_ASYNC16(sb + 2 * PLB + soff, pb);
            if (BP == 2) CP_ASYNC16(sb + 3 * PLB + soff, pb + Bsplit);
        }
        CP_COMMIT();
    };

    auto compute = [&](int s) {
        const __half* base = (const __half*)(sm + s * STGB);
        const __half* Ah0 = base + wm * 64 * LDS_AB;
        const __half* Al0 = Ah0 + PLE;
        const __half* Bh0 = base + 2 * PLE + wn * 32 * LDS_AB;
        const __half* Bl0 = Bh0 + PLE;
#pragma unroll
        for (int ks = 0; ks < 4; ks++) {
            wmma::fragment<wmma::matrix_a, 16, 16, 16, __half, wmma::row_major> fah[4], fal[4];
            wmma::fragment<wmma::matrix_b, 16, 16, 16, __half, wmma::col_major> fbh[2], fbl[2];
#pragma unroll
            for (int i = 0; i < 4; i++) {
                wmma::load_matrix_sync(fah[i], Ah0 + i * 16 * LDS_AB + ks * 16, LDS_AB);
                if (AP == 2)
                    wmma::load_matrix_sync(fal[i], Al0 + i * 16 * LDS_AB + ks * 16, LDS_AB);
            }
#pragma unroll
            for (int j = 0; j < 2; j++) {
                wmma::load_matrix_sync(fbh[j], Bh0 + j * 16 * LDS_AB + ks * 16, LDS_AB);
                if (BP == 2)
                    wmma::load_matrix_sync(fbl[j], Bl0 + j * 16 * LDS_AB + ks * 16, LDS_AB);
            }
#pragma unroll
            for (int i = 0; i < 4; i++)
#pragma unroll
                for (int j = 0; j < 2; j++) {
                    wmma::mma_sync(acc[i][j], fah[i], fbh[j], acc[i][j]);       // fp32 acc
                    if (BP == 2)
                        wmma::mma_sync(hacc[i][j], fah[i], fbl[j], hacc[i][j]); // fp16 acc
                    if (AP == 2)
                        wmma::mma_sync(hacc[i][j], fal[i], fbh[j], hacc[i][j]); // fp16 acc
                }
        }
    };

    // ---- 2-stage pipelined mainloop (R4 structure — measured best) ----
    const int T = K / BKK;
    ldst(0, 0);
    ldst(1, 1);
    for (int t = 0; t < T; t++) {
        if (t == T - 1) { CP_WAIT0(); } else { CP_WAIT1(); }
        __syncthreads();
        compute(t & 1);
        __syncthreads();
        if (t + 2 < T) ldst(t + 2, t & 1);
    }

    // ---- epilogue: stage accumulators through SMEM, combine ----
#pragma unroll
    for (int i = 0; i < 4; i++)
#pragma unroll
        for (int j = 0; j < 2; j++) {
            wmma::store_matrix_sync(Cs + (size_t)(wm * 64 + i * 16) * LDC_S + wn * 32 + j * 16,
                                    acc[i][j], LDC_S, wmma::mem_row_major);
            if (CORR)
                wmma::store_matrix_sync(Hs + (size_t)(wm * 64 + i * 16) * LDC_S + wn * 32 + j * 16,
                                        hacc[i][j], LDC_S, wmma::mem_row_major);
        }
    __syncthreads();

    const int row = tid >> 1;
    const int ch  = (tid & 1) * 64;
    const float*  crow = Cs + (size_t)row * LDC_S + ch;
    const __half* hrow = Hs + (size_t)row * LDC_S + ch;
    const int gr = rowBase + row;
    const int gc = colBase + ch;

    auto getv = [&](int idx) -> float {
        float v = crow[idx];
        if (CORR) v += __half2float(hrow[idx]);
        return v;
    };

    if (EPI == 0) {
        __half* Ch = (__half*)Cgv + (size_t)zb * sCb + (size_t)zh * sCh +
                     (size_t)gr * ldc + gc;
#pragma unroll
        for (int cb = 0; cb < 64; cb += 8) {
            __align__(16) __half hv[8], lv[8];
#pragma unroll
            for (int j = 0; j < 8; j++) {
                float v = getv(cb + j);
                hv[j] = __float2half_rn(v);
                lv[j] = __float2half_rn(v - __half2float(hv[j]));
            }
            *(uint4*)(Ch + cb)          = *(uint4*)hv;
            *(uint4*)(Ch + Csplit + cb) = *(uint4*)lv;
        }
    } else if (EPI == 2) {
        __half* Ch = (__half*)Cgv + (size_t)zb * sCb + (size_t)zh * sCh +
                     (size_t)gr * ldc + gc;
#pragma unroll
        for (int cb = 0; cb < 64; cb += 8) {
            __align__(16) __half hv[8];
#pragma unroll
            for (int j = 0; j < 8; j++) hv[j] = __float2half_rn(getv(cb + j));
            *(uint4*)(Ch + cb) = *(uint4*)hv;
        }
    } else if (EPI == 1) {
        float* C = (float*)Cgv + (size_t)zb * sCb + (size_t)zh * sCh + (size_t)gr * ldc + gc;
        const int* mrow = maskg + (size_t)zb * sMb + (size_t)gr * NL + gc;
#pragma unroll
        for (int j4 = 0; j4 < 16; j4++) {
            int4 m = *(const int4*)(mrow + j4 * 4);
            int mm[4] = {m.x, m.y, m.z, m.w};
            float ov[4];
#pragma unroll
            for (int j = 0; j < 4; j++) {
                float s = getv(j4 * 4 + j) * 0.0625f;   // 1/sqrt(256)
                s = fminf(15.f, fmaxf(-15.f, s));
                ov[j] = mm[j] ? s : 30000.f;
            }
            *(float4*)(C + j4 * 4) = *(float4*)ov;
        }
    } else {  // EPI == 3: plain fp32
        float* C = (float*)Cgv + (size_t)zb * sCb + (size_t)zh * sCh + (size_t)gr * ldc + gc;
#pragma unroll
        for (int j4 = 0; j4 < 16; j4++) {
            float ov[4] = {getv(j4 * 4), getv(j4 * 4 + 1), getv(j4 * 4 + 2), getv(j4 * 4 + 3)};
            *(float4*)(C + j4 * 4) = *(float4*)ov;
        }
    }
}

// ---------------------------------------------------------------------------
// masked softmax in place (sentinel > 1000 = masked); emits single fp16 plane.
// ---------------------------------------------------------------------------
__global__ void __launch_bounds__(256) softmax_k(float* __restrict__ attn,
                                                 __half* __restrict__ ap)
{
    __shared__ float sh[8];
    const size_t rbase = (size_t)blockIdx.x * 1024;
    float* p = attn + rbase;
    const int t = threadIdx.x;

    float4 v4 = ((const float4*)p)[t];
    float x[4] = {v4.x, v4.y, v4.z, v4.w};
    bool msk[4];
    float mx = -1e30f;
#pragma unroll
    for (int i = 0; i < 4; i++) {
        msk[i] = (x[i] > 1000.f);
        if (msk[i]) x[i] = 0.f;
        mx = fmaxf(mx, x[i]);
    }
#pragma unroll
    for (int o = 16; o; o >>= 1) mx = fmaxf(mx, __shfl_xor_sync(0xffffffffu, mx, o));
    if ((t & 31) == 0) sh[t >> 5] = mx;
    __syncthreads();
    mx = sh[0];
#pragma unroll
    for (int i = 1; i < 8; i++) mx = fmaxf(mx, sh[i]);

    float e[4], s = 0.f;
#pragma unroll
    for (int i = 0; i < 4; i++) {
        e[i] = msk[i] ? 0.f : __expf(x[i] - mx);
        s += e[i];
    }
#pragma unroll
    for (int o = 16; o; o >>= 1) s += __shfl_xor_sync(0xffffffffu, s, o);
    __syncthreads();
    if ((t & 31) == 0) sh[t >> 5] = s;
    __syncthreads();
    s = 0.f;
#pragma unroll
    for (int i = 0; i < 8; i++) s += sh[i];

    const float inv = 1.f / (s + 1e-6f);
    float ov[4] = {e[0] * inv, e[1] * inv, e[2] * inv, e[3] * inv};
    ((float4*)p)[t] = *(float4*)ov;

    __align__(8) __half h[4];
#pragma unroll
    for (int i = 0; i < 4; i++) h[i] = __float2half_rn(ov[i]);
    *(uint2*)(ap + rbase + (size_t)t * 4) = *(uint2*)h;
}

// ---------------------------------------------------------------------------
// split-K reduce + bias + residual + LayerNorm
// ---------------------------------------------------------------------------
__global__ void __launch_bounds__(256) fc_ln_k(
    const float* __restrict__ tmp, const float* __restrict__ fcb,
    const float* __restrict__ resid, const float* __restrict__ lg,
    const float* __restrict__ lb, float* __restrict__ out)
{
    __shared__ float shs[8], shq[8];
    const size_t o = (size_t)blockIdx.x * 256 + threadIdx.x;
    const int t = threadIdx.x;

    float v = tmp[o] + tmp[o + 1048576] + tmp[o + 2097152] + tmp[o + 3145728]
            + fcb[t] + resid[o];

    float s = v, qq = v * v;
#pragma unroll
    for (int d = 16; d; d >>= 1) {
        s  += __shfl_xor_sync(0xffffffffu, s, d);
        qq += __shfl_xor_sync(0xffffffffu, qq, d);
    }
    if ((t & 31) == 0) { shs[t >> 5] = s; shq[t >> 5] = qq; }
    __syncthreads();
    s = 0.f; qq = 0.f;
#pragma unroll
    for (int i = 0; i < 8; i++) { s += shs[i]; qq += shq[i]; }

    const float mean = s * (1.f / 256.f);
    const float var  = qq * (1.f / 256.f) - mean * mean;
    out[o] = (v - mean) * rsqrtf(var + 1e-5f) * lg[t] + lb[t];
}

// ---------------------------------------------------------------------------
extern "C" void kernel_launch(void* const* d_in, const int* in_sizes, int n_in,
                              void* d_out, int out_size)
{
    const float* q    = (const float*)d_in[0];
    const int*   mask = (const int*)  d_in[1];
    const float* k    = (const float*)d_in[2];
    const float* v    = (const float*)d_in[3];
    const float* w_qs = (const float*)d_in[4];
    const float* w_ks = (const float*)d_in[5];
    const float* w_vs = (const float*)d_in[6];
    const float* fc_w = (const float*)d_in[7];
    const float* fc_b = (const float*)d_in[8];
    const float* ln_g = (const float*)d_in[9];
    const float* ln_b = (const float*)d_in[10];

    float* out  = (float*)d_out;
    float* attn = out + (size_t)NBL * ND;

    __half *qp, *kp, *vp, *wqp, *wkp, *wvp, *fcwp, *qhp, *khp, *vht, *hop, *ap;
    float* tmp;
    cudaGetSymbolAddress((void**)&qp,   g_qp);
    cudaGetSymbolAddress((void**)&kp,   g_kp);
    cudaGetSymbolAddress((void**)&vp,   g_vp);
    cudaGetSymbolAddress((void**)&wqp,  g_wqp);
    cudaGetSymbolAddress((void**)&wkp,  g_wkp);
    cudaGetSymbolAddress((void**)&wvp,  g_wvp);
    cudaGetSymbolAddress((void**)&fcwp, g_fcwp);
    cudaGetSymbolAddress((void**)&qhp,  g_qhp);
    cudaGetSymbolAddress((void**)&khp,  g_khp);
    cudaGetSymbolAddress((void**)&vht,  g_vht);
    cudaGetSymbolAddress((void**)&hop,  g_hop);
    cudaGetSymbolAddress((void**)&ap,   g_ap);
    cudaGetSymbolAddress((void**)&tmp,  g_tmp);

    cudaFuncSetAttribute(tgemm<2, 2, 2>, cudaFuncAttributeMaxDynamicSharedMemorySize, SMEMB);
    cudaFuncSetAttribute(tgemm<1, 1, 1>, cudaFuncAttributeMaxDynamicSharedMemorySize, SMEMB);
    cudaFuncSetAttribute(tgemm<2, 1, 1>, cudaFuncAttributeMaxDynamicSharedMemorySize, SMEMB);
    cudaFuncSetAttribute(tgemm<3, 1, 1>, cudaFuncAttributeMaxDynamicSharedMemorySize, SMEMB);

    // ---- fused conversions: launch 0 = q/k/v, launch 1 = 4 weight tensors ----
    cvt4_k<<<dim3(NBL * ND / 4 / 256, 3), 256>>>(
        q, k, v, v, qp, kp, vp, vp, NBL * ND / 4, (long)NBL * ND);
    cvt4_k<<<dim3(NHD * ND / 4 / 256, 4), 256>>>(
        w_qs, w_ks, w_vs, fc_w, wqp, wkp, wvp, fcwp, NHD * ND / 4, (long)NHD * ND);

    const long QKSZ = (long)NBL * ND;        // 1048576
    const long WSZ  = (long)NHD * ND;        // 524288
    const long BIG  = (long)NBL * NHD;       // 8388608

    // ---- Q, K projections (full x3 precision, single-plane fp16 out) ----
    tgemm<2, 2, 2><<<dim3(16, 32, 1), 256, SMEMB>>>(
        qp, QKSZ, ND, wqp, WSZ, ND, qhp, NHD, 0, ND, 1,
        0, 0, 0, 0, 0, 0, nullptr, 0);
    tgemm<2, 2, 2><<<dim3(16, 32, 1), 256, SMEMB>>>(
        kp, QKSZ, ND, wkp, WSZ, ND, khp, NHD, 0, ND, 1,
        0, 0, 0, 0, 0, 0, nullptr, 0);

    // ---- V projection (1x1, single-plane out): vht[hd, token] = w_vs @ v^T ----
    tgemm<2, 1, 1><<<dim3(32, 16, 1), 256, SMEMB>>>(
        wvp, 0, ND, vp, 0, ND, vht, NBL, 0, ND, 1,
        0, 0, 0, 0, 0, 0, nullptr, 0);

    // ---- scores (1x1, launch #6 — profiled): attn = qh @ kh^T /16, clip, mask ----
    tgemm<1, 1, 1><<<dim3(8, 8, 32), 256, SMEMB>>>(
        qhp, 0, NHD, khp, 0, NHD, attn, NL, 0, ND, NB,
        (long)NL * NHD, (long)ND,
        (long)NL * NHD, (long)ND,
        (long)NL * NL, (long)NB * NL * NL,
        mask, (long)NL * NL);

    // ---- masked softmax in place + single fp16 plane ----
    softmax_k<<<NH * NB * NL, 256>>>(attn, ap);

    // ---- attn @ V (1x1): hop[b,l, h*256+d] ----
    tgemm<2, 1, 1><<<dim3(2, 8, 32), 256, SMEMB>>>(
        ap, 0, NL, vht, 0, NBL, hop, NHD, 0, NL, NB,
        (long)NL * NL, (long)NB * NL * NL,
        (long)NL, (long)ND * NBL,
        (long)NL * NHD, (long)ND,
        nullptr, 0);

    // ---- fc (1x1): split-K = 4 -> fp32 partials ----
    tgemm<3, 1, 1><<<dim3(2, 32, 4), 256, SMEMB>>>(
        hop, 0, NHD, fcwp, 0, NHD, tmp, ND, 0, 512, 1,
        0, 512, 0, 512, 0, (long)NBL * ND, nullptr, 0);

    // ---- reduce + bias + residual + LayerNorm ----
    fc_ln_k<<<NBL, 256>>>(tmp, fc_b, q, ln_g, ln_b, out);
}

// round 12
// speedup vs baseline: 1.9536x; 1.0718x over previous
#include <cuda_runtime.h>
#include <cuda_fp16.h>
#include <mma.h>
#include <cstdint>

using namespace nvcuda;

#define NB 4
#define NL 1024
#define ND 256
#define NH 8
#define NHD 2048
#define NBL 4096
#define ATT ((size_t)NB * NH * NL * NL)   // 33,554,432 attn elems

#define BKK 64                 // k-tile
#define LDS_AB 72              // BK(64) + 8 pad -> 144B rows, LDSM conflict-free
#define PLE (128 * LDS_AB)     // elems per plane tile (9216)
#define PLB (PLE * 2)          // bytes per plane tile (18432)
#define STGB (4 * PLB)         // bytes per stage: Ahi|Alo|Bhi|Blo (73728)
#define LDC_S 132              // epilogue smem stride (elems)
#define CS_B  (128 * LDC_S * 4)            // fp32 staging bytes (67584)
#define SMEMB (2 * STGB)       // 147456 B (>= Cs 67584 + Hs 33792)

// ---------------------------------------------------------------------------
// cp.async helpers
// ---------------------------------------------------------------------------
__device__ __forceinline__ uint32_t smem_u32(const void* p) {
    uint32_t a;
    asm("{ .reg .u64 t; cvta.to.shared.u64 t, %1; cvt.u32.u64 %0, t; }" : "=r"(a) : "l"(p));
    return a;
}
#define CP_ASYNC16(dst, src) \
    asm volatile("cp.async.cg.shared.global [%0], [%1], 16;" :: "r"(dst), "l"(src) : "memory")
#define CP_COMMIT() asm volatile("cp.async.commit_group;" ::: "memory")
#define CP_WAIT0()  asm volatile("cp.async.wait_group 0;" ::: "memory")
#define CP_WAIT1()  asm volatile("cp.async.wait_group 1;" ::: "memory")

// ---------------------------------------------------------------------------
// scratch (device globals — allocations forbidden)
// q/k fused buffers: [q_hi | q_lo | k_hi | k_lo], ditto weights, outputs [qh|kh]
// ---------------------------------------------------------------------------
static __device__ __align__(16) __half g_qkp[4 * NBL * ND];
static __device__ __align__(16) __half g_vp[2 * NBL * ND];
static __device__ __align__(16) __half g_wqkp[4 * NHD * ND];
static __device__ __align__(16) __half g_wvp[2 * NHD * ND];
static __device__ __align__(16) __half g_fcwp[2 * ND * NHD];
static __device__ __align__(16) __half g_qkhp[2 * (size_t)NBL * NHD];  // [qh | kh]
static __device__ __align__(16) __half g_vht[(size_t)NHD * NBL];       // single plane
static __device__ __align__(16) __half g_hop[(size_t)NBL * NHD];       // single plane
static __device__ __align__(16) __half g_ap[ATT];                      // single plane
static __device__ float g_tmp[(size_t)4 * NBL * ND];

// ---------------------------------------------------------------------------
// fused fp32 -> (hi, lo) fp16 planes for up to 4 tensors (blockIdx.y selects)
// ---------------------------------------------------------------------------
__global__ void __launch_bounds__(256) cvt4_k(
    const float* __restrict__ s0, const float* __restrict__ s1,
    const float* __restrict__ s2, const float* __restrict__ s3,
    __half* __restrict__ d0, __half* __restrict__ d1,
    __half* __restrict__ d2, __half* __restrict__ d3,
    int n4, long split)
{
    const int which = blockIdx.y;
    const float* x = which == 0 ? s0 : which == 1 ? s1 : which == 2 ? s2 : s3;
    __half* hi = which == 0 ? d0 : which == 1 ? d1 : which == 2 ? d2 : d3;
    int i = blockIdx.x * 256 + threadIdx.x;
    if (i >= n4) return;
    float4 v = *((const float4*)x + i);
    float f[4] = {v.x, v.y, v.z, v.w};
    __align__(8) __half h[4], l[4];
#pragma unroll
    for (int j = 0; j < 4; j++) {
        h[j] = __float2half_rn(f[j]);
        l[j] = __float2half_rn(f[j] - __half2float(h[j]));
    }
    *(uint2*)(hi + (size_t)i * 4)         = *(uint2*)h;
    *(uint2*)(hi + split + (size_t)i * 4) = *(uint2*)l;
}

// ---------------------------------------------------------------------------
// WMMA fp16 GEMM, configurable compensation planes.
//   AP/BP = number of fp16 planes for A/B (1 or 2).
//   Main term Ah*Bh -> fp32 acc; correction terms -> fp16 acc (combined in epi).
//   EPI 0: fp16 hi/lo out  1: scores(scale/clip/mask->sentinel)
//   EPI 2: fp16 single out 3: plain fp32 out
// 256 threads (8 warps, 2x4), warp tile 64x32, BK=64, 2-stage cp.async.
// ---------------------------------------------------------------------------
template <int EPI, int AP, int BP>
__global__ void __launch_bounds__(256, 1) tgemm(
    const __half* __restrict__ Ag, long Asplit, int lda,
    const __half* __restrict__ Bg, long Bsplit, int ldb,
    void* __restrict__ Cgv, int ldc, long Csplit,
    int K, int nBdim,
    long sAb, long sAh, long sBb, long sBh, long sCb, long sCh,
    const int* __restrict__ maskg, long sMb)
{
    constexpr bool CORR = (AP + BP > 2);
    extern __shared__ __align__(16) char sm[];
    const uint32_t smb = smem_u32(sm);
    float*  Cs = (float*)sm;               // fp32 acc staging
    __half* Hs = (__half*)(sm + CS_B);     // fp16 correction staging

    const int tid = threadIdx.x;
    const int wid = tid >> 5;
    const int wm = wid & 1;   // warp row (2 x 64)
    const int wn = wid >> 1;  // warp col (4 x 32)

    const int z = blockIdx.z, zb = z % nBdim, zh = z / nBdim;
    const __half* Ap_ = Ag + (size_t)zb * sAb + (size_t)zh * sAh;
    const __half* Bp_ = Bg + (size_t)zb * sBb + (size_t)zh * sBh;

    const int rowBase = blockIdx.y * 128;
    const int colBase = blockIdx.x * 128;

    wmma::fragment<wmma::accumulator, 16, 16, 16, float>  acc[4][2];
    wmma::fragment<wmma::accumulator, 16, 16, 16, __half> hacc[4][2];
#pragma unroll
    for (int i = 0; i < 4; i++)
#pragma unroll
        for (int j = 0; j < 2; j++) {
            wmma::fill_fragment(acc[i][j], 0.f);
            if (CORR) wmma::fill_fragment(hacc[i][j], __float2half(0.f));
        }

    // issue one stage of async loads (only the planes in use)
    auto ldst = [&](int t, int s) {
        const int ko = t * BKK;
        const uint32_t sb = smb + s * STGB;
#pragma unroll
        for (int i = 0; i < 4; i++) {
            const int c = tid + i * 256;          // 0..1023
            const int row = c >> 3, col = (c & 7) * 8;
            const uint32_t soff = (uint32_t)(row * LDS_AB + col) * 2;
            const __half* pa = Ap_ + (size_t)(rowBase + row) * lda + ko + col;
            CP_ASYNC16(sb + soff, pa);
            if (AP == 2) CP_ASYNC16(sb + PLB + soff, pa + Asplit);
            const __half* pb = Bp_ + (size_t)(colBase + row) * ldb + ko + col;
            CP_ASYNC16(sb + 2 * PLB + soff, pb);
            if (BP == 2) CP_ASYNC16(sb + 3 * PLB + soff, pb + Bsplit);
        }
        CP_COMMIT();
    };

    auto compute = [&](int s) {
        const __half* base = (const __half*)(sm + s * STGB);
        const __half* Ah0 = base + wm * 64 * LDS_AB;
        const __half* Al0 = Ah0 + PLE;
        const __half* Bh0 = base + 2 * PLE + wn * 32 * LDS_AB;
        const __half* Bl0 = Bh0 + PLE;
#pragma unroll
        for (int ks = 0; ks < 4; ks++) {
            wmma::fragment<wmma::matrix_a, 16, 16, 16, __half, wmma::row_major> fah[4], fal[4];
            wmma::fragment<wmma::matrix_b, 16, 16, 16, __half, wmma::col_major> fbh[2], fbl[2];
#pragma unroll
            for (int i = 0; i < 4; i++) {
                wmma::load_matrix_sync(fah[i], Ah0 + i * 16 * LDS_AB + ks * 16, LDS_AB);
                if (AP == 2)
                    wmma::load_matrix_sync(fal[i], Al0 + i * 16 * LDS_AB + ks * 16, LDS_AB);
            }
#pragma unroll
            for (int j = 0; j < 2; j++) {
                wmma::load_matrix_sync(fbh[j], Bh0 + j * 16 * LDS_AB + ks * 16, LDS_AB);
                if (BP == 2)
                    wmma::load_matrix_sync(fbl[j], Bl0 + j * 16 * LDS_AB + ks * 16, LDS_AB);
            }
#pragma unroll
            for (int i = 0; i < 4; i++)
#pragma unroll
                for (int j = 0; j < 2; j++) {
                    wmma::mma_sync(acc[i][j], fah[i], fbh[j], acc[i][j]);       // fp32 acc
                    if (BP == 2)
                        wmma::mma_sync(hacc[i][j], fah[i], fbl[j], hacc[i][j]); // fp16 acc
                    if (AP == 2)
                        wmma::mma_sync(hacc[i][j], fal[i], fbh[j], hacc[i][j]); // fp16 acc
                }
        }
    };

    // ---- 2-stage pipelined mainloop (R4 structure — measured best) ----
    const int T = K / BKK;
    ldst(0, 0);
    ldst(1, 1);
    for (int t = 0; t < T; t++) {
        if (t == T - 1) { CP_WAIT0(); } else { CP_WAIT1(); }
        __syncthreads();
        compute(t & 1);
        __syncthreads();
        if (t + 2 < T) ldst(t + 2, t & 1);
    }

    // ---- epilogue: stage accumulators through SMEM, combine ----
#pragma unroll
    for (int i = 0; i < 4; i++)
#pragma unroll
        for (int j = 0; j < 2; j++) {
            wmma::store_matrix_sync(Cs + (size_t)(wm * 64 + i * 16) * LDC_S + wn * 32 + j * 16,
                                    acc[i][j], LDC_S, wmma::mem_row_major);
            if (CORR)
                wmma::store_matrix_sync(Hs + (size_t)(wm * 64 + i * 16) * LDC_S + wn * 32 + j * 16,
                                        hacc[i][j], LDC_S, wmma::mem_row_major);
        }
    __syncthreads();

    const int row = tid >> 1;
    const int ch  = (tid & 1) * 64;
    const float*  crow = Cs + (size_t)row * LDC_S + ch;
    const __half* hrow = Hs + (size_t)row * LDC_S + ch;
    const int gr = rowBase + row;
    const int gc = colBase + ch;

    auto getv = [&](int idx) -> float {
        float v = crow[idx];
        if (CORR) v += __half2float(hrow[idx]);
        return v;
    };

    if (EPI == 0) {
        __half* Ch = (__half*)Cgv + (size_t)zb * sCb + (size_t)zh * sCh +
                     (size_t)gr * ldc + gc;
#pragma unroll
        for (int cb = 0; cb < 64; cb += 8) {
            __align__(16) __half hv[8], lv[8];
#pragma unroll
            for (int j = 0; j < 8; j++) {
                float v = getv(cb + j);
                hv[j] = __float2half_rn(v);
                lv[j] = __float2half_rn(v - __half2float(hv[j]));
            }
            *(uint4*)(Ch + cb)          = *(uint4*)hv;
            *(uint4*)(Ch + Csplit + cb) = *(uint4*)lv;
        }
    } else if (EPI == 2) {
        __half* Ch = (__half*)Cgv + (size_t)zb * sCb + (size_t)zh * sCh +
                     (size_t)gr * ldc + gc;
#pragma unroll
        for (int cb = 0; cb < 64; cb += 8) {
            __align__(16) __half hv[8];
#pragma unroll
            for (int j = 0; j < 8; j++) hv[j] = __float2half_rn(getv(cb + j));
            *(uint4*)(Ch + cb) = *(uint4*)hv;
        }
    } else if (EPI == 1) {
        float* C = (float*)Cgv + (size_t)zb * sCb + (size_t)zh * sCh + (size_t)gr * ldc + gc;
        const int* mrow = maskg + (size_t)zb * sMb + (size_t)gr * NL + gc;
#pragma unroll
        for (int j4 = 0; j4 < 16; j4++) {
            int4 m = *(const int4*)(mrow + j4 * 4);
            int mm[4] = {m.x, m.y, m.z, m.w};
            float ov[4];
#pragma unroll
            for (int j = 0; j < 4; j++) {
                float s = getv(j4 * 4 + j) * 0.0625f;   // 1/sqrt(256)
                s = fminf(15.f, fmaxf(-15.f, s));
                ov[j] = mm[j] ? s : 30000.f;
            }
            *(float4*)(C + j4 * 4) = *(float4*)ov;
        }
    } else {  // EPI == 3: plain fp32
        float* C = (float*)Cgv + (size_t)zb * sCb + (size_t)zh * sCh + (size_t)gr * ldc + gc;
#pragma unroll
        for (int j4 = 0; j4 < 16; j4++) {
            float ov[4] = {getv(j4 * 4), getv(j4 * 4 + 1), getv(j4 * 4 + 2), getv(j4 * 4 + 3)};
            *(float4*)(C + j4 * 4) = *(float4*)ov;
        }
    }
}

// ---------------------------------------------------------------------------
// masked softmax in place (sentinel > 1000 = masked); emits single fp16 plane.
// ---------------------------------------------------------------------------
__global__ void __launch_bounds__(256) softmax_k(float* __restrict__ attn,
                                                 __half* __restrict__ ap)
{
    __shared__ float sh[8];
    const size_t rbase = (size_t)blockIdx.x * 1024;
    float* p = attn + rbase;
    const int t = threadIdx.x;

    float4 v4 = ((const float4*)p)[t];
    float x[4] = {v4.x, v4.y, v4.z, v4.w};
    bool msk[4];
    float mx = -1e30f;
#pragma unroll
    for (int i = 0; i < 4; i++) {
        msk[i] = (x[i] > 1000.f);
        if (msk[i]) x[i] = 0.f;
        mx = fmaxf(mx, x[i]);
    }
#pragma unroll
    for (int o = 16; o; o >>= 1) mx = fmaxf(mx, __shfl_xor_sync(0xffffffffu, mx, o));
    if ((t & 31) == 0) sh[t >> 5] = mx;
    __syncthreads();
    mx = sh[0];
#pragma unroll
    for (int i = 1; i < 8; i++) mx = fmaxf(mx, sh[i]);

    float e[4], s = 0.f;
#pragma unroll
    for (int i = 0; i < 4; i++) {
        e[i] = msk[i] ? 0.f : __expf(x[i] - mx);
        s += e[i];
    }
#pragma unroll
    for (int o = 16; o; o >>= 1) s += __shfl_xor_sync(0xffffffffu, s, o);
    __syncthreads();
    if ((t & 31) == 0) sh[t >> 5] = s;
    __syncthreads();
    s = 0.f;
#pragma unroll
    for (int i = 0; i < 8; i++) s += sh[i];

    const float inv = 1.f / (s + 1e-6f);
    float ov[4] = {e[0] * inv, e[1] * inv, e[2] * inv, e[3] * inv};
    ((float4*)p)[t] = *(float4*)ov;

    __align__(8) __half h[4];
#pragma unroll
    for (int i = 0; i < 4; i++) h[i] = __float2half_rn(ov[i]);
    *(uint2*)(ap + rbase + (size_t)t * 4) = *(uint2*)h;
}

// ---------------------------------------------------------------------------
// split-K reduce + bias + residual + LayerNorm
// ---------------------------------------------------------------------------
__global__ void __launch_bounds__(256) fc_ln_k(
    const float* __restrict__ tmp, const float* __restrict__ fcb,
    const float* __restrict__ resid, const float* __restrict__ lg,
    const float* __restrict__ lb, float* __restrict__ out)
{
    __shared__ float shs[8], shq[8];
    const size_t o = (size_t)blockIdx.x * 256 + threadIdx.x;
    const int t = threadIdx.x;

    float v = tmp[o] + tmp[o + 1048576] + tmp[o + 2097152] + tmp[o + 3145728]
            + fcb[t] + resid[o];

    float s = v, qq = v * v;
#pragma unroll
    for (int d = 16; d; d >>= 1) {
        s  += __shfl_xor_sync(0xffffffffu, s, d);
        qq += __shfl_xor_sync(0xffffffffu, qq, d);
    }
    if ((t & 31) == 0) { shs[t >> 5] = s; shq[t >> 5] = qq; }
    __syncthreads();
    s = 0.f; qq = 0.f;
#pragma unroll
    for (int i = 0; i < 8; i++) { s += shs[i]; qq += shq[i]; }

    const float mean = s * (1.f / 256.f);
    const float var  = qq * (1.f / 256.f) - mean * mean;
    out[o] = (v - mean) * rsqrtf(var + 1e-5f) * lg[t] + lb[t];
}

// ---------------------------------------------------------------------------
extern "C" void kernel_launch(void* const* d_in, const int* in_sizes, int n_in,
                              void* d_out, int out_size)
{
    const float* q    = (const float*)d_in[0];
    const int*   mask = (const int*)  d_in[1];
    const float* k    = (const float*)d_in[2];
    const float* v    = (const float*)d_in[3];
    const float* w_qs = (const float*)d_in[4];
    const float* w_ks = (const float*)d_in[5];
    const float* w_vs = (const float*)d_in[6];
    const float* fc_w = (const float*)d_in[7];
    const float* fc_b = (const float*)d_in[8];
    const float* ln_g = (const float*)d_in[9];
    const float* ln_b = (const float*)d_in[10];

    float* out  = (float*)d_out;
    float* attn = out + (size_t)NBL * ND;

    __half *qkp, *vp, *wqkp, *wvp, *fcwp, *qkhp, *vht, *hop, *ap;
    float* tmp;
    cudaGetSymbolAddress((void**)&qkp,  g_qkp);
    cudaGetSymbolAddress((void**)&vp,   g_vp);
    cudaGetSymbolAddress((void**)&wqkp, g_wqkp);
    cudaGetSymbolAddress((void**)&wvp,  g_wvp);
    cudaGetSymbolAddress((void**)&fcwp, g_fcwp);
    cudaGetSymbolAddress((void**)&qkhp, g_qkhp);
    cudaGetSymbolAddress((void**)&vht,  g_vht);
    cudaGetSymbolAddress((void**)&hop,  g_hop);
    cudaGetSymbolAddress((void**)&ap,   g_ap);
    cudaGetSymbolAddress((void**)&tmp,  g_tmp);

    cudaFuncSetAttribute(tgemm<2, 2, 1>, cudaFuncAttributeMaxDynamicSharedMemorySize, SMEMB);
    cudaFuncSetAttribute(tgemm<1, 1, 1>, cudaFuncAttributeMaxDynamicSharedMemorySize, SMEMB);
    cudaFuncSetAttribute(tgemm<2, 1, 1>, cudaFuncAttributeMaxDynamicSharedMemorySize, SMEMB);
    cudaFuncSetAttribute(tgemm<3, 1, 1>, cudaFuncAttributeMaxDynamicSharedMemorySize, SMEMB);

    const long QKSZ = (long)NBL * ND;        // 1048576
    const long WSZ  = (long)NHD * ND;        // 524288
    const long BIG  = (long)NBL * NHD;       // 8388608

    // ---- fused conversions: launch 0 = q/k/v (split=QKSZ), launch 1 = weights (split=WSZ)
    cvt4_k<<<dim3(NBL * ND / 4 / 256, 3), 256>>>(
        q, k, v, v, qkp, qkp + 2 * QKSZ, vp, vp, NBL * ND / 4, QKSZ);
    cvt4_k<<<dim3(NHD * ND / 4 / 256, 4), 256>>>(
        w_qs, w_ks, w_vs, fc_w, wqkp, wqkp + 2 * WSZ, wvp, fcwp, NHD * ND / 4, WSZ);

    // ---- Q+K projections fused (2 MMAs: in hi/lo x weight hi), z selects q/k ----
    tgemm<2, 2, 1><<<dim3(16, 32, 2), 256, SMEMB>>>(
        qkp, QKSZ, ND, wqkp, WSZ, ND, qkhp, NHD, 0, ND, 1,
        0, 2 * QKSZ,      // A: zh -> q/k input planes
        0, 2 * WSZ,       // B: zh -> wq/wk planes
        0, BIG,           // C: zh -> qh/kh
        nullptr, 0);

    // ---- V projection (1x1, single-plane out): vht[hd, token] = w_vs @ v^T ----
    tgemm<2, 1, 1><<<dim3(32, 16, 1), 256, SMEMB>>>(
        wvp, 0, ND, vp, 0, ND, vht, NBL, 0, ND, 1,
        0, 0, 0, 0, 0, 0, nullptr, 0);

    // ---- scores (1x1): attn[(h*B+b)] = qh @ kh^T /16, clip, mask ----
    tgemm<1, 1, 1><<<dim3(8, 8, 32), 256, SMEMB>>>(
        qkhp, 0, NHD, qkhp + BIG, 0, NHD, attn, NL, 0, ND, NB,
        (long)NL * NHD, (long)ND,
        (long)NL * NHD, (long)ND,
        (long)NL * NL, (long)NB * NL * NL,
        mask, (long)NL * NL);

    // ---- masked softmax in place + single fp16 plane ----
    softmax_k<<<NH * NB * NL, 256>>>(attn, ap);

    // ---- attn @ V (1x1): hop[b,l, h*256+d] ----
    tgemm<2, 1, 1><<<dim3(2, 8, 32), 256, SMEMB>>>(
        ap, 0, NL, vht, 0, NBL, hop, NHD, 0, NL, NB,
        (long)NL * NL, (long)NB * NL * NL,
        (long)NL, (long)ND * NBL,
        (long)NL * NHD, (long)ND,
        nullptr, 0);

    // ---- fc (1x1): split-K = 4 -> fp32 partials ----
    tgemm<3, 1, 1><<<dim3(2, 32, 4), 256, SMEMB>>>(
        hop, 0, NHD, fcwp, 0, NHD, tmp, ND, 0, 512, 1,
        0, 512, 0, 512, 0, (long)NBL * ND, nullptr, 0);

    // ---- reduce + bias + residual + LayerNorm ----
    fc_ln_k<<<NBL, 256>>>(tmp, fc_b, q, ln_g, ln_b, out);
}

// round 13
// speedup vs baseline: 2.1920x; 1.1221x over previous
#include <cuda_runtime.h>
#include <cuda_fp16.h>
#include <mma.h>
#include <cstdint>

using namespace nvcuda;

#define NB 4
#define NL 1024
#define ND 256
#define NH 8
#define NHD 2048
#define NBL 4096
#define ATT ((size_t)NB * NH * NL * NL)   // 33,554,432 attn elems

#define BKK 64                 // k-tile
#define LDS_AB 72              // BK(64) + 8 pad -> 144B rows, LDSM conflict-free
#define PLE (128 * LDS_AB)     // elems per plane tile (9216)
#define PLB (PLE * 2)          // bytes per plane tile (18432)
#define LDC_S 132              // epilogue smem stride (elems)
#define CS_B  (128 * LDC_S * 4)            // fp32 staging bytes (67584)

// ---------------------------------------------------------------------------
// cp.async helpers
// ---------------------------------------------------------------------------
__device__ __forceinline__ uint32_t smem_u32(const void* p) {
    uint32_t a;
    asm("{ .reg .u64 t; cvta.to.shared.u64 t, %1; cvt.u32.u64 %0, t; }" : "=r"(a) : "l"(p));
    return a;
}
#define CP_ASYNC16(dst, src) \
    asm volatile("cp.async.cg.shared.global [%0], [%1], 16;" :: "r"(dst), "l"(src) : "memory")
#define CP_COMMIT() asm volatile("cp.async.commit_group;" ::: "memory")
#define CP_WAIT0()  asm volatile("cp.async.wait_group 0;" ::: "memory")
#define CP_WAIT1()  asm volatile("cp.async.wait_group 1;" ::: "memory")

// ---------------------------------------------------------------------------
// scratch (device globals — allocations forbidden)
// q/k fused buffers: [q_hi | q_lo | k_hi | k_lo], ditto weights, outputs [qh|kh]
// ---------------------------------------------------------------------------
static __device__ __align__(16) __half g_qkp[4 * NBL * ND];
static __device__ __align__(16) __half g_vp[2 * NBL * ND];
static __device__ __align__(16) __half g_wqkp[4 * NHD * ND];
static __device__ __align__(16) __half g_wvp[2 * NHD * ND];
static __device__ __align__(16) __half g_fcwp[2 * ND * NHD];
static __device__ __align__(16) __half g_qkhp[2 * (size_t)NBL * NHD];  // [qh | kh]
static __device__ __align__(16) __half g_vht[(size_t)NHD * NBL];       // single plane
static __device__ __align__(16) __half g_hop[(size_t)NBL * NHD];       // single plane
static __device__ __align__(16) __half g_ap[ATT];                      // single plane
static __device__ float g_tmp[(size_t)4 * NBL * ND];

// ---------------------------------------------------------------------------
// fused fp32 -> (hi, lo) fp16 planes for up to 4 tensors (blockIdx.y selects)
// ---------------------------------------------------------------------------
__global__ void __launch_bounds__(256) cvt4_k(
    const float* __restrict__ s0, const float* __restrict__ s1,
    const float* __restrict__ s2, const float* __restrict__ s3,
    __half* __restrict__ d0, __half* __restrict__ d1,
    __half* __restrict__ d2, __half* __restrict__ d3,
    int n4, long split)
{
    const int which = blockIdx.y;
    const float* x = which == 0 ? s0 : which == 1 ? s1 : which == 2 ? s2 : s3;
    __half* hi = which == 0 ? d0 : which == 1 ? d1 : which == 2 ? d2 : d3;
    int i = blockIdx.x * 256 + threadIdx.x;
    if (i >= n4) return;
    float4 v = *((const float4*)x + i);
    float f[4] = {v.x, v.y, v.z, v.w};
    __align__(8) __half h[4], l[4];
#pragma unroll
    for (int j = 0; j < 4; j++) {
        h[j] = __float2half_rn(f[j]);
        l[j] = __float2half_rn(f[j] - __half2float(h[j]));
    }
    *(uint2*)(hi + (size_t)i * 4)         = *(uint2*)h;
    *(uint2*)(hi + split + (size_t)i * 4) = *(uint2*)l;
}

// ---------------------------------------------------------------------------
// WMMA fp16 GEMM, configurable compensation planes, compact SMEM.
//   AP/BP = number of fp16 planes for A/B (1 or 2). Stage = (AP+BP)*PLB bytes.
//   Occupancy: 1 CTA/SM for multi-plane kernels, 2 CTAs/SM for 1x1 kernels.
//   Main term Ah*Bh -> fp32 acc; correction terms -> fp16 acc (combined in epi).
//   EPI 1: scores(scale/clip/mask->sentinel)  2: fp16 single out  3: fp32 out
// 256 threads (8 warps, 2x4), warp tile 64x32, BK=64, 2-stage cp.async.
// ---------------------------------------------------------------------------
template <int EPI, int AP, int BP>
__global__ void __launch_bounds__(256, (AP + BP > 2) ? 1 : 2) tgemm(
    const __half* __restrict__ Ag, long Asplit, int lda,
    const __half* __restrict__ Bg, long Bsplit, int ldb,
    void* __restrict__ Cgv, int ldc, long Csplit,
    int K, int nBdim,
    long sAb, long sAh, long sBb, long sBh, long sCb, long sCh,
    const int* __restrict__ maskg, long sMb)
{
    constexpr bool CORR = (AP + BP > 2);
    constexpr int  STGBT = (AP + BP) * PLB;   // bytes per pipeline stage
    extern __shared__ __align__(16) char sm[];
    const uint32_t smb = smem_u32(sm);
    float*  Cs = (float*)sm;               // fp32 acc staging
    __half* Hs = (__half*)(sm + CS_B);     // fp16 correction staging (CORR only)

    const int tid = threadIdx.x;
    const int wid = tid >> 5;
    const int wm = wid & 1;   // warp row (2 x 64)
    const int wn = wid >> 1;  // warp col (4 x 32)

    const int z = blockIdx.z, zb = z % nBdim, zh = z / nBdim;
    const __half* Ap_ = Ag + (size_t)zb * sAb + (size_t)zh * sAh;
    const __half* Bp_ = Bg + (size_t)zb * sBb + (size_t)zh * sBh;

    const int rowBase = blockIdx.y * 128;
    const int colBase = blockIdx.x * 128;

    wmma::fragment<wmma::accumulator, 16, 16, 16, float>  acc[4][2];
    wmma::fragment<wmma::accumulator, 16, 16, 16, __half> hacc[4][2];
#pragma unroll
    for (int i = 0; i < 4; i++)
#pragma unroll
        for (int j = 0; j < 2; j++) {
            wmma::fill_fragment(acc[i][j], 0.f);
            if (CORR) wmma::fill_fragment(hacc[i][j], __float2half(0.f));
        }

    // issue one stage of async loads (compact layout: only planes in use)
    auto ldst = [&](int t, int s) {
        const int ko = t * BKK;
        const uint32_t sb = smb + s * STGBT;
#pragma unroll
        for (int i = 0; i < 4; i++) {
            const int c = tid + i * 256;          // 0..1023
            const int row = c >> 3, col = (c & 7) * 8;
            const uint32_t soff = (uint32_t)(row * LDS_AB + col) * 2;
            const __half* pa = Ap_ + (size_t)(rowBase + row) * lda + ko + col;
            CP_ASYNC16(sb + soff, pa);
            if (AP == 2) CP_ASYNC16(sb + PLB + soff, pa + Asplit);
            const __half* pb = Bp_ + (size_t)(colBase + row) * ldb + ko + col;
            CP_ASYNC16(sb + AP * PLB + soff, pb);
            if (BP == 2) CP_ASYNC16(sb + (AP + 1) * PLB + soff, pb + Bsplit);
        }
        CP_COMMIT();
    };

    auto compute = [&](int s) {
        const __half* base = (const __half*)(sm + s * STGBT);
        const __half* Ah0 = base + wm * 64 * LDS_AB;
        const __half* Al0 = Ah0 + PLE;
        const __half* Bh0 = base + AP * PLE + wn * 32 * LDS_AB;
        const __half* Bl0 = Bh0 + PLE;
#pragma unroll
        for (int ks = 0; ks < 4; ks++) {
            wmma::fragment<wmma::matrix_a, 16, 16, 16, __half, wmma::row_major> fah[4], fal[4];
            wmma::fragment<wmma::matrix_b, 16, 16, 16, __half, wmma::col_major> fbh[2], fbl[2];
#pragma unroll
            for (int i = 0; i < 4; i++) {
                wmma::load_matrix_sync(fah[i], Ah0 + i * 16 * LDS_AB + ks * 16, LDS_AB);
                if (AP == 2)
                    wmma::load_matrix_sync(fal[i], Al0 + i * 16 * LDS_AB + ks * 16, LDS_AB);
            }
#pragma unroll
            for (int j = 0; j < 2; j++) {
                wmma::load_matrix_sync(fbh[j], Bh0 + j * 16 * LDS_AB + ks * 16, LDS_AB);
                if (BP == 2)
                    wmma::load_matrix_sync(fbl[j], Bl0 + j * 16 * LDS_AB + ks * 16, LDS_AB);
            }
#pragma unroll
            for (int i = 0; i < 4; i++)
#pragma unroll
                for (int j = 0; j < 2; j++) {
                    wmma::mma_sync(acc[i][j], fah[i], fbh[j], acc[i][j]);       // fp32 acc
                    if (BP == 2)
                        wmma::mma_sync(hacc[i][j], fah[i], fbl[j], hacc[i][j]); // fp16 acc
                    if (AP == 2)
                        wmma::mma_sync(hacc[i][j], fal[i], fbh[j], hacc[i][j]); // fp16 acc
                }
        }
    };

    // ---- 2-stage pipelined mainloop (R4 structure — measured best) ----
    const int T = K / BKK;
    ldst(0, 0);
    ldst(1, 1);
    for (int t = 0; t < T; t++) {
        if (t == T - 1) { CP_WAIT0(); } else { CP_WAIT1(); }
        __syncthreads();
        compute(t & 1);
        __syncthreads();
        if (t + 2 < T) ldst(t + 2, t & 1);
    }

    // ---- epilogue: stage accumulators through SMEM, combine ----
#pragma unroll
    for (int i = 0; i < 4; i++)
#pragma unroll
        for (int j = 0; j < 2; j++) {
            wmma::store_matrix_sync(Cs + (size_t)(wm * 64 + i * 16) * LDC_S + wn * 32 + j * 16,
                                    acc[i][j], LDC_S, wmma::mem_row_major);
            if (CORR)
                wmma::store_matrix_sync(Hs + (size_t)(wm * 64 + i * 16) * LDC_S + wn * 32 + j * 16,
                                        hacc[i][j], LDC_S, wmma::mem_row_major);
        }
    __syncthreads();

    const int row = tid >> 1;
    const int ch  = (tid & 1) * 64;
    const float*  crow = Cs + (size_t)row * LDC_S + ch;
    const __half* hrow = Hs + (size_t)row * LDC_S + ch;
    const int gr = rowBase + row;
    const int gc = colBase + ch;

    auto getv = [&](int idx) -> float {
        float v = crow[idx];
        if (CORR) v += __half2float(hrow[idx]);
        return v;
    };

    if (EPI == 2) {
        __half* Ch = (__half*)Cgv + (size_t)zb * sCb + (size_t)zh * sCh +
                     (size_t)gr * ldc + gc;
#pragma unroll
        for (int cb = 0; cb < 64; cb += 8) {
            __align__(16) __half hv[8];
#pragma unroll
            for (int j = 0; j < 8; j++) hv[j] = __float2half_rn(getv(cb + j));
            *(uint4*)(Ch + cb) = *(uint4*)hv;
        }
    } else if (EPI == 1) {
        float* C = (float*)Cgv + (size_t)zb * sCb + (size_t)zh * sCh + (size_t)gr * ldc + gc;
        const int* mrow = maskg + (size_t)zb * sMb + (size_t)gr * NL + gc;
#pragma unroll
        for (int j4 = 0; j4 < 16; j4++) {
            int4 m = *(const int4*)(mrow + j4 * 4);
            int mm[4] = {m.x, m.y, m.z, m.w};
            float ov[4];
#pragma unroll
            for (int j = 0; j < 4; j++) {
                float s = getv(j4 * 4 + j) * 0.0625f;   // 1/sqrt(256)
                s = fminf(15.f, fmaxf(-15.f, s));
                ov[j] = mm[j] ? s : 30000.f;
            }
            *(float4*)(C + j4 * 4) = *(float4*)ov;
        }
    } else {  // EPI == 3: plain fp32
        float* C = (float*)Cgv + (size_t)zb * sCb + (size_t)zh * sCh + (size_t)gr * ldc + gc;
#pragma unroll
        for (int j4 = 0; j4 < 16; j4++) {
            float ov[4] = {getv(j4 * 4), getv(j4 * 4 + 1), getv(j4 * 4 + 2), getv(j4 * 4 + 3)};
            *(float4*)(C + j4 * 4) = *(float4*)ov;
        }
    }
}

#define SMEM_21 (2 * 3 * PLB)   // 110592 B for AP+BP=3 kernels
#define SMEM_11 (2 * 2 * PLB)   // 73728 B for 1x1 kernels (2 CTAs/SM)

// ---------------------------------------------------------------------------
// masked softmax in place (sentinel > 1000 = masked); emits single fp16 plane.
// ---------------------------------------------------------------------------
__global__ void __launch_bounds__(256) softmax_k(float* __restrict__ attn,
                                                 __half* __restrict__ ap)
{
    __shared__ float sh[8];
    const size_t rbase = (size_t)blockIdx.x * 1024;
    float* p = attn + rbase;
    const int t = threadIdx.x;

    float4 v4 = ((const float4*)p)[t];
    float x[4] = {v4.x, v4.y, v4.z, v4.w};
    bool msk[4];
    float mx = -1e30f;
#pragma unroll
    for (int i = 0; i < 4; i++) {
        msk[i] = (x[i] > 1000.f);
        if (msk[i]) x[i] = 0.f;
        mx = fmaxf(mx, x[i]);
    }
#pragma unroll
    for (int o = 16; o; o >>= 1) mx = fmaxf(mx, __shfl_xor_sync(0xffffffffu, mx, o));
    if ((t & 31) == 0) sh[t >> 5] = mx;
    __syncthreads();
    mx = sh[0];
#pragma unroll
    for (int i = 1; i < 8; i++) mx = fmaxf(mx, sh[i]);

    float e[4], s = 0.f;
#pragma unroll
    for (int i = 0; i < 4; i++) {
        e[i] = msk[i] ? 0.f : __expf(x[i] - mx);
        s += e[i];
    }
#pragma unroll
    for (int o = 16; o; o >>= 1) s += __shfl_xor_sync(0xffffffffu, s, o);
    __syncthreads();
    if ((t & 31) == 0) sh[t >> 5] = s;
    __syncthreads();
    s = 0.f;
#pragma unroll
    for (int i = 0; i < 8; i++) s += sh[i];

    const float inv = 1.f / (s + 1e-6f);
    float ov[4] = {e[0] * inv, e[1] * inv, e[2] * inv, e[3] * inv};
    ((float4*)p)[t] = *(float4*)ov;

    __align__(8) __half h[4];
#pragma unroll
    for (int i = 0; i < 4; i++) h[i] = __float2half_rn(ov[i]);
    *(uint2*)(ap + rbase + (size_t)t * 4) = *(uint2*)h;
}

// ---------------------------------------------------------------------------
// split-K reduce + bias + residual + LayerNorm
// ---------------------------------------------------------------------------
__global__ void __launch_bounds__(256) fc_ln_k(
    const float* __restrict__ tmp, const float* __restrict__ fcb,
    const float* __restrict__ resid, const float* __restrict__ lg,
    const float* __restrict__ lb, float* __restrict__ out)
{
    __shared__ float shs[8], shq[8];
    const size_t o = (size_t)blockIdx.x * 256 + threadIdx.x;
    const int t = threadIdx.x;

    float v = tmp[o] + tmp[o + 1048576] + tmp[o + 2097152] + tmp[o + 3145728]
            + fcb[t] + resid[o];

    float s = v, qq = v * v;
#pragma unroll
    for (int d = 16; d; d >>= 1) {
        s  += __shfl_xor_sync(0xffffffffu, s, d);
        qq += __shfl_xor_sync(0xffffffffu, qq, d);
    }
    if ((t & 31) == 0) { shs[t >> 5] = s; shq[t >> 5] = qq; }
    __syncthreads();
    s = 0.f; qq = 0.f;
#pragma unroll
    for (int i = 0; i < 8; i++) { s += shs[i]; qq += shq[i]; }

    const float mean = s * (1.f / 256.f);
    const float var  = qq * (1.f / 256.f) - mean * mean;
    out[o] = (v - mean) * rsqrtf(var + 1e-5f) * lg[t] + lb[t];
}

// ---------------------------------------------------------------------------
extern "C" void kernel_launch(void* const* d_in, const int* in_sizes, int n_in,
                              void* d_out, int out_size)
{
    const float* q    = (const float*)d_in[0];
    const int*   mask = (const int*)  d_in[1];
    const float* k    = (const float*)d_in[2];
    const float* v    = (const float*)d_in[3];
    const float* w_qs = (const float*)d_in[4];
    const float* w_ks = (const float*)d_in[5];
    const float* w_vs = (const float*)d_in[6];
    const float* fc_w = (const float*)d_in[7];
    const float* fc_b = (const float*)d_in[8];
    const float* ln_g = (const float*)d_in[9];
    const float* ln_b = (const float*)d_in[10];

    float* out  = (float*)d_out;
    float* attn = out + (size_t)NBL * ND;

    __half *qkp, *vp, *wqkp, *wvp, *fcwp, *qkhp, *vht, *hop, *ap;
    float* tmp;
    cudaGetSymbolAddress((void**)&qkp,  g_qkp);
    cudaGetSymbolAddress((void**)&vp,   g_vp);
    cudaGetSymbolAddress((void**)&wqkp, g_wqkp);
    cudaGetSymbolAddress((void**)&wvp,  g_wvp);
    cudaGetSymbolAddress((void**)&fcwp, g_fcwp);
    cudaGetSymbolAddress((void**)&qkhp, g_qkhp);
    cudaGetSymbolAddress((void**)&vht,  g_vht);
    cudaGetSymbolAddress((void**)&hop,  g_hop);
    cudaGetSymbolAddress((void**)&ap,   g_ap);
    cudaGetSymbolAddress((void**)&tmp,  g_tmp);

    cudaFuncSetAttribute(tgemm<2, 2, 1>, cudaFuncAttributeMaxDynamicSharedMemorySize, SMEM_21);
    cudaFuncSetAttribute(tgemm<1, 1, 1>, cudaFuncAttributeMaxDynamicSharedMemorySize, SMEM_11);
    cudaFuncSetAttribute(tgemm<2, 1, 1>, cudaFuncAttributeMaxDynamicSharedMemorySize, SMEM_11);
    cudaFuncSetAttribute(tgemm<3, 1, 1>, cudaFuncAttributeMaxDynamicSharedMemorySize, SMEM_11);

    const long QKSZ = (long)NBL * ND;        // 1048576
    const long WSZ  = (long)NHD * ND;        // 524288
    const long BIG  = (long)NBL * NHD;       // 8388608

    // ---- fused conversions: launch 0 = q/k/v (split=QKSZ), launch 1 = weights (split=WSZ)
    cvt4_k<<<dim3(NBL * ND / 4 / 256, 3), 256>>>(
        q, k, v, v, qkp, qkp + 2 * QKSZ, vp, vp, NBL * ND / 4, QKSZ);
    cvt4_k<<<dim3(NHD * ND / 4 / 256, 4), 256>>>(
        w_qs, w_ks, w_vs, fc_w, wqkp, wqkp + 2 * WSZ, wvp, fcwp, NHD * ND / 4, WSZ);

    // ---- Q+K projections fused (2 MMAs: in hi/lo x weight hi), z selects q/k ----
    tgemm<2, 2, 1><<<dim3(16, 32, 2), 256, SMEM_21>>>(
        qkp, QKSZ, ND, wqkp, WSZ, ND, qkhp, NHD, 0, ND, 1,
        0, 2 * QKSZ,      // A: zh -> q/k input planes
        0, 2 * WSZ,       // B: zh -> wq/wk planes
        0, BIG,           // C: zh -> qh/kh
        nullptr, 0);

    // ---- V projection (1x1, single-plane out): vht[hd, token] = w_vs @ v^T ----
    tgemm<2, 1, 1><<<dim3(32, 16, 1), 256, SMEM_11>>>(
        wvp, 0, ND, vp, 0, ND, vht, NBL, 0, ND, 1,
        0, 0, 0, 0, 0, 0, nullptr, 0);

    // ---- scores (1x1): attn[(h*B+b)] = qh @ kh^T /16, clip, mask ----
    tgemm<1, 1, 1><<<dim3(8, 8, 32), 256, SMEM_11>>>(
        qkhp, 0, NHD, qkhp + BIG, 0, NHD, attn, NL, 0, ND, NB,
        (long)NL * NHD, (long)ND,
        (long)NL * NHD, (long)ND,
        (long)NL * NL, (long)NB * NL * NL,
        mask, (long)NL * NL);

    // ---- masked softmax in place + single fp16 plane ----
    softmax_k<<<NH * NB * NL, 256>>>(attn, ap);

    // ---- attn @ V (1x1): hop[b,l, h*256+d] ----
    tgemm<2, 1, 1><<<dim3(2, 8, 32), 256, SMEM_11>>>(
        ap, 0, NL, vht, 0, NBL, hop, NHD, 0, NL, NB,
        (long)NL * NL, (long)NB * NL * NL,
        (long)NL, (long)ND * NBL,
        (long)NL * NHD, (long)ND,
        nullptr, 0);

    // ---- fc (1x1): split-K = 4 -> fp32 partials ----
    tgemm<3, 1, 1><<<dim3(2, 32, 4), 256, SMEM_11>>>(
        hop, 0, NHD, fcwp, 0, NHD, tmp, ND, 0, 512, 1,
        0, 512, 0, 512, 0, (long)NBL * ND, nullptr, 0);

    // ---- reduce + bias + residual + LayerNorm ----
    fc_ln_k<<<NBL, 256>>>(tmp, fc_b, q, ln_g, ln_b, out);
}

// round 14
// speedup vs baseline: 2.3794x; 1.0855x over previous
#include <cuda_runtime.h>
#include <cuda_fp16.h>
#include <mma.h>
#include <cstdint>

using namespace nvcuda;

#define NB 4
#define NL 1024
#define ND 256
#define NH 8
#define NHD 2048
#define NBL 4096
#define ATT ((size_t)NB * NH * NL * NL)   // 33,554,432 attn elems

#define BKK 64                 // k-tile
#define LDS_AB 72              // BK(64) + 8 pad -> 144B rows, LDSM conflict-free
#define PLE (128 * LDS_AB)     // elems per plane tile (9216)
#define PLB (PLE * 2)          // bytes per plane tile (18432)
#define LDC_S 132              // epilogue smem stride (elems)
#define CS_B  (128 * LDC_S * 4)            // fp32 staging bytes (67584)

// ---------------------------------------------------------------------------
// cp.async helpers
// ---------------------------------------------------------------------------
__device__ __forceinline__ uint32_t smem_u32(const void* p) {
    uint32_t a;
    asm("{ .reg .u64 t; cvta.to.shared.u64 t, %1; cvt.u32.u64 %0, t; }" : "=r"(a) : "l"(p));
    return a;
}
#define CP_ASYNC16(dst, src) \
    asm volatile("cp.async.cg.shared.global [%0], [%1], 16;" :: "r"(dst), "l"(src) : "memory")
#define CP_COMMIT() asm volatile("cp.async.commit_group;" ::: "memory")
#define CP_WAIT0()  asm volatile("cp.async.wait_group 0;" ::: "memory")
#define CP_WAIT1()  asm volatile("cp.async.wait_group 1;" ::: "memory")

// ---------------------------------------------------------------------------
// scratch (device globals — allocations forbidden)
// q/k fused buffers: [q_hi | q_lo | k_hi | k_lo] (lo kept by cvt, unused now)
// ---------------------------------------------------------------------------
static __device__ __align__(16) __half g_qkp[4 * NBL * ND];
static __device__ __align__(16) __half g_vp[2 * NBL * ND];
static __device__ __align__(16) __half g_wqkp[4 * NHD * ND];
static __device__ __align__(16) __half g_wvp[2 * NHD * ND];
static __device__ __align__(16) __half g_fcwp[2 * ND * NHD];
static __device__ __align__(16) __half g_qkhp[2 * (size_t)NBL * NHD];  // [qh | kh]
static __device__ __align__(16) __half g_vht[(size_t)NHD * NBL];       // single plane
static __device__ __align__(16) __half g_hop[(size_t)NBL * NHD];       // single plane
static __device__ __align__(16) __half g_ap[ATT];                      // single plane
static __device__ float g_tmp[(size_t)4 * NBL * ND];

// ---------------------------------------------------------------------------
// fused fp32 -> (hi, lo) fp16 planes for up to 4 tensors (blockIdx.y selects)
// ---------------------------------------------------------------------------
__global__ void __launch_bounds__(256) cvt4_k(
    const float* __restrict__ s0, const float* __restrict__ s1,
    const float* __restrict__ s2, const float* __restrict__ s3,
    __half* __restrict__ d0, __half* __restrict__ d1,
    __half* __restrict__ d2, __half* __restrict__ d3,
    int n4, long split)
{
    const int which = blockIdx.y;
    const float* x = which == 0 ? s0 : which == 1 ? s1 : which == 2 ? s2 : s3;
    __half* hi = which == 0 ? d0 : which == 1 ? d1 : which == 2 ? d2 : d3;
    int i = blockIdx.x * 256 + threadIdx.x;
    if (i >= n4) return;
    float4 v = *((const float4*)x + i);
    float f[4] = {v.x, v.y, v.z, v.w};
    __align__(8) __half h[4];
#pragma unroll
    for (int j = 0; j < 4; j++) h[j] = __float2half_rn(f[j]);
    *(uint2*)(hi + (size_t)i * 4) = *(uint2*)h;
    (void)split;
}

// ---------------------------------------------------------------------------
// WMMA fp16 GEMM, configurable compensation planes, compact SMEM.
//   AP/BP = number of fp16 planes for A/B (1 or 2). Stage = (AP+BP)*PLB bytes.
//   Occupancy: 1 CTA/SM for multi-plane kernels, 2 CTAs/SM for 1x1 kernels.
//   Main term Ah*Bh -> fp32 acc; correction terms -> fp16 acc (combined in epi).
//   EPI 1: scores(scale/clip/mask->sentinel)  2: fp16 single out  3: fp32 out
// 256 threads (8 warps, 2x4), warp tile 64x32, BK=64, 2-stage cp.async.
// ---------------------------------------------------------------------------
template <int EPI, int AP, int BP>
__global__ void __launch_bounds__(256, (AP + BP > 2) ? 1 : 2) tgemm(
    const __half* __restrict__ Ag, long Asplit, int lda,
    const __half* __restrict__ Bg, long Bsplit, int ldb,
    void* __restrict__ Cgv, int ldc, long Csplit,
    int K, int nBdim,
    long sAb, long sAh, long sBb, long sBh, long sCb, long sCh,
    const int* __restrict__ maskg, long sMb)
{
    constexpr bool CORR = (AP + BP > 2);
    constexpr int  STGBT = (AP + BP) * PLB;   // bytes per pipeline stage
    extern __shared__ __align__(16) char sm[];
    const uint32_t smb = smem_u32(sm);
    float*  Cs = (float*)sm;               // fp32 acc staging
    __half* Hs = (__half*)(sm + CS_B);     // fp16 correction staging (CORR only)

    const int tid = threadIdx.x;
    const int wid = tid >> 5;
    const int wm = wid & 1;   // warp row (2 x 64)
    const int wn = wid >> 1;  // warp col (4 x 32)

    const int z = blockIdx.z, zb = z % nBdim, zh = z / nBdim;
    const __half* Ap_ = Ag + (size_t)zb * sAb + (size_t)zh * sAh;
    const __half* Bp_ = Bg + (size_t)zb * sBb + (size_t)zh * sBh;

    const int rowBase = blockIdx.y * 128;
    const int colBase = blockIdx.x * 128;

    wmma::fragment<wmma::accumulator, 16, 16, 16, float>  acc[4][2];
    wmma::fragment<wmma::accumulator, 16, 16, 16, __half> hacc[4][2];
#pragma unroll
    for (int i = 0; i < 4; i++)
#pragma unroll
        for (int j = 0; j < 2; j++) {
            wmma::fill_fragment(acc[i][j], 0.f);
            if (CORR) wmma::fill_fragment(hacc[i][j], __float2half(0.f));
        }

    // issue one stage of async loads (compact layout: only planes in use)
    auto ldst = [&](int t, int s) {
        const int ko = t * BKK;
        const uint32_t sb = smb + s * STGBT;
#pragma unroll
        for (int i = 0; i < 4; i++) {
            const int c = tid + i * 256;          // 0..1023
            const int row = c >> 3, col = (c & 7) * 8;
            const uint32_t soff = (uint32_t)(row * LDS_AB + col) * 2;
            const __half* pa = Ap_ + (size_t)(rowBase + row) * lda + ko + col;
            CP_ASYNC16(sb + soff, pa);
            if (AP == 2) CP_ASYNC16(sb + PLB + soff, pa + Asplit);
            const __half* pb = Bp_ + (size_t)(colBase + row) * ldb + ko + col;
            CP_ASYNC16(sb + AP * PLB + soff, pb);
            if (BP == 2) CP_ASYNC16(sb + (AP + 1) * PLB + soff, pb + Bsplit);
        }
        CP_COMMIT();
    };

    auto compute = [&](int s) {
        const __half* base = (const __half*)(sm + s * STGBT);
        const __half* Ah0 = base + wm * 64 * LDS_AB;
        const __half* Al0 = Ah0 + PLE;
        const __half* Bh0 = base + AP * PLE + wn * 32 * LDS_AB;
        const __half* Bl0 = Bh0 + PLE;
#pragma unroll
        for (int ks = 0; ks < 4; ks++) {
            wmma::fragment<wmma::matrix_a, 16, 16, 16, __half, wmma::row_major> fah[4], fal[4];
            wmma::fragment<wmma::matrix_b, 16, 16, 16, __half, wmma::col_major> fbh[2], fbl[2];
#pragma unroll
            for (int i = 0; i < 4; i++) {
                wmma::load_matrix_sync(fah[i], Ah0 + i * 16 * LDS_AB + ks * 16, LDS_AB);
                if (AP == 2)
                    wmma::load_matrix_sync(fal[i], Al0 + i * 16 * LDS_AB + ks * 16, LDS_AB);
            }
#pragma unroll
            for (int j = 0; j < 2; j++) {
                wmma::load_matrix_sync(fbh[j], Bh0 + j * 16 * LDS_AB + ks * 16, LDS_AB);
                if (BP == 2)
                    wmma::load_matrix_sync(fbl[j], Bl0 + j * 16 * LDS_AB + ks * 16, LDS_AB);
            }
#pragma unroll
            for (int i = 0; i < 4; i++)
#pragma unroll
                for (int j = 0; j < 2; j++) {
                    wmma::mma_sync(acc[i][j], fah[i], fbh[j], acc[i][j]);       // fp32 acc
                    if (BP == 2)
                        wmma::mma_sync(hacc[i][j], fah[i], fbl[j], hacc[i][j]); // fp16 acc
                    if (AP == 2)
                        wmma::mma_sync(hacc[i][j], fal[i], fbh[j], hacc[i][j]); // fp16 acc
                }
        }
    };

    // ---- 2-stage pipelined mainloop (R4 structure — measured best) ----
    const int T = K / BKK;
    ldst(0, 0);
    ldst(1, 1);
    for (int t = 0; t < T; t++) {
        if (t == T - 1) { CP_WAIT0(); } else { CP_WAIT1(); }
        __syncthreads();
        compute(t & 1);
        __syncthreads();
        if (t + 2 < T) ldst(t + 2, t & 1);
    }

    // ---- epilogue: stage accumulators through SMEM, combine ----
#pragma unroll
    for (int i = 0; i < 4; i++)
#pragma unroll
        for (int j = 0; j < 2; j++) {
            wmma::store_matrix_sync(Cs + (size_t)(wm * 64 + i * 16) * LDC_S + wn * 32 + j * 16,
                                    acc[i][j], LDC_S, wmma::mem_row_major);
            if (CORR)
                wmma::store_matrix_sync(Hs + (size_t)(wm * 64 + i * 16) * LDC_S + wn * 32 + j * 16,
                                        hacc[i][j], LDC_S, wmma::mem_row_major);
        }
    __syncthreads();

    const int row = tid >> 1;
    const int ch  = (tid & 1) * 64;
    const float*  crow = Cs + (size_t)row * LDC_S + ch;
    const __half* hrow = Hs + (size_t)row * LDC_S + ch;
    const int gr = rowBase + row;
    const int gc = colBase + ch;

    auto getv = [&](int idx) -> float {
        float v = crow[idx];
        if (CORR) v += __half2float(hrow[idx]);
        return v;
    };

    if (EPI == 2) {
        __half* Ch = (__half*)Cgv + (size_t)zb * sCb + (size_t)zh * sCh +
                     (size_t)gr * ldc + gc;
#pragma unroll
        for (int cb = 0; cb < 64; cb += 8) {
            __align__(16) __half hv[8];
#pragma unroll
            for (int j = 0; j < 8; j++) hv[j] = __float2half_rn(getv(cb + j));
            *(uint4*)(Ch + cb) = *(uint4*)hv;
        }
    } else if (EPI == 1) {
        float* C = (float*)Cgv + (size_t)zb * sCb + (size_t)zh * sCh + (size_t)gr * ldc + gc;
        const int* mrow = maskg + (size_t)zb * sMb + (size_t)gr * NL + gc;
#pragma unroll
        for (int j4 = 0; j4 < 16; j4++) {
            int4 m = *(const int4*)(mrow + j4 * 4);
            int mm[4] = {m.x, m.y, m.z, m.w};
            float ov[4];
#pragma unroll
            for (int j = 0; j < 4; j++) {
                float s = getv(j4 * 4 + j) * 0.0625f;   // 1/sqrt(256)
                s = fminf(15.f, fmaxf(-15.f, s));
                ov[j] = mm[j] ? s : 30000.f;
            }
            *(float4*)(C + j4 * 4) = *(float4*)ov;
        }
    } else {  // EPI == 3: plain fp32
        float* C = (float*)Cgv + (size_t)zb * sCb + (size_t)zh * sCh + (size_t)gr * ldc + gc;
#pragma unroll
        for (int j4 = 0; j4 < 16; j4++) {
            float ov[4] = {getv(j4 * 4), getv(j4 * 4 + 1), getv(j4 * 4 + 2), getv(j4 * 4 + 3)};
            *(float4*)(C + j4 * 4) = *(float4*)ov;
        }
    }
}

#define SMEM_11 (2 * 2 * PLB)   // 73728 B for 1x1 kernels (2 CTAs/SM)

// ---------------------------------------------------------------------------
// masked softmax in place (sentinel > 1000 = masked); emits single fp16 plane.
// ---------------------------------------------------------------------------
__global__ void __launch_bounds__(256) softmax_k(float* __restrict__ attn,
                                                 __half* __restrict__ ap)
{
    __shared__ float sh[8];
    const size_t rbase = (size_t)blockIdx.x * 1024;
    float* p = attn + rbase;
    const int t = threadIdx.x;

    float4 v4 = ((const float4*)p)[t];
    float x[4] = {v4.x, v4.y, v4.z, v4.w};
    bool msk[4];
    float mx = -1e30f;
#pragma unroll
    for (int i = 0; i < 4; i++) {
        msk[i] = (x[i] > 1000.f);
        if (msk[i]) x[i] = 0.f;
        mx = fmaxf(mx, x[i]);
    }
#pragma unroll
    for (int o = 16; o; o >>= 1) mx = fmaxf(mx, __shfl_xor_sync(0xffffffffu, mx, o));
    if ((t & 31) == 0) sh[t >> 5] = mx;
    __syncthreads();
    mx = sh[0];
#pragma unroll
    for (int i = 1; i < 8; i++) mx = fmaxf(mx, sh[i]);

    float e[4], s = 0.f;
#pragma unroll
    for (int i = 0; i < 4; i++) {
        e[i] = msk[i] ? 0.f : __expf(x[i] - mx);
        s += e[i];
    }
#pragma unroll
    for (int o = 16; o; o >>= 1) s += __shfl_xor_sync(0xffffffffu, s, o);
    __syncthreads();
    if ((t & 31) == 0) sh[t >> 5] = s;
    __syncthreads();
    s = 0.f;
#pragma unroll
    for (int i = 0; i < 8; i++) s += sh[i];

    const float inv = 1.f / (s + 1e-6f);
    float ov[4] = {e[0] * inv, e[1] * inv, e[2] * inv, e[3] * inv};
    ((float4*)p)[t] = *(float4*)ov;

    __align__(8) __half h[4];
#pragma unroll
    for (int i = 0; i < 4; i++) h[i] = __float2half_rn(ov[i]);
    *(uint2*)(ap + rbase + (size_t)t * 4) = *(uint2*)h;
}

// ---------------------------------------------------------------------------
// split-K reduce + bias + residual + LayerNorm
// ---------------------------------------------------------------------------
__global__ void __launch_bounds__(256) fc_ln_k(
    const float* __restrict__ tmp, const float* __restrict__ fcb,
    const float* __restrict__ resid, const float* __restrict__ lg,
    const float* __restrict__ lb, float* __restrict__ out)
{
    __shared__ float shs[8], shq[8];
    const size_t o = (size_t)blockIdx.x * 256 + threadIdx.x;
    const int t = threadIdx.x;

    float v = tmp[o] + tmp[o + 1048576] + tmp[o + 2097152] + tmp[o + 3145728]
            + fcb[t] + resid[o];

    float s = v, qq = v * v;
#pragma unroll
    for (int d = 16; d; d >>= 1) {
        s  += __shfl_xor_sync(0xffffffffu, s, d);
        qq += __shfl_xor_sync(0xffffffffu, qq, d);
    }
    if ((t & 31) == 0) { shs[t >> 5] = s; shq[t >> 5] = qq; }
    __syncthreads();
    s = 0.f; qq = 0.f;
#pragma unroll
    for (int i = 0; i < 8; i++) { s += shs[i]; qq += shq[i]; }

    const float mean = s * (1.f / 256.f);
    const float var  = qq * (1.f / 256.f) - mean * mean;
    out[o] = (v - mean) * rsqrtf(var + 1e-5f) * lg[t] + lb[t];
}

// ---------------------------------------------------------------------------
extern "C" void kernel_launch(void* const* d_in, const int* in_sizes, int n_in,
                              void* d_out, int out_size)
{
    const float* q    = (const float*)d_in[0];
    const int*   mask = (const int*)  d_in[1];
    const float* k    = (const float*)d_in[2];
    const float* v    = (const float*)d_in[3];
    const float* w_qs = (const float*)d_in[4];
    const float* w_ks = (const float*)d_in[5];
    const float* w_vs = (const float*)d_in[6];
    const float* fc_w = (const float*)d_in[7];
    const float* fc_b = (const float*)d_in[8];
    const float* ln_g = (const float*)d_in[9];
    const float* ln_b = (const float*)d_in[10];

    float* out  = (float*)d_out;
    float* attn = out + (size_t)NBL * ND;

    __half *qkp, *vp, *wqkp, *wvp, *fcwp, *qkhp, *vht, *hop, *ap;
    float* tmp;
    cudaGetSymbolAddress((void**)&qkp,  g_qkp);
    cudaGetSymbolAddress((void**)&vp,   g_vp);
    cudaGetSymbolAddress((void**)&wqkp, g_wqkp);
    cudaGetSymbolAddress((void**)&wvp,  g_wvp);
    cudaGetSymbolAddress((void**)&fcwp, g_fcwp);
    cudaGetSymbolAddress((void**)&qkhp, g_qkhp);
    cudaGetSymbolAddress((void**)&vht,  g_vht);
    cudaGetSymbolAddress((void**)&hop,  g_hop);
    cudaGetSymbolAddress((void**)&ap,   g_ap);
    cudaGetSymbolAddress((void**)&tmp,  g_tmp);

    cudaFuncSetAttribute(tgemm<1, 1, 1>, cudaFuncAttributeMaxDynamicSharedMemorySize, SMEM_11);
    cudaFuncSetAttribute(tgemm<2, 1, 1>, cudaFuncAttributeMaxDynamicSharedMemorySize, SMEM_11);
    cudaFuncSetAttribute(tgemm<3, 1, 1>, cudaFuncAttributeMaxDynamicSharedMemorySize, SMEM_11);

    const long QKSZ = (long)NBL * ND;        // 1048576
    const long WSZ  = (long)NHD * ND;        // 524288
    const long BIG  = (long)NBL * NHD;       // 8388608

    // ---- fused conversions (hi planes only now) ----
    // layout kept: q_hi @ 0, k_hi @ 2*QKSZ; wq_hi @ 0, wk_hi @ 2*WSZ
    cvt4_k<<<dim3(NBL * ND / 4 / 256, 3), 256>>>(
        q, k, v, v, qkp, qkp + 2 * QKSZ, vp, vp, NBL * ND / 4, 0);
    cvt4_k<<<dim3(NHD * ND / 4 / 256, 4), 256>>>(
        w_qs, w_ks, w_vs, fc_w, wqkp, wqkp + 2 * WSZ, wvp, fcwp, NHD * ND / 4, 0);

    // ---- Q+K projections fused, 1 MMA each (z selects q/k) ----
    tgemm<2, 1, 1><<<dim3(16, 32, 2), 256, SMEM_11>>>(
        qkp, 0, ND, wqkp, 0, ND, qkhp, NHD, 0, ND, 1,
        0, 2 * QKSZ,      // A: zh -> q/k hi plane
        0, 2 * WSZ,       // B: zh -> wq/wk hi plane
        0, BIG,           // C: zh -> qh/kh
        nullptr, 0);

    // ---- V projection (1x1, single-plane out): vht[hd, token] = w_vs @ v^T ----
    tgemm<2, 1, 1><<<dim3(32, 16, 1), 256, SMEM_11>>>(
        wvp, 0, ND, vp, 0, ND, vht, NBL, 0, ND, 1,
        0, 0, 0, 0, 0, 0, nullptr, 0);

    // ---- scores (1x1): attn[(h*B+b)] = qh @ kh^T /16, clip, mask ----
    tgemm<1, 1, 1><<<dim3(8, 8, 32), 256, SMEM_11>>>(
        qkhp, 0, NHD, qkhp + BIG, 0, NHD, attn, NL, 0, ND, NB,
        (long)NL * NHD, (long)ND,
        (long)NL * NHD, (long)ND,
        (long)NL * NL, (long)NB * NL * NL,
        mask, (long)NL * NL);

    // ---- masked softmax in place + single fp16 plane ----
    softmax_k<<<NH * NB * NL, 256>>>(attn, ap);

    // ---- attn @ V (1x1): hop[b,l, h*256+d] ----
    tgemm<2, 1, 1><<<dim3(2, 8, 32), 256, SMEM_11>>>(
        ap, 0, NL, vht, 0, NBL, hop, NHD, 0, NL, NB,
        (long)NL * NL, (long)NB * NL * NL,
        (long)NL, (long)ND * NBL,
        (long)NL * NHD, (long)ND,
        nullptr, 0);

    // ---- fc (1x1): split-K = 4 -> fp32 partials ----
    tgemm<3, 1, 1><<<dim3(2, 32, 4), 256, SMEM_11>>>(
        hop, 0, NHD, fcwp, 0, NHD, tmp, ND, 0, 512, 1,
        0, 512, 0, 512, 0, (long)NBL * ND, nullptr, 0);

    // ---- reduce + bias + residual + LayerNorm ----
    fc_ln_k<<<NBL, 256>>>(tmp, fc_b, q, ln_g, ln_b, out);
}

// round 15
// speedup vs baseline: 2.4162x; 1.0155x over previous
#include <cuda_runtime.h>
#include <cuda_fp16.h>
#include <mma.h>
#include <cstdint>

using namespace nvcuda;

#define NB 4
#define NL 1024
#define ND 256
#define NH 8
#define NHD 2048
#define NBL 4096
#define ATT ((size_t)NB * NH * NL * NL)   // 33,554,432 attn elems

#define BKK 64                 // k-tile
#define LDS_AB 72              // BK(64) + 8 pad -> 144B rows, LDSM conflict-free
#define PLE (128 * LDS_AB)     // elems per plane tile (9216)
#define PLB (PLE * 2)          // bytes per plane tile (18432)
#define LDC_S 132              // epilogue smem stride (elems)
#define CS_B  (128 * LDC_S * 4)            // fp32 staging bytes (67584)

// ---------------------------------------------------------------------------
// cp.async helpers
// ---------------------------------------------------------------------------
__device__ __forceinline__ uint32_t smem_u32(const void* p) {
    uint32_t a;
    asm("{ .reg .u64 t; cvta.to.shared.u64 t, %1; cvt.u32.u64 %0, t; }" : "=r"(a) : "l"(p));
    return a;
}
#define CP_ASYNC16(dst, src) \
    asm volatile("cp.async.cg.shared.global [%0], [%1], 16;" :: "r"(dst), "l"(src) : "memory")
#define CP_COMMIT() asm volatile("cp.async.commit_group;" ::: "memory")
#define CP_WAIT0()  asm volatile("cp.async.wait_group 0;" ::: "memory")
#define CP_WAIT1()  asm volatile("cp.async.wait_group 1;" ::: "memory")

// ---------------------------------------------------------------------------
// scratch (device globals — allocations forbidden)
// ---------------------------------------------------------------------------
static __device__ __align__(16) __half g_qkp[4 * NBL * ND];
static __device__ __align__(16) __half g_vp[2 * NBL * ND];
static __device__ __align__(16) __half g_wqkp[4 * NHD * ND];
static __device__ __align__(16) __half g_wvp[2 * NHD * ND];
static __device__ __align__(16) __half g_fcwp[2 * ND * NHD];
static __device__ __align__(16) __half g_qkhp[2 * (size_t)NBL * NHD];  // [qh | kh]
static __device__ __align__(16) __half g_vht[(size_t)NHD * NBL];       // single plane
static __device__ __align__(16) __half g_hop[(size_t)NBL * NHD];       // single plane
static __device__ __align__(16) __half g_ap[ATT];                      // single plane
static __device__ float g_tmp[(size_t)4 * NBL * ND];

// ---------------------------------------------------------------------------
// fused fp32 -> fp16 hi planes for up to 4 tensors (blockIdx.y selects)
// ---------------------------------------------------------------------------
__global__ void __launch_bounds__(256) cvt4_k(
    const float* __restrict__ s0, const float* __restrict__ s1,
    const float* __restrict__ s2, const float* __restrict__ s3,
    __half* __restrict__ d0, __half* __restrict__ d1,
    __half* __restrict__ d2, __half* __restrict__ d3,
    int n4)
{
    const int which = blockIdx.y;
    const float* x = which == 0 ? s0 : which == 1 ? s1 : which == 2 ? s2 : s3;
    __half* hi = which == 0 ? d0 : which == 1 ? d1 : which == 2 ? d2 : d3;
    int i = blockIdx.x * 256 + threadIdx.x;
    if (i >= n4) return;
    float4 v = *((const float4*)x + i);
    float f[4] = {v.x, v.y, v.z, v.w};
    __align__(8) __half h[4];
#pragma unroll
    for (int j = 0; j < 4; j++) h[j] = __float2half_rn(f[j]);
    *(uint2*)(hi + (size_t)i * 4) = *(uint2*)h;
}

// ---------------------------------------------------------------------------
// WMMA fp16 1x1 GEMM (single plane each side), compact SMEM, 2 CTAs/SM.
//   EPI 1: scores(scale/clip/mask->sentinel)  2: fp16 single out  3: fp32 out
// 256 threads (8 warps, 2x4), warp tile 64x32, BK=64, 2-stage cp.async.
// ---------------------------------------------------------------------------
template <int EPI>
__global__ void __launch_bounds__(256, 2) tgemm(
    const __half* __restrict__ Ag, int lda,
    const __half* __restrict__ Bg, int ldb,
    void* __restrict__ Cgv, int ldc,
    int K, int nBdim,
    long sAb, long sAh, long sBb, long sBh, long sCb, long sCh,
    const int* __restrict__ maskg, long sMb)
{
    constexpr int STGBT = 2 * PLB;   // bytes per pipeline stage (A|B)
    extern __shared__ __align__(16) char sm[];
    const uint32_t smb = smem_u32(sm);
    float* Cs = (float*)sm;          // fp32 acc staging

    const int tid = threadIdx.x;
    const int wid = tid >> 5;
    const int wm = wid & 1;   // warp row (2 x 64)
    const int wn = wid >> 1;  // warp col (4 x 32)

    const int z = blockIdx.z, zb = z % nBdim, zh = z / nBdim;
    const __half* Ap_ = Ag + (size_t)zb * sAb + (size_t)zh * sAh;
    const __half* Bp_ = Bg + (size_t)zb * sBb + (size_t)zh * sBh;

    const int rowBase = blockIdx.y * 128;
    const int colBase = blockIdx.x * 128;

    wmma::fragment<wmma::accumulator, 16, 16, 16, float> acc[4][2];
#pragma unroll
    for (int i = 0; i < 4; i++)
#pragma unroll
        for (int j = 0; j < 2; j++) wmma::fill_fragment(acc[i][j], 0.f);

    auto ldst = [&](int t, int s) {
        const int ko = t * BKK;
        const uint32_t sb = smb + s * STGBT;
#pragma unroll
        for (int i = 0; i < 4; i++) {
            const int c = tid + i * 256;          // 0..1023
            const int row = c >> 3, col = (c & 7) * 8;
            const uint32_t soff = (uint32_t)(row * LDS_AB + col) * 2;
            const __half* pa = Ap_ + (size_t)(rowBase + row) * lda + ko + col;
            CP_ASYNC16(sb + soff, pa);
            const __half* pb = Bp_ + (size_t)(colBase + row) * ldb + ko + col;
            CP_ASYNC16(sb + PLB + soff, pb);
        }
        CP_COMMIT();
    };

    auto compute = [&](int s) {
        const __half* base = (const __half*)(sm + s * STGBT);
        const __half* Ah0 = base + wm * 64 * LDS_AB;
        const __half* Bh0 = base + PLE + wn * 32 * LDS_AB;
#pragma unroll
        for (int ks = 0; ks < 4; ks++) {
            wmma::fragment<wmma::matrix_a, 16, 16, 16, __half, wmma::row_major> fah[4];
            wmma::fragment<wmma::matrix_b, 16, 16, 16, __half, wmma::col_major> fbh[2];
#pragma unroll
            for (int i = 0; i < 4; i++)
                wmma::load_matrix_sync(fah[i], Ah0 + i * 16 * LDS_AB + ks * 16, LDS_AB);
#pragma unroll
            for (int j = 0; j < 2; j++)
                wmma::load_matrix_sync(fbh[j], Bh0 + j * 16 * LDS_AB + ks * 16, LDS_AB);
#pragma unroll
            for (int i = 0; i < 4; i++)
#pragma unroll
                for (int j = 0; j < 2; j++)
                    wmma::mma_sync(acc[i][j], fah[i], fbh[j], acc[i][j]);
        }
    };

    // ---- 2-stage pipelined mainloop (R4 structure — measured best) ----
    const int T = K / BKK;
    ldst(0, 0);
    ldst(1, 1);
    for (int t = 0; t < T; t++) {
        if (t == T - 1) { CP_WAIT0(); } else { CP_WAIT1(); }
        __syncthreads();
        compute(t & 1);
        __syncthreads();
        if (t + 2 < T) ldst(t + 2, t & 1);
    }

    // ---- epilogue: stage accumulators through SMEM ----
#pragma unroll
    for (int i = 0; i < 4; i++)
#pragma unroll
        for (int j = 0; j < 2; j++)
            wmma::store_matrix_sync(Cs + (size_t)(wm * 64 + i * 16) * LDC_S + wn * 32 + j * 16,
                                    acc[i][j], LDC_S, wmma::mem_row_major);
    __syncthreads();

    const int row = tid >> 1;
    const int ch  = (tid & 1) * 64;
    const float* crow = Cs + (size_t)row * LDC_S + ch;
    const int gr = rowBase + row;
    const int gc = colBase + ch;

    if (EPI == 2) {
        __half* Ch = (__half*)Cgv + (size_t)zb * sCb + (size_t)zh * sCh +
                     (size_t)gr * ldc + gc;
#pragma unroll
        for (int cb = 0; cb < 64; cb += 8) {
            __align__(16) __half hv[8];
#pragma unroll
            for (int j = 0; j < 8; j++) hv[j] = __float2half_rn(crow[cb + j]);
            *(uint4*)(Ch + cb) = *(uint4*)hv;
        }
    } else if (EPI == 1) {
        float* C = (float*)Cgv + (size_t)zb * sCb + (size_t)zh * sCh + (size_t)gr * ldc + gc;
        const int* mrow = maskg + (size_t)zb * sMb + (size_t)gr * NL + gc;
#pragma unroll
        for (int j4 = 0; j4 < 16; j4++) {
            int4 m = *(const int4*)(mrow + j4 * 4);
            int mm[4] = {m.x, m.y, m.z, m.w};
            float ov[4];
#pragma unroll
            for (int j = 0; j < 4; j++) {
                float s = crow[j4 * 4 + j] * 0.0625f;   // 1/sqrt(256)
                s = fminf(15.f, fmaxf(-15.f, s));
                ov[j] = mm[j] ? s : 30000.f;
            }
            *(float4*)(C + j4 * 4) = *(float4*)ov;
        }
    } else {  // EPI == 3: plain fp32
        float* C = (float*)Cgv + (size_t)zb * sCb + (size_t)zh * sCh + (size_t)gr * ldc + gc;
#pragma unroll
        for (int j4 = 0; j4 < 16; j4++) {
            float ov[4] = {crow[j4 * 4], crow[j4 * 4 + 1], crow[j4 * 4 + 2], crow[j4 * 4 + 3]};
            *(float4*)(C + j4 * 4) = *(float4*)ov;
        }
    }
}

#define SMEM_11 (2 * 2 * PLB)   // 73728 B (2 CTAs/SM)

// ---------------------------------------------------------------------------
// masked softmax in place (sentinel > 1000 = masked); emits single fp16 plane.
// ---------------------------------------------------------------------------
__global__ void __launch_bounds__(256) softmax_k(float* __restrict__ attn,
                                                 __half* __restrict__ ap)
{
    __shared__ float sh[8];
    const size_t rbase = (size_t)blockIdx.x * 1024;
    float* p = attn + rbase;
    const int t = threadIdx.x;

    float4 v4 = ((const float4*)p)[t];
    float x[4] = {v4.x, v4.y, v4.z, v4.w};
    bool msk[4];
    float mx = -1e30f;
#pragma unroll
    for (int i = 0; i < 4; i++) {
        msk[i] = (x[i] > 1000.f);
        if (msk[i]) x[i] = 0.f;
        mx = fmaxf(mx, x[i]);
    }
#pragma unroll
    for (int o = 16; o; o >>= 1) mx = fmaxf(mx, __shfl_xor_sync(0xffffffffu, mx, o));
    if ((t & 31) == 0) sh[t >> 5] = mx;
    __syncthreads();
    mx = sh[0];
#pragma unroll
    for (int i = 1; i < 8; i++) mx = fmaxf(mx, sh[i]);

    float e[4], s = 0.f;
#pragma unroll
    for (int i = 0; i < 4; i++) {
        e[i] = msk[i] ? 0.f : __expf(x[i] - mx);
        s += e[i];
    }
#pragma unroll
    for (int o = 16; o; o >>= 1) s += __shfl_xor_sync(0xffffffffu, s, o);
    __syncthreads();
    if ((t & 31) == 0) sh[t >> 5] = s;
    __syncthreads();
    s = 0.f;
#pragma unroll
    for (int i = 0; i < 8; i++) s += sh[i];

    const float inv = 1.f / (s + 1e-6f);
    float ov[4] = {e[0] * inv, e[1] * inv, e[2] * inv, e[3] * inv};
    ((float4*)p)[t] = *(float4*)ov;

    __align__(8) __half h[4];
#pragma unroll
    for (int i = 0; i < 4; i++) h[i] = __float2half_rn(ov[i]);
    *(uint2*)(ap + rbase + (size_t)t * 4) = *(uint2*)h;
}

// ---------------------------------------------------------------------------
// split-K reduce + bias + residual + LayerNorm
// ---------------------------------------------------------------------------
__global__ void __launch_bounds__(256) fc_ln_k(
    const float* __restrict__ tmp, const float* __restrict__ fcb,
    const float* __restrict__ resid, const float* __restrict__ lg,
    const float* __restrict__ lb, float* __restrict__ out)
{
    __shared__ float shs[8], shq[8];
    const size_t o = (size_t)blockIdx.x * 256 + threadIdx.x;
    const int t = threadIdx.x;

    float v = tmp[o] + tmp[o + 1048576] + tmp[o + 2097152] + tmp[o + 3145728]
            + fcb[t] + resid[o];

    float s = v, qq = v * v;
#pragma unroll
    for (int d = 16; d; d >>= 1) {
        s  += __shfl_xor_sync(0xffffffffu, s, d);
        qq += __shfl_xor_sync(0xffffffffu, qq, d);
    }
    if ((t & 31) == 0) { shs[t >> 5] = s; shq[t >> 5] = qq; }
    __syncthreads();
    s = 0.f; qq = 0.f;
#pragma unroll
    for (int i = 0; i < 8; i++) { s += shs[i]; qq += shq[i]; }

    const float mean = s * (1.f / 256.f);
    const float var  = qq * (1.f / 256.f) - mean * mean;
    out[o] = (v - mean) * rsqrtf(var + 1e-5f) * lg[t] + lb[t];
}

// ---------------------------------------------------------------------------
extern "C" void kernel_launch(void* const* d_in, const int* in_sizes, int n_in,
                              void* d_out, int out_size)
{
    const float* q    = (const float*)d_in[0];
    const int*   mask = (const int*)  d_in[1];
    const float* k    = (const float*)d_in[2];
    const float* v    = (const float*)d_in[3];
    const float* w_qs = (const float*)d_in[4];
    const float* w_ks = (const float*)d_in[5];
    const float* w_vs = (const float*)d_in[6];
    const float* fc_w = (const float*)d_in[7];
    const float* fc_b = (const float*)d_in[8];
    const float* ln_g = (const float*)d_in[9];
    const float* ln_b = (const float*)d_in[10];

    float* out  = (float*)d_out;
    float* attn = out + (size_t)NBL * ND;

    __half *qkp, *vp, *wqkp, *wvp, *fcwp, *qkhp, *vht, *hop, *ap;
    float* tmp;
    cudaGetSymbolAddress((void**)&qkp,  g_qkp);
    cudaGetSymbolAddress((void**)&vp,   g_vp);
    cudaGetSymbolAddress((void**)&wqkp, g_wqkp);
    cudaGetSymbolAddress((void**)&wvp,  g_wvp);
    cudaGetSymbolAddress((void**)&fcwp, g_fcwp);
    cudaGetSymbolAddress((void**)&qkhp, g_qkhp);
    cudaGetSymbolAddress((void**)&vht,  g_vht);
    cudaGetSymbolAddress((void**)&hop,  g_hop);
    cudaGetSymbolAddress((void**)&ap,   g_ap);
    cudaGetSymbolAddress((void**)&tmp,  g_tmp);

    cudaFuncSetAttribute(tgemm<1>, cudaFuncAttributeMaxDynamicSharedMemorySize, SMEM_11);
    cudaFuncSetAttribute(tgemm<2>, cudaFuncAttributeMaxDynamicSharedMemorySize, SMEM_11);
    cudaFuncSetAttribute(tgemm<3>, cudaFuncAttributeMaxDynamicSharedMemorySize, SMEM_11);

    // side stream + events (created once; constant resources, identical work
    // per call — no per-call device memory activity)
    static cudaStream_t s1 = [] {
        cudaStream_t s;
        cudaStreamCreateWithFlags(&s, cudaStreamNonBlocking);
        return s;
    }();
    static cudaEvent_t e0 = [] {
        cudaEvent_t e; cudaEventCreateWithFlags(&e, cudaEventDisableTiming); return e;
    }();
    static cudaEvent_t e_qkv = [] {
        cudaEvent_t e; cudaEventCreateWithFlags(&e, cudaEventDisableTiming); return e;
    }();
    static cudaEvent_t e_w = [] {
        cudaEvent_t e; cudaEventCreateWithFlags(&e, cudaEventDisableTiming); return e;
    }();
    static cudaEvent_t e_pv = [] {
        cudaEvent_t e; cudaEventCreateWithFlags(&e, cudaEventDisableTiming); return e;
    }();

    const long QKSZ = (long)NBL * ND;        // 1048576
    const long WSZ  = (long)NHD * ND;        // 524288
    const long BIG  = (long)NBL * NHD;       // 8388608

    // ---- fork side stream ----
    cudaEventRecord(e0, 0);
    cudaStreamWaitEvent(s1, e0, 0);

    // s0: convert q/k/v (hi planes; k stored at qkp + 2*QKSZ)
    cvt4_k<<<dim3(NBL * ND / 4 / 256, 3), 256>>>(
        q, k, v, v, qkp, qkp + 2 * QKSZ, vp, vp, NBL * ND / 4);
    cudaEventRecord(e_qkv, 0);

    // s1: convert weights (wk stored at wqkp + 2*WSZ)
    cvt4_k<<<dim3(NHD * ND / 4 / 256, 4), 256, 0, s1>>>(
        w_qs, w_ks, w_vs, fc_w, wqkp, wqkp + 2 * WSZ, wvp, fcwp, NHD * ND / 4);
    cudaEventRecord(e_w, s1);

    // s1: V projection (needs vp from s0): vht[hd, token] = w_vs @ v^T
    cudaStreamWaitEvent(s1, e_qkv, 0);
    tgemm<2><<<dim3(32, 16, 1), 256, SMEM_11, s1>>>(
        wvp, ND, vp, ND, vht, NBL, ND, 1,
        0, 0, 0, 0, 0, 0, nullptr, 0);
    cudaEventRecord(e_pv, s1);

    // s0: Q+K projections fused (needs wqkp from s1), z selects q/k
    cudaStreamWaitEvent(0, e_w, 0);
    tgemm<2><<<dim3(16, 32, 2), 256, SMEM_11>>>(
        qkp, ND, wqkp, ND, qkhp, NHD, ND, 1,
        0, 2 * QKSZ,      // A: zh -> q/k hi plane
        0, 2 * WSZ,       // B: zh -> wq/wk hi plane
        0, BIG,           // C: zh -> qh/kh
        nullptr, 0);

    // s0: scores: attn[(h*B+b)] = qh @ kh^T /16, clip, mask
    tgemm<1><<<dim3(8, 8, 32), 256, SMEM_11>>>(
        qkhp, NHD, qkhp + BIG, NHD, attn, NL, ND, NB,
        (long)NL * NHD, (long)ND,
        (long)NL * NHD, (long)ND,
        (long)NL * NL, (long)NB * NL * NL,
        mask, (long)NL * NL);

    // s0: masked softmax in place + single fp16 plane
    softmax_k<<<NH * NB * NL, 256>>>(attn, ap);

    // s0: attn @ V (join: needs vht from s1)
    cudaStreamWaitEvent(0, e_pv, 0);
    tgemm<2><<<dim3(2, 8, 32), 256, SMEM_11>>>(
        ap, NL, vht, NBL, hop, NHD, NL, NB,
        (long)NL * NL, (long)NB * NL * NL,
        (long)NL, (long)ND * NBL,
        (long)NL * NHD, (long)ND,
        nullptr, 0);

    // s0: fc split-K = 4 -> fp32 partials
    tgemm<3><<<dim3(2, 32, 4), 256, SMEM_11>>>(
        hop, NHD, fcwp, NHD, tmp, ND, 512, 1,
        0, 512, 0, 512, 0, (long)NBL * ND, nullptr, 0);

    // s0: reduce + bias + residual + LayerNorm
    fc_ln_k<<<NBL, 256>>>(tmp, fc_b, q, ln_g, ln_b, out);
}